// round 1
// baseline (speedup 1.0000x reference)
#include <cuda_runtime.h>
#include <math.h>

// Problem constants
#define B_  2
#define S_  2048
#define D_  1024
#define H_  16
#define DH_ 64
#define R_  8
#define M_  (B_*S_)          // 4096 rows total

// Scratch (device globals; no allocation allowed)
__device__ float g_x[M_*D_];      // RMS-normed input
__device__ float g_hq[M_*D_];
__device__ float g_hk[M_*D_];
__device__ float g_hv[M_*D_];
__device__ float g_attn[M_*D_];

#define FULLMASK 0xffffffffu

// ---------------------------------------------------------------------------
// RMSNorm: one block per row (1024 elems), 256 threads
// ---------------------------------------------------------------------------
__global__ __launch_bounds__(256) void rmsnorm_kernel(
    const float* __restrict__ hs, const float* __restrict__ w, float* __restrict__ out)
{
    int row = blockIdx.x;
    int t = threadIdx.x;
    const float* x = hs + (long)row * D_;

    float v[4];
    float ss = 0.f;
    #pragma unroll
    for (int i = 0; i < 4; i++) {
        v[i] = x[t + i * 256];
        ss += v[i] * v[i];
    }
    // warp reduce
    #pragma unroll
    for (int o = 16; o > 0; o >>= 1) ss += __shfl_xor_sync(FULLMASK, ss, o);
    __shared__ float red[8];
    if ((t & 31) == 0) red[t >> 5] = ss;
    __syncthreads();
    __shared__ float s_inv;
    if (t == 0) {
        float s = 0.f;
        #pragma unroll
        for (int i = 0; i < 8; i++) s += red[i];
        s_inv = rsqrtf(s / (float)D_ + 1e-5f);
    }
    __syncthreads();
    float inv = s_inv;
    #pragma unroll
    for (int i = 0; i < 4; i++) {
        int d = t + i * 256;
        out[(long)row * D_ + d] = v[i] * inv * w[d];
    }
}

// ---------------------------------------------------------------------------
// GEMM NT: C[M,1024] = A[M,1024] @ W[1024,1024]^T  (+ optional residual)
// Block tile 128x128, BK=16, 256 threads, 8x8 per-thread microtile.
// ---------------------------------------------------------------------------
template <bool RESID>
__global__ __launch_bounds__(256) void gemm_nt_kernel(
    const float* __restrict__ A, const float* __restrict__ W,
    const float* __restrict__ resid, float* __restrict__ C)
{
    __shared__ float As[16][132];
    __shared__ float Ws[16][132];

    int tid = threadIdx.x;
    int tx = tid & 15;
    int ty = tid >> 4;
    long aBase = (long)blockIdx.y * 128 * D_;
    long wBase = (long)blockIdx.x * 128 * D_;

    float acc[8][8];
    #pragma unroll
    for (int i = 0; i < 8; i++)
        #pragma unroll
        for (int j = 0; j < 8; j++) acc[i][j] = 0.f;

    for (int k0 = 0; k0 < D_; k0 += 16) {
        // Load 128x16 tiles of A and W, transposed into smem
        #pragma unroll
        for (int l = 0; l < 2; l++) {
            int idx = tid + l * 256;   // 0..511 float4 slots
            int r = idx >> 2;          // 0..127
            int c4 = idx & 3;          // 0..3
            float4 a = *(const float4*)&A[aBase + (long)r * D_ + k0 + c4 * 4];
            As[c4*4+0][r] = a.x; As[c4*4+1][r] = a.y;
            As[c4*4+2][r] = a.z; As[c4*4+3][r] = a.w;
            float4 wv = *(const float4*)&W[wBase + (long)r * D_ + k0 + c4 * 4];
            Ws[c4*4+0][r] = wv.x; Ws[c4*4+1][r] = wv.y;
            Ws[c4*4+2][r] = wv.z; Ws[c4*4+3][r] = wv.w;
        }
        __syncthreads();

        #pragma unroll
        for (int kk = 0; kk < 16; kk++) {
            float a[8], b[8];
            *(float4*)&a[0] = *(const float4*)&As[kk][ty * 8];
            *(float4*)&a[4] = *(const float4*)&As[kk][ty * 8 + 4];
            *(float4*)&b[0] = *(const float4*)&Ws[kk][tx * 8];
            *(float4*)&b[4] = *(const float4*)&Ws[kk][tx * 8 + 4];
            #pragma unroll
            for (int i = 0; i < 8; i++)
                #pragma unroll
                for (int j = 0; j < 8; j++)
                    acc[i][j] += a[i] * b[j];
        }
        __syncthreads();
    }

    int rowC = blockIdx.y * 128 + ty * 8;
    int colC = blockIdx.x * 128 + tx * 8;
    #pragma unroll
    for (int i = 0; i < 8; i++) {
        long base = (long)(rowC + i) * D_ + colC;
        #pragma unroll
        for (int j = 0; j < 8; j += 4) {
            float4 v;
            v.x = acc[i][j+0]; v.y = acc[i][j+1];
            v.z = acc[i][j+2]; v.w = acc[i][j+3];
            if (RESID) {
                float4 rv = *(const float4*)&resid[base + j];
                v.x += rv.x; v.y += rv.y; v.z += rv.z; v.w += rv.w;
            }
            *(float4*)&C[base + j] = v;
        }
    }
}

// ---------------------------------------------------------------------------
// LoRA: h[i,:] += 2 * (h[i,:] @ A[b]) @ B[b]^T   (one block per row)
// A, Bm: [B, D, R] each (Bm accessed as Bm[b,d,r])
// ---------------------------------------------------------------------------
__global__ __launch_bounds__(256) void lora_kernel(
    float* __restrict__ h, const float* __restrict__ A, const float* __restrict__ Bm)
{
    int i = blockIdx.x;
    int b = i / S_;
    int t = threadIdx.x;
    const float* Ab = A + (long)b * D_ * R_;
    const float* Bb = Bm + (long)b * D_ * R_;

    float hr[4];
    float part[R_];
    #pragma unroll
    for (int r = 0; r < R_; r++) part[r] = 0.f;
    #pragma unroll
    for (int l = 0; l < 4; l++) {
        int d = t + l * 256;
        hr[l] = h[(long)i * D_ + d];
        #pragma unroll
        for (int r = 0; r < R_; r++) part[r] += hr[l] * Ab[d * R_ + r];
    }
    // block reduce the 8 partials
    #pragma unroll
    for (int r = 0; r < R_; r++)
        #pragma unroll
        for (int o = 16; o > 0; o >>= 1)
            part[r] += __shfl_xor_sync(FULLMASK, part[r], o);
    __shared__ float zred[8][R_];
    if ((t & 31) == 0)
        #pragma unroll
        for (int r = 0; r < R_; r++) zred[t >> 5][r] = part[r];
    __syncthreads();
    __shared__ float z[R_];
    if (t < R_) {
        float s = 0.f;
        #pragma unroll
        for (int w = 0; w < 8; w++) s += zred[w][t];
        z[t] = s;
    }
    __syncthreads();
    #pragma unroll
    for (int l = 0; l < 4; l++) {
        int d = t + l * 256;
        float delta = 0.f;
        #pragma unroll
        for (int r = 0; r < R_; r++) delta += z[r] * Bb[d * R_ + r];
        h[(long)i * D_ + d] = hr[l] + 2.f * delta;
    }
}

// ---------------------------------------------------------------------------
// Flash attention, fp32, causal. One block per (q-tile of 64, head, batch).
// 256 threads: thread (tx,ty) (16x16) owns 4x4 of both S-tile and O-tile.
// Dynamic smem: Qs[64][68](d-major) Ks[64][68](d-major) Vs[64][68] Ps[64][68]
// ---------------------------------------------------------------------------
__global__ __launch_bounds__(256) void flash_kernel(
    const float* __restrict__ Q, const float* __restrict__ K,
    const float* __restrict__ V, float* __restrict__ O)
{
    extern __shared__ float sm[];
    float* Qs = sm;                 // [d][q], pitch 68
    float* Ks = sm + 64 * 68;       // [d][k], pitch 68
    float* Vs = sm + 2 * 64 * 68;   // [k][d], pitch 68
    float* Ps = sm + 3 * 64 * 68;   // [q][k], pitch 68

    int qt = blockIdx.x;            // 0..31
    int h  = blockIdx.y;            // 0..15
    int b  = blockIdx.z;            // 0..1
    int tid = threadIdx.x;
    int tx = tid & 15;
    int ty = tid >> 4;

    const float* Qp = Q + ((long)(b * S_ + qt * 64)) * D_ + h * DH_;

    // Load Q tile transposed: Qs[d][q]
    #pragma unroll
    for (int l = 0; l < 4; l++) {
        int idx = tid + l * 256;     // 0..1023 float4 slots (64 rows x 16)
        int q  = idx >> 4;
        int c4 = idx & 15;
        float4 v = *(const float4*)&Qp[(long)q * D_ + c4 * 4];
        Qs[(c4*4+0)*68 + q] = v.x; Qs[(c4*4+1)*68 + q] = v.y;
        Qs[(c4*4+2)*68 + q] = v.z; Qs[(c4*4+3)*68 + q] = v.w;
    }

    float o[4][4];
    float m[4], lsum[4];
    #pragma unroll
    for (int i = 0; i < 4; i++) {
        m[i] = -1e30f; lsum[i] = 0.f;
        #pragma unroll
        for (int j = 0; j < 4; j++) o[i][j] = 0.f;
    }

    for (int kt = 0; kt <= qt; kt++) {
        const float* Kp = K + ((long)(b * S_ + kt * 64)) * D_ + h * DH_;
        const float* Vp = V + ((long)(b * S_ + kt * 64)) * D_ + h * DH_;
        // Load K transposed [d][k], V natural [k][d]
        #pragma unroll
        for (int l = 0; l < 4; l++) {
            int idx = tid + l * 256;
            int r  = idx >> 4;
            int c4 = idx & 15;
            float4 kv = *(const float4*)&Kp[(long)r * D_ + c4 * 4];
            Ks[(c4*4+0)*68 + r] = kv.x; Ks[(c4*4+1)*68 + r] = kv.y;
            Ks[(c4*4+2)*68 + r] = kv.z; Ks[(c4*4+3)*68 + r] = kv.w;
            float4 vv = *(const float4*)&Vp[(long)r * D_ + c4 * 4];
            *(float4*)&Vs[r * 68 + c4 * 4] = vv;
        }
        __syncthreads();

        // S = Q K^T  (4x4 per thread)
        float acc[4][4];
        #pragma unroll
        for (int i = 0; i < 4; i++)
            #pragma unroll
            for (int j = 0; j < 4; j++) acc[i][j] = 0.f;
        #pragma unroll 4
        for (int dk = 0; dk < 64; dk++) {
            float4 a = *(const float4*)&Qs[dk * 68 + ty * 4];
            float4 bb = *(const float4*)&Ks[dk * 68 + tx * 4];
            float av[4] = {a.x, a.y, a.z, a.w};
            float bv[4] = {bb.x, bb.y, bb.z, bb.w};
            #pragma unroll
            for (int i = 0; i < 4; i++)
                #pragma unroll
                for (int j = 0; j < 4; j++)
                    acc[i][j] += av[i] * bv[j];
        }

        const float scale = 0.125f;   // 1/sqrt(64)
        bool diag = (kt == qt);
        #pragma unroll
        for (int i = 0; i < 4; i++)
            #pragma unroll
            for (int j = 0; j < 4; j++) {
                float s = acc[i][j] * scale;
                if (diag && (tx * 4 + j) > (ty * 4 + i)) s = -1e30f;
                acc[i][j] = s;
            }

        // online softmax (row groups of 16 lanes: xor over lane bits 0..3)
        #pragma unroll
        for (int i = 0; i < 4; i++) {
            float mloc = fmaxf(fmaxf(acc[i][0], acc[i][1]), fmaxf(acc[i][2], acc[i][3]));
            #pragma unroll
            for (int off = 1; off < 16; off <<= 1)
                mloc = fmaxf(mloc, __shfl_xor_sync(FULLMASK, mloc, off));
            float mnew = fmaxf(m[i], mloc);
            float alpha = __expf(m[i] - mnew);
            float rsum = 0.f;
            #pragma unroll
            for (int j = 0; j < 4; j++) {
                float p = __expf(acc[i][j] - mnew);
                acc[i][j] = p;
                rsum += p;
            }
            #pragma unroll
            for (int off = 1; off < 16; off <<= 1)
                rsum += __shfl_xor_sync(FULLMASK, rsum, off);
            lsum[i] = lsum[i] * alpha + rsum;
            m[i] = mnew;
            #pragma unroll
            for (int j = 0; j < 4; j++) o[i][j] *= alpha;
        }

        // write P to smem
        #pragma unroll
        for (int i = 0; i < 4; i++) {
            float4 v;
            v.x = acc[i][0]; v.y = acc[i][1]; v.z = acc[i][2]; v.w = acc[i][3];
            *(float4*)&Ps[(ty * 4 + i) * 68 + tx * 4] = v;
        }
        __syncthreads();

        // O += P @ V
        #pragma unroll 4
        for (int kk = 0; kk < 64; kk++) {
            float4 bv = *(const float4*)&Vs[kk * 68 + tx * 4];
            float a0 = Ps[(ty*4+0)*68 + kk];
            float a1 = Ps[(ty*4+1)*68 + kk];
            float a2 = Ps[(ty*4+2)*68 + kk];
            float a3 = Ps[(ty*4+3)*68 + kk];
            o[0][0] += a0*bv.x; o[0][1] += a0*bv.y; o[0][2] += a0*bv.z; o[0][3] += a0*bv.w;
            o[1][0] += a1*bv.x; o[1][1] += a1*bv.y; o[1][2] += a1*bv.z; o[1][3] += a1*bv.w;
            o[2][0] += a2*bv.x; o[2][1] += a2*bv.y; o[2][2] += a2*bv.z; o[2][3] += a2*bv.w;
            o[3][0] += a3*bv.x; o[3][1] += a3*bv.y; o[3][2] += a3*bv.z; o[3][3] += a3*bv.w;
        }
        __syncthreads();
    }

    // normalize + write out
    #pragma unroll
    for (int i = 0; i < 4; i++) {
        float inv = 1.f / lsum[i];
        int row = qt * 64 + ty * 4 + i;
        float4 v;
        v.x = o[i][0]*inv; v.y = o[i][1]*inv; v.z = o[i][2]*inv; v.w = o[i][3]*inv;
        *(float4*)&O[((long)(b * S_ + row)) * D_ + h * DH_ + tx * 4] = v;
    }
}

// ---------------------------------------------------------------------------
// Launch
// ---------------------------------------------------------------------------
extern "C" void kernel_launch(void* const* d_in, const int* in_sizes, int n_in,
                              void* d_out, int out_size)
{
    const float* hidden = (const float*)d_in[0];
    // d_in[1] = attention_mask: always causal tril -> handled analytically
    const float* lora   = (const float*)d_in[2];   // [4, B, D, R]
    const float* ln_w   = (const float*)d_in[3];
    const float* Wq     = (const float*)d_in[4];
    const float* Wk     = (const float*)d_in[5];
    const float* Wv     = (const float*)d_in[6];
    const float* Wo     = (const float*)d_in[7];
    float* out = (float*)d_out;

    float *x, *hq, *hk, *hv, *attn;
    cudaGetSymbolAddress((void**)&x,    g_x);
    cudaGetSymbolAddress((void**)&hq,   g_hq);
    cudaGetSymbolAddress((void**)&hk,   g_hk);
    cudaGetSymbolAddress((void**)&hv,   g_hv);
    cudaGetSymbolAddress((void**)&attn, g_attn);

    // flash kernel needs 69632 B of dynamic smem
    static const int FLASH_SMEM = 4 * 64 * 68 * sizeof(float);
    cudaFuncSetAttribute(flash_kernel, cudaFuncAttributeMaxDynamicSharedMemorySize, FLASH_SMEM);

    // 1. RMSNorm
    rmsnorm_kernel<<<M_, 256>>>(hidden, ln_w, x);

    // 2. QKV projections
    dim3 gg(D_ / 128, M_ / 128);
    gemm_nt_kernel<false><<<gg, 256>>>(x, Wq, nullptr, hq);
    gemm_nt_kernel<false><<<gg, 256>>>(x, Wk, nullptr, hk);
    gemm_nt_kernel<false><<<gg, 256>>>(x, Wv, nullptr, hv);

    // 3. LoRA deltas (A_q = lora[0], A_k = lora[1], B_q = lora[2], B_k = lora[3])
    const long LSZ = (long)B_ * D_ * R_;
    lora_kernel<<<M_, 256>>>(hq, lora + 0 * LSZ, lora + 2 * LSZ);
    lora_kernel<<<M_, 256>>>(hk, lora + 1 * LSZ, lora + 3 * LSZ);

    // 4. Causal flash attention
    dim3 fg(S_ / 64, H_, B_);
    flash_kernel<<<fg, 256, FLASH_SMEM>>>(hq, hk, hv, attn);

    // 5. Output projection + residual
    gemm_nt_kernel<true><<<gg, 256>>>(attn, Wo, hidden, out);
}

// round 3
// speedup vs baseline: 2.1814x; 2.1814x over previous
#include <cuda_runtime.h>
#include <cstdint>
#include <math.h>

// Problem constants
#define B_  2
#define S_  2048
#define D_  1024
#define H_  16
#define DH_ 64
#define R_  8
#define M_  (B_*S_)          // 4096 rows

// Scratch (device globals; no allocation allowed)
__device__ float g_x[M_*D_];
__device__ float g_hq[M_*D_];
__device__ float g_hk[M_*D_];
__device__ float g_hv[M_*D_];
__device__ float g_attn[M_*D_];

#define FULLMASK 0xffffffffu

// ===========================================================================
// PTX helpers (arch-agnostic: mma.sync + ldmatrix + cp.async, sm_80+)
// ===========================================================================
__device__ __forceinline__ uint32_t smem_u32(const void* p) {
    uint32_t a;
    asm("{ .reg .u64 t; cvta.to.shared.u64 t, %1; cvt.u32.u64 %0, t; }"
        : "=r"(a) : "l"(p));
    return a;
}

#define LDSM4(R0,R1,R2,R3,ADDR) \
    asm volatile("ldmatrix.sync.aligned.m8n8.x4.shared.b16 {%0,%1,%2,%3}, [%4];" \
        : "=r"(R0), "=r"(R1), "=r"(R2), "=r"(R3) : "r"(ADDR))

// D = A(16x8 tf32) * B(8x8 tf32) + D, fp32 accum
#define MMA_TF32(C, A, B0, B1) \
    asm volatile("mma.sync.aligned.m16n8k8.row.col.f32.tf32.tf32.f32 " \
        "{%0,%1,%2,%3}, {%4,%5,%6,%7}, {%8,%9}, {%0,%1,%2,%3};" \
        : "+f"((C)[0]), "+f"((C)[1]), "+f"((C)[2]), "+f"((C)[3]) \
        : "r"((A)[0]), "r"((A)[1]), "r"((A)[2]), "r"((A)[3]), "r"(B0), "r"(B1))

#define CP16(DST, SRC) \
    asm volatile("cp.async.cg.shared.global [%0], [%1], 16;" :: "r"(DST), "l"(SRC))
#define CP_COMMIT() asm volatile("cp.async.commit_group;" ::: "memory")
#define CP_WAIT(N)  asm volatile("cp.async.wait_group %0;" :: "n"(N) : "memory")

// ---------------------------------------------------------------------------
// RMSNorm: one block per row (1024 elems), 256 threads
// ---------------------------------------------------------------------------
__global__ __launch_bounds__(256) void rmsnorm_kernel(
    const float* __restrict__ hs, const float* __restrict__ w, float* __restrict__ out)
{
    int row = blockIdx.x;
    int t = threadIdx.x;
    const float* x = hs + (long)row * D_;

    float v[4];
    float ss = 0.f;
    #pragma unroll
    for (int i = 0; i < 4; i++) {
        v[i] = x[t + i * 256];
        ss += v[i] * v[i];
    }
    #pragma unroll
    for (int o = 16; o > 0; o >>= 1) ss += __shfl_xor_sync(FULLMASK, ss, o);
    __shared__ float red[8];
    if ((t & 31) == 0) red[t >> 5] = ss;
    __syncthreads();
    __shared__ float s_inv;
    if (t == 0) {
        float s = 0.f;
        #pragma unroll
        for (int i = 0; i < 8; i++) s += red[i];
        s_inv = rsqrtf(s / (float)D_ + 1e-5f);
    }
    __syncthreads();
    float inv = s_inv;
    #pragma unroll
    for (int i = 0; i < 4; i++) {
        int d = t + i * 256;
        out[(long)row * D_ + d] = v[i] * inv * w[d];
    }
}

// ---------------------------------------------------------------------------
// tf32 mma.sync GEMM NT: C[M,1024] = A[M,1024] @ W[1024,1024]^T (+ residual)
// CTA 128x128, BK=32, 4 warps x (64x64), cp.async double-buffered smem.
// smem pitch 36 floats -> conflict-free ldmatrix frag loads.
// ---------------------------------------------------------------------------
#define GP 36
#define GTILE_B (128*GP*4)       // 18432 bytes per tile buffer
#define GEMM_SMEM (4*GTILE_B)    // A[2] + B[2] = 73728

template <bool RESID>
__global__ __launch_bounds__(128, 2) void gemm_mma_kernel(
    const float* __restrict__ A, const float* __restrict__ W,
    const float* __restrict__ resid, float* __restrict__ C)
{
    extern __shared__ __align__(16) char gsm[];
    const uint32_t sA = smem_u32(gsm);
    const uint32_t sB = sA + 2 * GTILE_B;

    int tid = threadIdx.x;
    int lane = tid & 31;
    int w = tid >> 5;
    int wm = (w >> 1) * 64;
    int wn = (w & 1) * 64;

    const float* aG = A + (long)(blockIdx.y * 128 + tid) * D_;
    const float* bG = W + (long)(blockIdx.x * 128 + tid) * D_;
    const uint32_t stSA = sA + tid * (GP * 4);
    const uint32_t stSB = sB + tid * (GP * 4);

    float acc[4][8][4];
    #pragma unroll
    for (int mt = 0; mt < 4; mt++)
        #pragma unroll
        for (int nt = 0; nt < 8; nt++)
            #pragma unroll
            for (int j = 0; j < 4; j++) acc[mt][nt][j] = 0.f;

    // ldmatrix lane address bases (bytes)
    const uint32_t aFragBase =
        ((wm + (lane & 15)) * GP + ((lane >> 4) << 2)) * 4;
    const uint32_t bFragBase =
        ((wn + (lane & 7) + ((lane >> 4) << 3)) * GP + (((lane >> 3) & 1) << 2)) * 4;

    // prefetch chunk 0
    #pragma unroll
    for (int c4 = 0; c4 < 8; c4++) {
        CP16(stSA + c4 * 16, aG + c4 * 4);
        CP16(stSB + c4 * 16, bG + c4 * 4);
    }
    CP_COMMIT();

    for (int kc = 0; kc < 32; kc++) {
        int buf = kc & 1;
        if (kc + 1 < 32) {
            const float* aN = aG + (kc + 1) * 32;
            const float* bN = bG + (kc + 1) * 32;
            uint32_t dA = stSA + (buf ^ 1) * GTILE_B;
            uint32_t dB = stSB + (buf ^ 1) * GTILE_B;
            #pragma unroll
            for (int c4 = 0; c4 < 8; c4++) {
                CP16(dA + c4 * 16, aN + c4 * 4);
                CP16(dB + c4 * 16, bN + c4 * 4);
            }
            CP_COMMIT();
            CP_WAIT(1);
        } else {
            CP_WAIT(0);
        }
        __syncthreads();

        uint32_t aBuf = sA + buf * GTILE_B + aFragBase;
        uint32_t bBuf = sB + buf * GTILE_B + bFragBase;

        #pragma unroll
        for (int ks = 0; ks < 4; ks++) {
            uint32_t af[4][4];
            uint32_t bf[8][2];
            #pragma unroll
            for (int mt = 0; mt < 4; mt++)
                LDSM4(af[mt][0], af[mt][1], af[mt][2], af[mt][3],
                      aBuf + (mt * 16 * GP + ks * 8) * 4);
            #pragma unroll
            for (int ntp = 0; ntp < 4; ntp++) {
                uint32_t r0, r1, r2, r3;
                LDSM4(r0, r1, r2, r3, bBuf + (ntp * 16 * GP + ks * 8) * 4);
                bf[2 * ntp][0] = r0; bf[2 * ntp][1] = r1;
                bf[2 * ntp + 1][0] = r2; bf[2 * ntp + 1][1] = r3;
            }
            #pragma unroll
            for (int mt = 0; mt < 4; mt++)
                #pragma unroll
                for (int nt = 0; nt < 8; nt++)
                    MMA_TF32(acc[mt][nt], af[mt], bf[nt][0], bf[nt][1]);
        }
        __syncthreads();
    }

    // Epilogue
    int rowBase = blockIdx.y * 128 + wm + (lane >> 2);
    int colBase = blockIdx.x * 128 + wn + 2 * (lane & 3);
    #pragma unroll
    for (int mt = 0; mt < 4; mt++) {
        #pragma unroll
        for (int nt = 0; nt < 8; nt++) {
            long i0 = (long)(rowBase + mt * 16) * D_ + colBase + nt * 8;
            long i1 = i0 + 8 * D_;
            float2 v0 = make_float2(acc[mt][nt][0], acc[mt][nt][1]);
            float2 v1 = make_float2(acc[mt][nt][2], acc[mt][nt][3]);
            if (RESID) {
                float2 r0 = *(const float2*)&resid[i0];
                float2 r1 = *(const float2*)&resid[i1];
                v0.x += r0.x; v0.y += r0.y;
                v1.x += r1.x; v1.y += r1.y;
            }
            *(float2*)&C[i0] = v0;
            *(float2*)&C[i1] = v1;
        }
    }
}

// ---------------------------------------------------------------------------
// LoRA: h[i,:] += 2 * (h[i,:] @ A[b]) @ B[b]^T   (one block per row)
// ---------------------------------------------------------------------------
__global__ __launch_bounds__(256) void lora_kernel(
    float* __restrict__ h, const float* __restrict__ A, const float* __restrict__ Bm)
{
    int i = blockIdx.x;
    int b = i / S_;
    int t = threadIdx.x;
    const float* Ab = A + (long)b * D_ * R_;
    const float* Bb = Bm + (long)b * D_ * R_;

    float hr[4];
    float part[R_];
    #pragma unroll
    for (int r = 0; r < R_; r++) part[r] = 0.f;
    #pragma unroll
    for (int l = 0; l < 4; l++) {
        int d = t + l * 256;
        hr[l] = h[(long)i * D_ + d];
        #pragma unroll
        for (int r = 0; r < R_; r++) part[r] += hr[l] * Ab[d * R_ + r];
    }
    #pragma unroll
    for (int r = 0; r < R_; r++)
        #pragma unroll
        for (int o = 16; o > 0; o >>= 1)
            part[r] += __shfl_xor_sync(FULLMASK, part[r], o);
    __shared__ float zred[8][R_];
    if ((t & 31) == 0)
        #pragma unroll
        for (int r = 0; r < R_; r++) zred[t >> 5][r] = part[r];
    __syncthreads();
    __shared__ float z[R_];
    if (t < R_) {
        float s = 0.f;
        #pragma unroll
        for (int w = 0; w < 8; w++) s += zred[w][t];
        z[t] = s;
    }
    __syncthreads();
    #pragma unroll
    for (int l = 0; l < 4; l++) {
        int d = t + l * 256;
        float delta = 0.f;
        #pragma unroll
        for (int r = 0; r < R_; r++) delta += z[r] * Bb[d * R_ + r];
        h[(long)i * D_ + d] = hr[l] + 2.f * delta;
    }
}

// ---------------------------------------------------------------------------
// Flash attention, tf32 mma, causal. Q tile = 128, K/V tile = 64.
// 8 warps x 16 q-rows. Q frags register-resident. Vs stored transposed.
// smem: Qs[128][68], Ks[64][68], Vs(d-major)[64][68], Ps[128][68]
// ---------------------------------------------------------------------------
#define FP 68
#define FLASH_SMEM ((128 + 64 + 64 + 128) * FP * 4)   // 104448

__global__ __launch_bounds__(256, 1) void flash_mma_kernel(
    const float* __restrict__ Q, const float* __restrict__ K,
    const float* __restrict__ V, float* __restrict__ O)
{
    extern __shared__ __align__(16) float smf[];
    float* Qs = smf;
    float* Ks = Qs + 128 * FP;
    float* Vs = Ks + 64 * FP;      // [d][kpos]
    float* Ps = Vs + 64 * FP;
    const uint32_t qsB = smem_u32(Qs);
    const uint32_t ksB = smem_u32(Ks);
    const uint32_t vsB = smem_u32(Vs);
    const uint32_t psB = smem_u32(Ps);

    int qi = blockIdx.x;   // 0..15
    int h  = blockIdx.y;
    int b  = blockIdx.z;
    int tid = threadIdx.x;
    int lane = tid & 31;
    int w = tid >> 5;      // 0..7

    const float* Qp = Q + (long)(b * S_ + qi * 128) * D_ + h * DH_;

    // Load Q tile [128][64]
    #pragma unroll
    for (int l = 0; l < 8; l++) {
        int idx = tid + l * 256;
        int q = idx >> 4, c4 = idx & 15;
        float4 v = *(const float4*)&Qp[(long)q * D_ + c4 * 4];
        *(float4*)&Qs[q * FP + c4 * 4] = v;
    }
    __syncthreads();

    // Q fragments (resident): 8 d-steps x 4 regs
    uint32_t qf[8][4];
    {
        uint32_t base = qsB + ((w * 16 + (lane & 15)) * FP + ((lane >> 4) << 2)) * 4;
        #pragma unroll
        for (int ds = 0; ds < 8; ds++)
            LDSM4(qf[ds][0], qf[ds][1], qf[ds][2], qf[ds][3], base + ds * 8 * 4);
    }

    float o[8][4];
    #pragma unroll
    for (int nt = 0; nt < 8; nt++)
        #pragma unroll
        for (int j = 0; j < 4; j++) o[nt][j] = 0.f;
    float m0 = -1e30f, m1 = -1e30f, l0 = 0.f, l1 = 0.f;

    // frag address bases
    const uint32_t kFragBase = ksB +
        (((lane & 7) + ((lane >> 4) << 3)) * FP + (((lane >> 3) & 1) << 2)) * 4;
    const uint32_t vFragBase = vsB +
        (((lane & 7) + ((lane >> 4) << 3)) * FP + (((lane >> 3) & 1) << 2)) * 4;
    const uint32_t pFragBase = psB +
        ((w * 16 + (lane & 15)) * FP + ((lane >> 4) << 2)) * 4;
    float* pRow0 = Ps + (w * 16 + (lane >> 2)) * FP + 2 * (lane & 3);

    int ktmax = 2 * qi + 2;
    for (int kt = 0; kt < ktmax; kt++) {
        const float* Kp = K + (long)(b * S_ + kt * 64) * D_ + h * DH_;
        const float* Vp = V + (long)(b * S_ + kt * 64) * D_ + h * DH_;

        // K natural [kpos][d]
        #pragma unroll
        for (int l = 0; l < 4; l++) {
            int idx = tid + l * 256;
            int kp = idx >> 4, c4 = idx & 15;
            float4 v = *(const float4*)&Kp[(long)kp * D_ + c4 * 4];
            *(float4*)&Ks[kp * FP + c4 * 4] = v;
        }
        // V transposed -> Vs[d][kpos]
        {
            int kp = tid & 63;
            int half = tid >> 6;   // 0..3
            #pragma unroll
            for (int i = 0; i < 4; i++) {
                int c4 = half * 4 + i;
                float4 v = *(const float4*)&Vp[(long)kp * D_ + c4 * 4];
                Vs[(c4 * 4 + 0) * FP + kp] = v.x;
                Vs[(c4 * 4 + 1) * FP + kp] = v.y;
                Vs[(c4 * 4 + 2) * FP + kp] = v.z;
                Vs[(c4 * 4 + 3) * FP + kp] = v.w;
            }
        }
        __syncthreads();

        bool active = (kt * 64) <= (qi * 128 + w * 16 + 15);
        if (active) {
            // S = Q K^T
            float s[8][4];
            #pragma unroll
            for (int nt = 0; nt < 8; nt++)
                #pragma unroll
                for (int j = 0; j < 4; j++) s[nt][j] = 0.f;

            #pragma unroll
            for (int ds = 0; ds < 8; ds++) {
                uint32_t bf[8][2];
                #pragma unroll
                for (int ntp = 0; ntp < 4; ntp++) {
                    uint32_t r0, r1, r2, r3;
                    LDSM4(r0, r1, r2, r3, kFragBase + (ntp * 16 * FP + ds * 8) * 4);
                    bf[2 * ntp][0] = r0; bf[2 * ntp][1] = r1;
                    bf[2 * ntp + 1][0] = r2; bf[2 * ntp + 1][1] = r3;
                }
                #pragma unroll
                for (int nt = 0; nt < 8; nt++)
                    MMA_TF32(s[nt], qf[ds], bf[nt][0], bf[nt][1]);
            }

            // scale + mask + online softmax
            bool needmask = (kt * 64 + 63) > (qi * 128 + w * 16);
            int row0 = qi * 128 + w * 16 + (lane >> 2);
            float ml0 = -1e30f, ml1 = -1e30f;
            #pragma unroll
            for (int nt = 0; nt < 8; nt++) {
                #pragma unroll
                for (int j = 0; j < 4; j++) {
                    float v = s[nt][j] * 0.125f;
                    if (needmask) {
                        int col = kt * 64 + nt * 8 + 2 * (lane & 3) + (j & 1);
                        int row = row0 + ((j >> 1) << 3);
                        if (col > row) v = -1e30f;
                    }
                    s[nt][j] = v;
                }
                ml0 = fmaxf(ml0, fmaxf(s[nt][0], s[nt][1]));
                ml1 = fmaxf(ml1, fmaxf(s[nt][2], s[nt][3]));
            }
            ml0 = fmaxf(ml0, __shfl_xor_sync(FULLMASK, ml0, 1));
            ml0 = fmaxf(ml0, __shfl_xor_sync(FULLMASK, ml0, 2));
            ml1 = fmaxf(ml1, __shfl_xor_sync(FULLMASK, ml1, 1));
            ml1 = fmaxf(ml1, __shfl_xor_sync(FULLMASK, ml1, 2));
            float mn0 = fmaxf(m0, ml0), mn1 = fmaxf(m1, ml1);
            float a0 = __expf(m0 - mn0), a1 = __expf(m1 - mn1);
            float sum0 = 0.f, sum1 = 0.f;
            #pragma unroll
            for (int nt = 0; nt < 8; nt++) {
                s[nt][0] = __expf(s[nt][0] - mn0);
                s[nt][1] = __expf(s[nt][1] - mn0);
                s[nt][2] = __expf(s[nt][2] - mn1);
                s[nt][3] = __expf(s[nt][3] - mn1);
                sum0 += s[nt][0] + s[nt][1];
                sum1 += s[nt][2] + s[nt][3];
            }
            sum0 += __shfl_xor_sync(FULLMASK, sum0, 1);
            sum0 += __shfl_xor_sync(FULLMASK, sum0, 2);
            sum1 += __shfl_xor_sync(FULLMASK, sum1, 1);
            sum1 += __shfl_xor_sync(FULLMASK, sum1, 2);
            l0 = l0 * a0 + sum0;
            l1 = l1 * a1 + sum1;
            m0 = mn0; m1 = mn1;
            #pragma unroll
            for (int nt = 0; nt < 8; nt++) {
                o[nt][0] *= a0; o[nt][1] *= a0;
                o[nt][2] *= a1; o[nt][3] *= a1;
            }

            // store P (per-warp slice, no cross-warp deps)
            #pragma unroll
            for (int nt = 0; nt < 8; nt++) {
                *(float2*)&pRow0[nt * 8] = make_float2(s[nt][0], s[nt][1]);
                *(float2*)&pRow0[8 * FP + nt * 8] = make_float2(s[nt][2], s[nt][3]);
            }
            __syncwarp();

            // O += P V
            #pragma unroll
            for (int ks = 0; ks < 8; ks++) {
                uint32_t pf[4];
                LDSM4(pf[0], pf[1], pf[2], pf[3], pFragBase + ks * 8 * 4);
                uint32_t vf[8][2];
                #pragma unroll
                for (int ntp = 0; ntp < 4; ntp++) {
                    uint32_t r0, r1, r2, r3;
                    LDSM4(r0, r1, r2, r3, vFragBase + (ntp * 16 * FP + ks * 8) * 4);
                    vf[2 * ntp][0] = r0; vf[2 * ntp][1] = r1;
                    vf[2 * ntp + 1][0] = r2; vf[2 * ntp + 1][1] = r3;
                }
                #pragma unroll
                for (int nt = 0; nt < 8; nt++)
                    MMA_TF32(o[nt], pf, vf[nt][0], vf[nt][1]);
            }
        }
        __syncthreads();
    }

    // normalize + write
    float inv0 = 1.f / l0, inv1 = 1.f / l1;
    int row0 = qi * 128 + w * 16 + (lane >> 2);
    long base0 = (long)(b * S_ + row0) * D_ + h * DH_ + 2 * (lane & 3);
    long base1 = base0 + 8 * D_;
    #pragma unroll
    for (int nt = 0; nt < 8; nt++) {
        *(float2*)&O[base0 + nt * 8] = make_float2(o[nt][0] * inv0, o[nt][1] * inv0);
        *(float2*)&O[base1 + nt * 8] = make_float2(o[nt][2] * inv1, o[nt][3] * inv1);
    }
}

// ---------------------------------------------------------------------------
// Launch
// ---------------------------------------------------------------------------
extern "C" void kernel_launch(void* const* d_in, const int* in_sizes, int n_in,
                              void* d_out, int out_size)
{
    const float* hidden = (const float*)d_in[0];
    // d_in[1] = attention_mask: causal tril -> handled analytically
    const float* lora   = (const float*)d_in[2];   // [4, B, D, R]
    const float* ln_w   = (const float*)d_in[3];
    const float* Wq     = (const float*)d_in[4];
    const float* Wk     = (const float*)d_in[5];
    const float* Wv     = (const float*)d_in[6];
    const float* Wo     = (const float*)d_in[7];
    float* out = (float*)d_out;

    float *x, *hq, *hk, *hv, *attn;
    cudaGetSymbolAddress((void**)&x,    g_x);
    cudaGetSymbolAddress((void**)&hq,   g_hq);
    cudaGetSymbolAddress((void**)&hk,   g_hk);
    cudaGetSymbolAddress((void**)&hv,   g_hv);
    cudaGetSymbolAddress((void**)&attn, g_attn);

    cudaFuncSetAttribute(gemm_mma_kernel<false>, cudaFuncAttributeMaxDynamicSharedMemorySize, GEMM_SMEM);
    cudaFuncSetAttribute(gemm_mma_kernel<true>,  cudaFuncAttributeMaxDynamicSharedMemorySize, GEMM_SMEM);
    cudaFuncSetAttribute(flash_mma_kernel, cudaFuncAttributeMaxDynamicSharedMemorySize, FLASH_SMEM);

    // 1. RMSNorm
    rmsnorm_kernel<<<M_, 256>>>(hidden, ln_w, x);

    // 2. QKV projections (tf32 mma.sync)
    dim3 gg(D_ / 128, M_ / 128);
    gemm_mma_kernel<false><<<gg, 128, GEMM_SMEM>>>(x, Wq, nullptr, hq);
    gemm_mma_kernel<false><<<gg, 128, GEMM_SMEM>>>(x, Wk, nullptr, hk);
    gemm_mma_kernel<false><<<gg, 128, GEMM_SMEM>>>(x, Wv, nullptr, hv);

    // 3. LoRA deltas
    const long LSZ = (long)B_ * D_ * R_;
    lora_kernel<<<M_, 256>>>(hq, lora + 0 * LSZ, lora + 2 * LSZ);
    lora_kernel<<<M_, 256>>>(hk, lora + 1 * LSZ, lora + 3 * LSZ);

    // 4. Causal flash attention (tf32 mma.sync)
    dim3 fg(S_ / 128, H_, B_);
    flash_mma_kernel<<<fg, 256, FLASH_SMEM>>>(hq, hk, hv, attn);

    // 5. Output projection + residual
    gemm_mma_kernel<true><<<gg, 128, GEMM_SMEM>>>(attn, Wo, hidden, out);
}

// round 4
// speedup vs baseline: 2.9723x; 1.3626x over previous
#include <cuda_runtime.h>
#include <cstdint>
#include <math.h>

// Problem constants
#define B_  2
#define S_  2048
#define D_  1024
#define H_  16
#define DH_ 64
#define R_  8
#define M_  (B_*S_)          // 4096 rows

// Scratch (device globals; no allocation allowed)
__device__ float g_x[M_*D_];
__device__ float g_hq[M_*D_];
__device__ float g_hk[M_*D_];
__device__ float g_hv[M_*D_];
__device__ float g_attn[M_*D_];

#define FULLMASK 0xffffffffu

// ===========================================================================
// PTX helpers (arch-agnostic: mma.sync + ldmatrix + cp.async)
// ===========================================================================
__device__ __forceinline__ uint32_t smem_u32(const void* p) {
    uint32_t a;
    asm("{ .reg .u64 t; cvta.to.shared.u64 t, %1; cvt.u32.u64 %0, t; }"
        : "=r"(a) : "l"(p));
    return a;
}

#define LDSM4(R0,R1,R2,R3,ADDR) \
    asm volatile("ldmatrix.sync.aligned.m8n8.x4.shared.b16 {%0,%1,%2,%3}, [%4];" \
        : "=r"(R0), "=r"(R1), "=r"(R2), "=r"(R3) : "r"(ADDR))

#define MMA_TF32(C, A, B0, B1) \
    asm volatile("mma.sync.aligned.m16n8k8.row.col.f32.tf32.tf32.f32 " \
        "{%0,%1,%2,%3}, {%4,%5,%6,%7}, {%8,%9}, {%0,%1,%2,%3};" \
        : "+f"((C)[0]), "+f"((C)[1]), "+f"((C)[2]), "+f"((C)[3]) \
        : "r"((A)[0]), "r"((A)[1]), "r"((A)[2]), "r"((A)[3]), "r"(B0), "r"(B1))

#define CP16(DST, SRC) \
    asm volatile("cp.async.cg.shared.global [%0], [%1], 16;" :: "r"(DST), "l"(SRC))
#define CP_COMMIT() asm volatile("cp.async.commit_group;" ::: "memory")
#define CP_WAIT(N)  asm volatile("cp.async.wait_group %0;" :: "n"(N) : "memory")

// ---------------------------------------------------------------------------
// RMSNorm
// ---------------------------------------------------------------------------
__global__ __launch_bounds__(256) void rmsnorm_kernel(
    const float* __restrict__ hs, const float* __restrict__ w, float* __restrict__ out)
{
    int row = blockIdx.x;
    int t = threadIdx.x;
    const float* x = hs + (long)row * D_;

    float v[4];
    float ss = 0.f;
    #pragma unroll
    for (int i = 0; i < 4; i++) {
        v[i] = x[t + i * 256];
        ss += v[i] * v[i];
    }
    #pragma unroll
    for (int o = 16; o > 0; o >>= 1) ss += __shfl_xor_sync(FULLMASK, ss, o);
    __shared__ float red[8];
    if ((t & 31) == 0) red[t >> 5] = ss;
    __syncthreads();
    __shared__ float s_inv;
    if (t == 0) {
        float s = 0.f;
        #pragma unroll
        for (int i = 0; i < 8; i++) s += red[i];
        s_inv = rsqrtf(s / (float)D_ + 1e-5f);
    }
    __syncthreads();
    float inv = s_inv;
    #pragma unroll
    for (int i = 0; i < 4; i++) {
        int d = t + i * 256;
        out[(long)row * D_ + d] = v[i] * inv * w[d];
    }
}

// ---------------------------------------------------------------------------
// Shared GEMM core: C[128x128 tile] = A @ W^T (+resid). 256 threads, 8 warps,
// warp tile 32x64, cp.async double-buffered, BK=32, smem pitch 36 floats.
// ---------------------------------------------------------------------------
#define GP 36
#define GTILE_B (128*GP*4)       // 18432 bytes per tile buffer
#define GEMM_SMEM (4*GTILE_B)    // 73728

template <bool RESID>
__device__ __forceinline__ void gemm128_core(
    const float* __restrict__ A, const float* __restrict__ W,
    const float* __restrict__ resid, float* __restrict__ C,
    int by, int bx, char* gsm)
{
    const uint32_t sA = smem_u32(gsm);
    const uint32_t sB = sA + 2 * GTILE_B;
    int tid = threadIdx.x;
    int lane = tid & 31;
    int w = tid >> 5;             // 0..7
    int wm = (w >> 1) * 32;
    int wn = (w & 1) * 64;

    const float* aP[4]; const float* bP[4];
    uint32_t stA[4], stB[4];
    #pragma unroll
    for (int l = 0; l < 4; l++) {
        int idx = tid + l * 256;  // 0..1023
        int r = idx >> 3, c4 = idx & 7;
        aP[l] = A + (long)(by * 128 + r) * D_ + c4 * 4;
        bP[l] = W + (long)(bx * 128 + r) * D_ + c4 * 4;
        stA[l] = sA + r * (GP * 4) + c4 * 16;
        stB[l] = sB + r * (GP * 4) + c4 * 16;
    }

    float acc[2][8][4];
    #pragma unroll
    for (int mt = 0; mt < 2; mt++)
        #pragma unroll
        for (int nt = 0; nt < 8; nt++)
            #pragma unroll
            for (int j = 0; j < 4; j++) acc[mt][nt][j] = 0.f;

    const uint32_t aFragBase = sA +
        ((wm + (lane & 15)) * GP + ((lane >> 4) << 2)) * 4;
    const uint32_t bFragBase = sB +
        ((wn + (lane & 7) + ((lane >> 4) << 3)) * GP + (((lane >> 3) & 1) << 2)) * 4;

    #pragma unroll
    for (int l = 0; l < 4; l++) { CP16(stA[l], aP[l]); CP16(stB[l], bP[l]); }
    CP_COMMIT();

    for (int kc = 0; kc < 32; kc++) {
        int buf = kc & 1;
        if (kc + 1 < 32) {
            #pragma unroll
            for (int l = 0; l < 4; l++) {
                CP16(stA[l] + (buf ^ 1) * GTILE_B, aP[l] + (kc + 1) * 32);
                CP16(stB[l] + (buf ^ 1) * GTILE_B, bP[l] + (kc + 1) * 32);
            }
            CP_COMMIT();
            CP_WAIT(1);
        } else {
            CP_WAIT(0);
        }
        __syncthreads();

        uint32_t aBuf = aFragBase + buf * GTILE_B;
        uint32_t bBuf = bFragBase + buf * GTILE_B;

        #pragma unroll
        for (int ks = 0; ks < 4; ks++) {
            uint32_t af[2][4];
            uint32_t bf[8][2];
            #pragma unroll
            for (int mt = 0; mt < 2; mt++)
                LDSM4(af[mt][0], af[mt][1], af[mt][2], af[mt][3],
                      aBuf + (mt * 16 * GP + ks * 8) * 4);
            #pragma unroll
            for (int ntp = 0; ntp < 4; ntp++) {
                uint32_t r0, r1, r2, r3;
                LDSM4(r0, r1, r2, r3, bBuf + (ntp * 16 * GP + ks * 8) * 4);
                bf[2 * ntp][0] = r0; bf[2 * ntp][1] = r1;
                bf[2 * ntp + 1][0] = r2; bf[2 * ntp + 1][1] = r3;
            }
            #pragma unroll
            for (int mt = 0; mt < 2; mt++)
                #pragma unroll
                for (int nt = 0; nt < 8; nt++)
                    MMA_TF32(acc[mt][nt], af[mt], bf[nt][0], bf[nt][1]);
        }
        __syncthreads();
    }

    // Epilogue
    #pragma unroll
    for (int mt = 0; mt < 2; mt++) {
        int row = by * 128 + wm + mt * 16 + (lane >> 2);
        int col = bx * 128 + wn + 2 * (lane & 3);
        #pragma unroll
        for (int nt = 0; nt < 8; nt++) {
            long i0 = (long)row * D_ + col + nt * 8;
            long i1 = i0 + 8 * D_;
            float2 v0 = make_float2(acc[mt][nt][0], acc[mt][nt][1]);
            float2 v1 = make_float2(acc[mt][nt][2], acc[mt][nt][3]);
            if (RESID) {
                float2 r0 = *(const float2*)&resid[i0];
                float2 r1 = *(const float2*)&resid[i1];
                v0.x += r0.x; v0.y += r0.y;
                v1.x += r1.x; v1.y += r1.y;
            }
            *(float2*)&C[i0] = v0;
            *(float2*)&C[i1] = v1;
        }
    }
}

// Fused QKV: grid (24, 32) — blockIdx.x selects weight (x>>3) and col block (x&7)
__global__ __launch_bounds__(256, 2) void gemm_qkv_kernel(
    const float* __restrict__ A,
    const float* __restrict__ Wq, const float* __restrict__ Wk, const float* __restrict__ Wv,
    float* __restrict__ hq, float* __restrict__ hk, float* __restrict__ hv)
{
    extern __shared__ __align__(16) char gsm[];
    int wsel = blockIdx.x >> 3;
    int bx = blockIdx.x & 7;
    const float* W = (wsel == 0) ? Wq : (wsel == 1) ? Wk : Wv;
    float* C = (wsel == 0) ? hq : (wsel == 1) ? hk : hv;
    gemm128_core<false>(A, W, nullptr, C, blockIdx.y, bx, gsm);
}

// Output projection + residual: grid (8, 32)
__global__ __launch_bounds__(256, 2) void gemm_o_kernel(
    const float* __restrict__ A, const float* __restrict__ W,
    const float* __restrict__ resid, float* __restrict__ C)
{
    extern __shared__ __align__(16) char gsm[];
    gemm128_core<true>(A, W, resid, C, blockIdx.y, blockIdx.x, gsm);
}

// ---------------------------------------------------------------------------
// LoRA: h[i,:] += 2 * (h[i,:] @ A[b]) @ B[b]^T   (one block per row)
// ---------------------------------------------------------------------------
__global__ __launch_bounds__(256) void lora_kernel(
    float* __restrict__ h, const float* __restrict__ A, const float* __restrict__ Bm)
{
    int i = blockIdx.x;
    int b = i / S_;
    int t = threadIdx.x;
    const float* Ab = A + (long)b * D_ * R_;
    const float* Bb = Bm + (long)b * D_ * R_;

    float hr[4];
    float part[R_];
    #pragma unroll
    for (int r = 0; r < R_; r++) part[r] = 0.f;
    #pragma unroll
    for (int l = 0; l < 4; l++) {
        int d = t + l * 256;
        hr[l] = h[(long)i * D_ + d];
        #pragma unroll
        for (int r = 0; r < R_; r++) part[r] += hr[l] * Ab[d * R_ + r];
    }
    #pragma unroll
    for (int r = 0; r < R_; r++)
        #pragma unroll
        for (int o = 16; o > 0; o >>= 1)
            part[r] += __shfl_xor_sync(FULLMASK, part[r], o);
    __shared__ float zred[8][R_];
    if ((t & 31) == 0)
        #pragma unroll
        for (int r = 0; r < R_; r++) zred[t >> 5][r] = part[r];
    __syncthreads();
    __shared__ float z[R_];
    if (t < R_) {
        float s = 0.f;
        #pragma unroll
        for (int w = 0; w < 8; w++) s += zred[w][t];
        z[t] = s;
    }
    __syncthreads();
    #pragma unroll
    for (int l = 0; l < 4; l++) {
        int d = t + l * 256;
        float delta = 0.f;
        #pragma unroll
        for (int r = 0; r < R_; r++) delta += z[r] * Bb[d * R_ + r];
        h[(long)i * D_ + d] = hr[l] + 2.f * delta;
    }
}

// ---------------------------------------------------------------------------
// Flash attention, tf32 mma, causal. Q tile = 128, K/V tile = 64.
// 8 warps x 16 q-rows. Register-pipelined K/V prefetch. Heavy tiles first.
// ---------------------------------------------------------------------------
#define FP 68
#define FLASH_SMEM ((128 + 64 + 64 + 128) * FP * 4)   // 104448

__global__ __launch_bounds__(256, 1) void flash_mma_kernel(
    const float* __restrict__ Q, const float* __restrict__ K,
    const float* __restrict__ V, float* __restrict__ O)
{
    extern __shared__ __align__(16) float smf[];
    float* Qs = smf;
    float* Ks = Qs + 128 * FP;
    float* Vs = Ks + 64 * FP;      // [d][kpos]
    float* Ps = Vs + 64 * FP;
    const uint32_t qsB = smem_u32(Qs);
    const uint32_t ksB = smem_u32(Ks);
    const uint32_t vsB = smem_u32(Vs);
    const uint32_t psB = smem_u32(Ps);

    int qi = (gridDim.x - 1) - blockIdx.x;   // heavy tiles launch first
    int h  = blockIdx.y;
    int b  = blockIdx.z;
    int tid = threadIdx.x;
    int lane = tid & 31;
    int w = tid >> 5;

    const float* Qp = Q + (long)(b * S_ + qi * 128) * D_ + h * DH_;

    // Load Q tile [128][64]
    #pragma unroll
    for (int l = 0; l < 8; l++) {
        int idx = tid + l * 256;
        int q = idx >> 4, c4 = idx & 15;
        float4 v = *(const float4*)&Qp[(long)q * D_ + c4 * 4];
        *(float4*)&Qs[q * FP + c4 * 4] = v;
    }

    // Load K/V tile 0 directly
    {
        const float* Kp = K + (long)(b * S_) * D_ + h * DH_;
        const float* Vp = V + (long)(b * S_) * D_ + h * DH_;
        #pragma unroll
        for (int l = 0; l < 4; l++) {
            int idx = tid + l * 256;
            int kp = idx >> 4, c4 = idx & 15;
            float4 v = *(const float4*)&Kp[(long)kp * D_ + c4 * 4];
            *(float4*)&Ks[kp * FP + c4 * 4] = v;
        }
        int kp = tid & 63;
        int half = tid >> 6;
        #pragma unroll
        for (int i = 0; i < 4; i++) {
            int c4 = half * 4 + i;
            float4 v = *(const float4*)&Vp[(long)kp * D_ + c4 * 4];
            Vs[(c4 * 4 + 0) * FP + kp] = v.x;
            Vs[(c4 * 4 + 1) * FP + kp] = v.y;
            Vs[(c4 * 4 + 2) * FP + kp] = v.z;
            Vs[(c4 * 4 + 3) * FP + kp] = v.w;
        }
    }
    __syncthreads();

    // Q fragments (resident)
    uint32_t qf[8][4];
    {
        uint32_t base = qsB + ((w * 16 + (lane & 15)) * FP + ((lane >> 4) << 2)) * 4;
        #pragma unroll
        for (int ds = 0; ds < 8; ds++)
            LDSM4(qf[ds][0], qf[ds][1], qf[ds][2], qf[ds][3], base + ds * 8 * 4);
    }

    float o[8][4];
    #pragma unroll
    for (int nt = 0; nt < 8; nt++)
        #pragma unroll
        for (int j = 0; j < 4; j++) o[nt][j] = 0.f;
    float m0 = -1e30f, m1 = -1e30f, l0 = 0.f, l1 = 0.f;

    const uint32_t kFragBase = ksB +
        (((lane & 7) + ((lane >> 4) << 3)) * FP + (((lane >> 3) & 1) << 2)) * 4;
    const uint32_t vFragBase = vsB +
        (((lane & 7) + ((lane >> 4) << 3)) * FP + (((lane >> 3) & 1) << 2)) * 4;
    const uint32_t pFragBase = psB +
        ((w * 16 + (lane & 15)) * FP + ((lane >> 4) << 2)) * 4;
    float* pRow0 = Ps + (w * 16 + (lane >> 2)) * FP + 2 * (lane & 3);

    int ktmax = 2 * qi + 2;
    for (int kt = 0; kt < ktmax; kt++) {
        // Prefetch next K/V tile into registers (hides global latency)
        float4 kreg[4], vreg[4];
        bool havenext = (kt + 1) < ktmax;
        if (havenext) {
            const float* Kp = K + (long)(b * S_ + (kt + 1) * 64) * D_ + h * DH_;
            const float* Vp = V + (long)(b * S_ + (kt + 1) * 64) * D_ + h * DH_;
            #pragma unroll
            for (int l = 0; l < 4; l++) {
                int idx = tid + l * 256;
                int kp = idx >> 4, c4 = idx & 15;
                kreg[l] = *(const float4*)&Kp[(long)kp * D_ + c4 * 4];
            }
            int kp = tid & 63;
            int half = tid >> 6;
            #pragma unroll
            for (int i = 0; i < 4; i++) {
                int c4 = half * 4 + i;
                vreg[i] = *(const float4*)&Vp[(long)kp * D_ + c4 * 4];
            }
        }

        bool active = (kt * 64) <= (qi * 128 + w * 16 + 15);
        if (active) {
            // S = Q K^T
            float s[8][4];
            #pragma unroll
            for (int nt = 0; nt < 8; nt++)
                #pragma unroll
                for (int j = 0; j < 4; j++) s[nt][j] = 0.f;

            #pragma unroll
            for (int ds = 0; ds < 8; ds++) {
                uint32_t bf[8][2];
                #pragma unroll
                for (int ntp = 0; ntp < 4; ntp++) {
                    uint32_t r0, r1, r2, r3;
                    LDSM4(r0, r1, r2, r3, kFragBase + (ntp * 16 * FP + ds * 8) * 4);
                    bf[2 * ntp][0] = r0; bf[2 * ntp][1] = r1;
                    bf[2 * ntp + 1][0] = r2; bf[2 * ntp + 1][1] = r3;
                }
                #pragma unroll
                for (int nt = 0; nt < 8; nt++)
                    MMA_TF32(s[nt], qf[ds], bf[nt][0], bf[nt][1]);
            }

            // scale + causal mask + online softmax
            bool needmask = (kt * 64 + 63) > (qi * 128 + w * 16);
            int row0 = qi * 128 + w * 16 + (lane >> 2);
            float ml0 = -1e30f, ml1 = -1e30f;
            #pragma unroll
            for (int nt = 0; nt < 8; nt++) {
                #pragma unroll
                for (int j = 0; j < 4; j++) {
                    float v = s[nt][j] * 0.125f;
                    if (needmask) {
                        int col = kt * 64 + nt * 8 + 2 * (lane & 3) + (j & 1);
                        int row = row0 + ((j >> 1) << 3);
                        if (col > row) v = -1e30f;
                    }
                    s[nt][j] = v;
                }
                ml0 = fmaxf(ml0, fmaxf(s[nt][0], s[nt][1]));
                ml1 = fmaxf(ml1, fmaxf(s[nt][2], s[nt][3]));
            }
            ml0 = fmaxf(ml0, __shfl_xor_sync(FULLMASK, ml0, 1));
            ml0 = fmaxf(ml0, __shfl_xor_sync(FULLMASK, ml0, 2));
            ml1 = fmaxf(ml1, __shfl_xor_sync(FULLMASK, ml1, 1));
            ml1 = fmaxf(ml1, __shfl_xor_sync(FULLMASK, ml1, 2));
            float mn0 = fmaxf(m0, ml0), mn1 = fmaxf(m1, ml1);
            float a0 = __expf(m0 - mn0), a1 = __expf(m1 - mn1);
            float sum0 = 0.f, sum1 = 0.f;
            #pragma unroll
            for (int nt = 0; nt < 8; nt++) {
                s[nt][0] = __expf(s[nt][0] - mn0);
                s[nt][1] = __expf(s[nt][1] - mn0);
                s[nt][2] = __expf(s[nt][2] - mn1);
                s[nt][3] = __expf(s[nt][3] - mn1);
                sum0 += s[nt][0] + s[nt][1];
                sum1 += s[nt][2] + s[nt][3];
            }
            sum0 += __shfl_xor_sync(FULLMASK, sum0, 1);
            sum0 += __shfl_xor_sync(FULLMASK, sum0, 2);
            sum1 += __shfl_xor_sync(FULLMASK, sum1, 1);
            sum1 += __shfl_xor_sync(FULLMASK, sum1, 2);
            l0 = l0 * a0 + sum0;
            l1 = l1 * a1 + sum1;
            m0 = mn0; m1 = mn1;
            #pragma unroll
            for (int nt = 0; nt < 8; nt++) {
                o[nt][0] *= a0; o[nt][1] *= a0;
                o[nt][2] *= a1; o[nt][3] *= a1;
            }

            // store P (per-warp slice)
            #pragma unroll
            for (int nt = 0; nt < 8; nt++) {
                *(float2*)&pRow0[nt * 8] = make_float2(s[nt][0], s[nt][1]);
                *(float2*)&pRow0[8 * FP + nt * 8] = make_float2(s[nt][2], s[nt][3]);
            }
            __syncwarp();

            // O += P V
            #pragma unroll
            for (int ks = 0; ks < 8; ks++) {
                uint32_t pf[4];
                LDSM4(pf[0], pf[1], pf[2], pf[3], pFragBase + ks * 8 * 4);
                uint32_t vf[8][2];
                #pragma unroll
                for (int ntp = 0; ntp < 4; ntp++) {
                    uint32_t r0, r1, r2, r3;
                    LDSM4(r0, r1, r2, r3, vFragBase + (ntp * 16 * FP + ks * 8) * 4);
                    vf[2 * ntp][0] = r0; vf[2 * ntp][1] = r1;
                    vf[2 * ntp + 1][0] = r2; vf[2 * ntp + 1][1] = r3;
                }
                #pragma unroll
                for (int nt = 0; nt < 8; nt++)
                    MMA_TF32(o[nt], pf, vf[nt][0], vf[nt][1]);
            }
        }
        __syncthreads();

        if (havenext) {
            #pragma unroll
            for (int l = 0; l < 4; l++) {
                int idx = tid + l * 256;
                int kp = idx >> 4, c4 = idx & 15;
                *(float4*)&Ks[kp * FP + c4 * 4] = kreg[l];
            }
            int kp = tid & 63;
            int half = tid >> 6;
            #pragma unroll
            for (int i = 0; i < 4; i++) {
                int c4 = half * 4 + i;
                Vs[(c4 * 4 + 0) * FP + kp] = vreg[i].x;
                Vs[(c4 * 4 + 1) * FP + kp] = vreg[i].y;
                Vs[(c4 * 4 + 2) * FP + kp] = vreg[i].z;
                Vs[(c4 * 4 + 3) * FP + kp] = vreg[i].w;
            }
            __syncthreads();
        }
    }

    // normalize + write
    float inv0 = 1.f / l0, inv1 = 1.f / l1;
    int row0 = qi * 128 + w * 16 + (lane >> 2);
    long base0 = (long)(b * S_ + row0) * D_ + h * DH_ + 2 * (lane & 3);
    long base1 = base0 + 8 * D_;
    #pragma unroll
    for (int nt = 0; nt < 8; nt++) {
        *(float2*)&O[base0 + nt * 8] = make_float2(o[nt][0] * inv0, o[nt][1] * inv0);
        *(float2*)&O[base1 + nt * 8] = make_float2(o[nt][2] * inv1, o[nt][3] * inv1);
    }
}

// ---------------------------------------------------------------------------
// Launch
// ---------------------------------------------------------------------------
extern "C" void kernel_launch(void* const* d_in, const int* in_sizes, int n_in,
                              void* d_out, int out_size)
{
    const float* hidden = (const float*)d_in[0];
    // d_in[1] = attention_mask: causal tril -> handled analytically
    const float* lora   = (const float*)d_in[2];   // [4, B, D, R]
    const float* ln_w   = (const float*)d_in[3];
    const float* Wq     = (const float*)d_in[4];
    const float* Wk     = (const float*)d_in[5];
    const float* Wv     = (const float*)d_in[6];
    const float* Wo     = (const float*)d_in[7];
    float* out = (float*)d_out;

    float *x, *hq, *hk, *hv, *attn;
    cudaGetSymbolAddress((void**)&x,    g_x);
    cudaGetSymbolAddress((void**)&hq,   g_hq);
    cudaGetSymbolAddress((void**)&hk,   g_hk);
    cudaGetSymbolAddress((void**)&hv,   g_hv);
    cudaGetSymbolAddress((void**)&attn, g_attn);

    cudaFuncSetAttribute(gemm_qkv_kernel, cudaFuncAttributeMaxDynamicSharedMemorySize, GEMM_SMEM);
    cudaFuncSetAttribute(gemm_o_kernel,   cudaFuncAttributeMaxDynamicSharedMemorySize, GEMM_SMEM);
    cudaFuncSetAttribute(flash_mma_kernel, cudaFuncAttributeMaxDynamicSharedMemorySize, FLASH_SMEM);

    // 1. RMSNorm
    rmsnorm_kernel<<<M_, 256>>>(hidden, ln_w, x);

    // 2. Fused QKV projections
    dim3 gq(24, M_ / 128);
    gemm_qkv_kernel<<<gq, 256, GEMM_SMEM>>>(x, Wq, Wk, Wv, hq, hk, hv);

    // 3. LoRA deltas
    const long LSZ = (long)B_ * D_ * R_;
    lora_kernel<<<M_, 256>>>(hq, lora + 0 * LSZ, lora + 2 * LSZ);
    lora_kernel<<<M_, 256>>>(hk, lora + 1 * LSZ, lora + 3 * LSZ);

    // 4. Causal flash attention
    dim3 fg(S_ / 128, H_, B_);
    flash_mma_kernel<<<fg, 256, FLASH_SMEM>>>(hq, hk, hv, attn);

    // 5. Output projection + residual
    dim3 go(8, M_ / 128);
    gemm_o_kernel<<<go, 256, GEMM_SMEM>>>(attn, Wo, hidden, out);
}

// round 5
// speedup vs baseline: 3.4148x; 1.1489x over previous
#include <cuda_runtime.h>
#include <cstdint>
#include <math.h>

// Problem constants
#define B_  2
#define S_  2048
#define D_  1024
#define H_  16
#define DH_ 64
#define R_  8
#define M_  (B_*S_)          // 4096 rows

// Scratch (device globals; no allocation allowed)
__device__ float g_x[M_*D_];
__device__ float g_hq[M_*D_];
__device__ float g_hk[M_*D_];
__device__ float g_hv[M_*D_];
__device__ float g_attn[M_*D_];

#define FULLMASK 0xffffffffu

// ===========================================================================
// PTX helpers (arch-agnostic: mma.sync + ldmatrix + cp.async)
// ===========================================================================
__device__ __forceinline__ uint32_t smem_u32(const void* p) {
    uint32_t a;
    asm("{ .reg .u64 t; cvta.to.shared.u64 t, %1; cvt.u32.u64 %0, t; }"
        : "=r"(a) : "l"(p));
    return a;
}

#define LDSM4(R0,R1,R2,R3,ADDR) \
    asm volatile("ldmatrix.sync.aligned.m8n8.x4.shared.b16 {%0,%1,%2,%3}, [%4];" \
        : "=r"(R0), "=r"(R1), "=r"(R2), "=r"(R3) : "r"(ADDR))

#define MMA_TF32(C, A, B0, B1) \
    asm volatile("mma.sync.aligned.m16n8k8.row.col.f32.tf32.tf32.f32 " \
        "{%0,%1,%2,%3}, {%4,%5,%6,%7}, {%8,%9}, {%0,%1,%2,%3};" \
        : "+f"((C)[0]), "+f"((C)[1]), "+f"((C)[2]), "+f"((C)[3]) \
        : "r"((A)[0]), "r"((A)[1]), "r"((A)[2]), "r"((A)[3]), "r"(B0), "r"(B1))

#define CP16(DST, SRC) \
    asm volatile("cp.async.cg.shared.global [%0], [%1], 16;" :: "r"(DST), "l"(SRC))
#define CP_COMMIT() asm volatile("cp.async.commit_group;" ::: "memory")
#define CP_WAIT(N)  asm volatile("cp.async.wait_group %0;" :: "n"(N) : "memory")

// ---------------------------------------------------------------------------
// RMSNorm
// ---------------------------------------------------------------------------
__global__ __launch_bounds__(256) void rmsnorm_kernel(
    const float* __restrict__ hs, const float* __restrict__ w, float* __restrict__ out)
{
    int row = blockIdx.x;
    int t = threadIdx.x;
    const float* x = hs + (long)row * D_;

    float v[4];
    float ss = 0.f;
    #pragma unroll
    for (int i = 0; i < 4; i++) {
        v[i] = x[t + i * 256];
        ss += v[i] * v[i];
    }
    #pragma unroll
    for (int o = 16; o > 0; o >>= 1) ss += __shfl_xor_sync(FULLMASK, ss, o);
    __shared__ float red[8];
    if ((t & 31) == 0) red[t >> 5] = ss;
    __syncthreads();
    __shared__ float s_inv;
    if (t == 0) {
        float s = 0.f;
        #pragma unroll
        for (int i = 0; i < 8; i++) s += red[i];
        s_inv = rsqrtf(s / (float)D_ + 1e-5f);
    }
    __syncthreads();
    float inv = s_inv;
    #pragma unroll
    for (int i = 0; i < 4; i++) {
        int d = t + i * 256;
        out[(long)row * D_ + d] = v[i] * inv * w[d];
    }
}

// ---------------------------------------------------------------------------
// Shared GEMM core: C[128x128 tile] = A @ W^T (+resid). 256 threads, 8 warps,
// warp tile 32x64, cp.async double-buffered, BK=32, smem pitch 36 floats.
// ---------------------------------------------------------------------------
#define GP 36
#define GTILE_B (128*GP*4)       // 18432 bytes per tile buffer
#define GEMM_SMEM (4*GTILE_B)    // 73728

template <bool RESID>
__device__ __forceinline__ void gemm128_core(
    const float* __restrict__ A, const float* __restrict__ W,
    const float* __restrict__ resid, float* __restrict__ C,
    int by, int bx, char* gsm)
{
    const uint32_t sA = smem_u32(gsm);
    const uint32_t sB = sA + 2 * GTILE_B;
    int tid = threadIdx.x;
    int lane = tid & 31;
    int w = tid >> 5;             // 0..7
    int wm = (w >> 1) * 32;
    int wn = (w & 1) * 64;

    const float* aP[4]; const float* bP[4];
    uint32_t stA[4], stB[4];
    #pragma unroll
    for (int l = 0; l < 4; l++) {
        int idx = tid + l * 256;  // 0..1023
        int r = idx >> 3, c4 = idx & 7;
        aP[l] = A + (long)(by * 128 + r) * D_ + c4 * 4;
        bP[l] = W + (long)(bx * 128 + r) * D_ + c4 * 4;
        stA[l] = sA + r * (GP * 4) + c4 * 16;
        stB[l] = sB + r * (GP * 4) + c4 * 16;
    }

    float acc[2][8][4];
    #pragma unroll
    for (int mt = 0; mt < 2; mt++)
        #pragma unroll
        for (int nt = 0; nt < 8; nt++)
            #pragma unroll
            for (int j = 0; j < 4; j++) acc[mt][nt][j] = 0.f;

    const uint32_t aFragBase = sA +
        ((wm + (lane & 15)) * GP + ((lane >> 4) << 2)) * 4;
    const uint32_t bFragBase = sB +
        ((wn + (lane & 7) + ((lane >> 4) << 3)) * GP + (((lane >> 3) & 1) << 2)) * 4;

    #pragma unroll
    for (int l = 0; l < 4; l++) { CP16(stA[l], aP[l]); CP16(stB[l], bP[l]); }
    CP_COMMIT();

    for (int kc = 0; kc < 32; kc++) {
        int buf = kc & 1;
        if (kc + 1 < 32) {
            #pragma unroll
            for (int l = 0; l < 4; l++) {
                CP16(stA[l] + (buf ^ 1) * GTILE_B, aP[l] + (kc + 1) * 32);
                CP16(stB[l] + (buf ^ 1) * GTILE_B, bP[l] + (kc + 1) * 32);
            }
            CP_COMMIT();
            CP_WAIT(1);
        } else {
            CP_WAIT(0);
        }
        __syncthreads();

        uint32_t aBuf = aFragBase + buf * GTILE_B;
        uint32_t bBuf = bFragBase + buf * GTILE_B;

        #pragma unroll
        for (int ks = 0; ks < 4; ks++) {
            uint32_t af[2][4];
            uint32_t bf[8][2];
            #pragma unroll
            for (int mt = 0; mt < 2; mt++)
                LDSM4(af[mt][0], af[mt][1], af[mt][2], af[mt][3],
                      aBuf + (mt * 16 * GP + ks * 8) * 4);
            #pragma unroll
            for (int ntp = 0; ntp < 4; ntp++) {
                uint32_t r0, r1, r2, r3;
                LDSM4(r0, r1, r2, r3, bBuf + (ntp * 16 * GP + ks * 8) * 4);
                bf[2 * ntp][0] = r0; bf[2 * ntp][1] = r1;
                bf[2 * ntp + 1][0] = r2; bf[2 * ntp + 1][1] = r3;
            }
            #pragma unroll
            for (int mt = 0; mt < 2; mt++)
                #pragma unroll
                for (int nt = 0; nt < 8; nt++)
                    MMA_TF32(acc[mt][nt], af[mt], bf[nt][0], bf[nt][1]);
        }
        __syncthreads();
    }

    // Epilogue
    #pragma unroll
    for (int mt = 0; mt < 2; mt++) {
        int row = by * 128 + wm + mt * 16 + (lane >> 2);
        int col = bx * 128 + wn + 2 * (lane & 3);
        #pragma unroll
        for (int nt = 0; nt < 8; nt++) {
            long i0 = (long)row * D_ + col + nt * 8;
            long i1 = i0 + 8 * D_;
            float2 v0 = make_float2(acc[mt][nt][0], acc[mt][nt][1]);
            float2 v1 = make_float2(acc[mt][nt][2], acc[mt][nt][3]);
            if (RESID) {
                float2 r0 = *(const float2*)&resid[i0];
                float2 r1 = *(const float2*)&resid[i1];
                v0.x += r0.x; v0.y += r0.y;
                v1.x += r1.x; v1.y += r1.y;
            }
            *(float2*)&C[i0] = v0;
            *(float2*)&C[i1] = v1;
        }
    }
}

// Fused QKV: grid (24, 32)
__global__ __launch_bounds__(256, 2) void gemm_qkv_kernel(
    const float* __restrict__ A,
    const float* __restrict__ Wq, const float* __restrict__ Wk, const float* __restrict__ Wv,
    float* __restrict__ hq, float* __restrict__ hk, float* __restrict__ hv)
{
    extern __shared__ __align__(16) char gsm[];
    int wsel = blockIdx.x >> 3;
    int bx = blockIdx.x & 7;
    const float* W = (wsel == 0) ? Wq : (wsel == 1) ? Wk : Wv;
    float* C = (wsel == 0) ? hq : (wsel == 1) ? hk : hv;
    gemm128_core<false>(A, W, nullptr, C, blockIdx.y, bx, gsm);
}

// Output projection + residual: grid (8, 32)
__global__ __launch_bounds__(256, 2) void gemm_o_kernel(
    const float* __restrict__ A, const float* __restrict__ W,
    const float* __restrict__ resid, float* __restrict__ C)
{
    extern __shared__ __align__(16) char gsm[];
    gemm128_core<true>(A, W, resid, C, blockIdx.y, blockIdx.x, gsm);
}

// ---------------------------------------------------------------------------
// Fused LoRA (q and k in one launch): h += 2 * (h @ A) @ B^T
// Grid (M_/32, 2). 32 rows per block. A,B staged in smem TRANSPOSED to [r][d]
// so all inner loads are stride-1 (conflict-free).
// Dynamic smem: As_t[8][1024] + Bs_t[8][1024] = 64 KB.
// ---------------------------------------------------------------------------
#define LROWS 32
#define LORA_SMEM (2 * R_ * D_ * 4)   // 65536

__global__ __launch_bounds__(256) void lora_fused_kernel(
    float* __restrict__ hq, float* __restrict__ hk, const float* __restrict__ lora)
{
    int which = blockIdx.y;                 // 0 = q, 1 = k
    float* h = which ? hk : hq;
    int rowBase = blockIdx.x * LROWS;
    int b = rowBase / S_;                   // constant within block (32 | 2048)
    const float* Ag = lora + ((long)which * B_ + b) * D_ * R_;        // [d][r]
    const float* Bg = lora + ((long)(2 + which) * B_ + b) * D_ * R_;  // [d][r]

    extern __shared__ __align__(16) float lsm[];
    float* As = lsm;             // [r][d] transposed
    float* Bs = lsm + R_ * D_;   // [r][d] transposed
    __shared__ float z[LROWS][R_];

    int tid = threadIdx.x;
    int lane = tid & 31, w = tid >> 5;

    // Stage A,B transposed: thread handles d = tid + 256k
    #pragma unroll
    for (int k = 0; k < 4; k++) {
        int d = tid + k * 256;
        float4 a0 = *(const float4*)&Ag[d * R_];
        float4 a1 = *(const float4*)&Ag[d * R_ + 4];
        float4 b0 = *(const float4*)&Bg[d * R_];
        float4 b1 = *(const float4*)&Bg[d * R_ + 4];
        As[0*D_+d] = a0.x; As[1*D_+d] = a0.y; As[2*D_+d] = a0.z; As[3*D_+d] = a0.w;
        As[4*D_+d] = a1.x; As[5*D_+d] = a1.y; As[6*D_+d] = a1.z; As[7*D_+d] = a1.w;
        Bs[0*D_+d] = b0.x; Bs[1*D_+d] = b0.y; Bs[2*D_+d] = b0.z; Bs[3*D_+d] = b0.w;
        Bs[4*D_+d] = b1.x; Bs[5*D_+d] = b1.y; Bs[6*D_+d] = b1.z; Bs[7*D_+d] = b1.w;
    }
    __syncthreads();

    // Phase 1: z[row][:] = h[row] @ A.  Warp w owns rows 4w..4w+3.
    #pragma unroll
    for (int rr = 0; rr < 4; rr++) {
        int row = rowBase + w * 4 + rr;
        const float* hrow = h + (long)row * D_;
        float part[R_];
        #pragma unroll
        for (int r = 0; r < R_; r++) part[r] = 0.f;
        #pragma unroll
        for (int k = 0; k < 32; k++) {
            int d = lane + k * 32;
            float hv = hrow[d];
            #pragma unroll
            for (int r = 0; r < R_; r++) part[r] += hv * As[r * D_ + d];
        }
        #pragma unroll
        for (int r = 0; r < R_; r++)
            #pragma unroll
            for (int o = 16; o > 0; o >>= 1)
                part[r] += __shfl_xor_sync(FULLMASK, part[r], o);
        if (lane == 0)
            #pragma unroll
            for (int r = 0; r < R_; r++) z[w * 4 + rr][r] = part[r];
    }
    __syncthreads();

    // Phase 2: h[row][d] += 2 * sum_r z[row][r] * B[d][r]
    // Each thread owns 4 d-values; B fragments stay in registers across rows.
    #pragma unroll
    for (int k = 0; k < 4; k++) {
        int d = tid + k * 256;
        float br[R_];
        #pragma unroll
        for (int r = 0; r < R_; r++) br[r] = Bs[r * D_ + d];
        for (int rr = 0; rr < LROWS; rr++) {
            long idx = (long)(rowBase + rr) * D_ + d;
            float delta = 0.f;
            #pragma unroll
            for (int r = 0; r < R_; r++) delta += z[rr][r] * br[r];
            h[idx] += 2.f * delta;
        }
    }
}

// ---------------------------------------------------------------------------
// Flash attention, tf32 mma, causal. Q tile = 128, K/V tile = 64.
// ---------------------------------------------------------------------------
#define FP 68
#define FLASH_SMEM ((128 + 64 + 64 + 128) * FP * 4)   // 104448

__global__ __launch_bounds__(256, 1) void flash_mma_kernel(
    const float* __restrict__ Q, const float* __restrict__ K,
    const float* __restrict__ V, float* __restrict__ O)
{
    extern __shared__ __align__(16) float smf[];
    float* Qs = smf;
    float* Ks = Qs + 128 * FP;
    float* Vs = Ks + 64 * FP;      // [d][kpos]
    float* Ps = Vs + 64 * FP;
    const uint32_t qsB = smem_u32(Qs);
    const uint32_t ksB = smem_u32(Ks);
    const uint32_t vsB = smem_u32(Vs);
    const uint32_t psB = smem_u32(Ps);

    int qi = (gridDim.x - 1) - blockIdx.x;   // heavy tiles launch first
    int h  = blockIdx.y;
    int b  = blockIdx.z;
    int tid = threadIdx.x;
    int lane = tid & 31;
    int w = tid >> 5;

    const float* Qp = Q + (long)(b * S_ + qi * 128) * D_ + h * DH_;

    #pragma unroll
    for (int l = 0; l < 8; l++) {
        int idx = tid + l * 256;
        int q = idx >> 4, c4 = idx & 15;
        float4 v = *(const float4*)&Qp[(long)q * D_ + c4 * 4];
        *(float4*)&Qs[q * FP + c4 * 4] = v;
    }

    {
        const float* Kp = K + (long)(b * S_) * D_ + h * DH_;
        const float* Vp = V + (long)(b * S_) * D_ + h * DH_;
        #pragma unroll
        for (int l = 0; l < 4; l++) {
            int idx = tid + l * 256;
            int kp = idx >> 4, c4 = idx & 15;
            float4 v = *(const float4*)&Kp[(long)kp * D_ + c4 * 4];
            *(float4*)&Ks[kp * FP + c4 * 4] = v;
        }
        int kp = tid & 63;
        int half = tid >> 6;
        #pragma unroll
        for (int i = 0; i < 4; i++) {
            int c4 = half * 4 + i;
            float4 v = *(const float4*)&Vp[(long)kp * D_ + c4 * 4];
            Vs[(c4 * 4 + 0) * FP + kp] = v.x;
            Vs[(c4 * 4 + 1) * FP + kp] = v.y;
            Vs[(c4 * 4 + 2) * FP + kp] = v.z;
            Vs[(c4 * 4 + 3) * FP + kp] = v.w;
        }
    }
    __syncthreads();

    uint32_t qf[8][4];
    {
        uint32_t base = qsB + ((w * 16 + (lane & 15)) * FP + ((lane >> 4) << 2)) * 4;
        #pragma unroll
        for (int ds = 0; ds < 8; ds++)
            LDSM4(qf[ds][0], qf[ds][1], qf[ds][2], qf[ds][3], base + ds * 8 * 4);
    }

    float o[8][4];
    #pragma unroll
    for (int nt = 0; nt < 8; nt++)
        #pragma unroll
        for (int j = 0; j < 4; j++) o[nt][j] = 0.f;
    float m0 = -1e30f, m1 = -1e30f, l0 = 0.f, l1 = 0.f;

    const uint32_t kFragBase = ksB +
        (((lane & 7) + ((lane >> 4) << 3)) * FP + (((lane >> 3) & 1) << 2)) * 4;
    const uint32_t vFragBase = vsB +
        (((lane & 7) + ((lane >> 4) << 3)) * FP + (((lane >> 3) & 1) << 2)) * 4;
    const uint32_t pFragBase = psB +
        ((w * 16 + (lane & 15)) * FP + ((lane >> 4) << 2)) * 4;
    float* pRow0 = Ps + (w * 16 + (lane >> 2)) * FP + 2 * (lane & 3);

    int ktmax = 2 * qi + 2;
    for (int kt = 0; kt < ktmax; kt++) {
        float4 kreg[4], vreg[4];
        bool havenext = (kt + 1) < ktmax;
        if (havenext) {
            const float* Kp = K + (long)(b * S_ + (kt + 1) * 64) * D_ + h * DH_;
            const float* Vp = V + (long)(b * S_ + (kt + 1) * 64) * D_ + h * DH_;
            #pragma unroll
            for (int l = 0; l < 4; l++) {
                int idx = tid + l * 256;
                int kp = idx >> 4, c4 = idx & 15;
                kreg[l] = *(const float4*)&Kp[(long)kp * D_ + c4 * 4];
            }
            int kp = tid & 63;
            int half = tid >> 6;
            #pragma unroll
            for (int i = 0; i < 4; i++) {
                int c4 = half * 4 + i;
                vreg[i] = *(const float4*)&Vp[(long)kp * D_ + c4 * 4];
            }
        }

        bool active = (kt * 64) <= (qi * 128 + w * 16 + 15);
        if (active) {
            float s[8][4];
            #pragma unroll
            for (int nt = 0; nt < 8; nt++)
                #pragma unroll
                for (int j = 0; j < 4; j++) s[nt][j] = 0.f;

            #pragma unroll
            for (int ds = 0; ds < 8; ds++) {
                uint32_t bf[8][2];
                #pragma unroll
                for (int ntp = 0; ntp < 4; ntp++) {
                    uint32_t r0, r1, r2, r3;
                    LDSM4(r0, r1, r2, r3, kFragBase + (ntp * 16 * FP + ds * 8) * 4);
                    bf[2 * ntp][0] = r0; bf[2 * ntp][1] = r1;
                    bf[2 * ntp + 1][0] = r2; bf[2 * ntp + 1][1] = r3;
                }
                #pragma unroll
                for (int nt = 0; nt < 8; nt++)
                    MMA_TF32(s[nt], qf[ds], bf[nt][0], bf[nt][1]);
            }

            bool needmask = (kt * 64 + 63) > (qi * 128 + w * 16);
            int row0 = qi * 128 + w * 16 + (lane >> 2);
            float ml0 = -1e30f, ml1 = -1e30f;
            #pragma unroll
            for (int nt = 0; nt < 8; nt++) {
                #pragma unroll
                for (int j = 0; j < 4; j++) {
                    float v = s[nt][j] * 0.125f;
                    if (needmask) {
                        int col = kt * 64 + nt * 8 + 2 * (lane & 3) + (j & 1);
                        int row = row0 + ((j >> 1) << 3);
                        if (col > row) v = -1e30f;
                    }
                    s[nt][j] = v;
                }
                ml0 = fmaxf(ml0, fmaxf(s[nt][0], s[nt][1]));
                ml1 = fmaxf(ml1, fmaxf(s[nt][2], s[nt][3]));
            }
            ml0 = fmaxf(ml0, __shfl_xor_sync(FULLMASK, ml0, 1));
            ml0 = fmaxf(ml0, __shfl_xor_sync(FULLMASK, ml0, 2));
            ml1 = fmaxf(ml1, __shfl_xor_sync(FULLMASK, ml1, 1));
            ml1 = fmaxf(ml1, __shfl_xor_sync(FULLMASK, ml1, 2));
            float mn0 = fmaxf(m0, ml0), mn1 = fmaxf(m1, ml1);
            float a0 = __expf(m0 - mn0), a1 = __expf(m1 - mn1);
            float sum0 = 0.f, sum1 = 0.f;
            #pragma unroll
            for (int nt = 0; nt < 8; nt++) {
                s[nt][0] = __expf(s[nt][0] - mn0);
                s[nt][1] = __expf(s[nt][1] - mn0);
                s[nt][2] = __expf(s[nt][2] - mn1);
                s[nt][3] = __expf(s[nt][3] - mn1);
                sum0 += s[nt][0] + s[nt][1];
                sum1 += s[nt][2] + s[nt][3];
            }
            sum0 += __shfl_xor_sync(FULLMASK, sum0, 1);
            sum0 += __shfl_xor_sync(FULLMASK, sum0, 2);
            sum1 += __shfl_xor_sync(FULLMASK, sum1, 1);
            sum1 += __shfl_xor_sync(FULLMASK, sum1, 2);
            l0 = l0 * a0 + sum0;
            l1 = l1 * a1 + sum1;
            m0 = mn0; m1 = mn1;
            #pragma unroll
            for (int nt = 0; nt < 8; nt++) {
                o[nt][0] *= a0; o[nt][1] *= a0;
                o[nt][2] *= a1; o[nt][3] *= a1;
            }

            #pragma unroll
            for (int nt = 0; nt < 8; nt++) {
                *(float2*)&pRow0[nt * 8] = make_float2(s[nt][0], s[nt][1]);
                *(float2*)&pRow0[8 * FP + nt * 8] = make_float2(s[nt][2], s[nt][3]);
            }
            __syncwarp();

            #pragma unroll
            for (int ks = 0; ks < 8; ks++) {
                uint32_t pf[4];
                LDSM4(pf[0], pf[1], pf[2], pf[3], pFragBase + ks * 8 * 4);
                uint32_t vf[8][2];
                #pragma unroll
                for (int ntp = 0; ntp < 4; ntp++) {
                    uint32_t r0, r1, r2, r3;
                    LDSM4(r0, r1, r2, r3, vFragBase + (ntp * 16 * FP + ks * 8) * 4);
                    vf[2 * ntp][0] = r0; vf[2 * ntp][1] = r1;
                    vf[2 * ntp + 1][0] = r2; vf[2 * ntp + 1][1] = r3;
                }
                #pragma unroll
                for (int nt = 0; nt < 8; nt++)
                    MMA_TF32(o[nt], pf, vf[nt][0], vf[nt][1]);
            }
        }
        __syncthreads();

        if (havenext) {
            #pragma unroll
            for (int l = 0; l < 4; l++) {
                int idx = tid + l * 256;
                int kp = idx >> 4, c4 = idx & 15;
                *(float4*)&Ks[kp * FP + c4 * 4] = kreg[l];
            }
            int kp = tid & 63;
            int half = tid >> 6;
            #pragma unroll
            for (int i = 0; i < 4; i++) {
                int c4 = half * 4 + i;
                Vs[(c4 * 4 + 0) * FP + kp] = vreg[i].x;
                Vs[(c4 * 4 + 1) * FP + kp] = vreg[i].y;
                Vs[(c4 * 4 + 2) * FP + kp] = vreg[i].z;
                Vs[(c4 * 4 + 3) * FP + kp] = vreg[i].w;
            }
            __syncthreads();
        }
    }

    float inv0 = 1.f / l0, inv1 = 1.f / l1;
    int row0 = qi * 128 + w * 16 + (lane >> 2);
    long base0 = (long)(b * S_ + row0) * D_ + h * DH_ + 2 * (lane & 3);
    long base1 = base0 + 8 * D_;
    #pragma unroll
    for (int nt = 0; nt < 8; nt++) {
        *(float2*)&O[base0 + nt * 8] = make_float2(o[nt][0] * inv0, o[nt][1] * inv0);
        *(float2*)&O[base1 + nt * 8] = make_float2(o[nt][2] * inv1, o[nt][3] * inv1);
    }
}

// ---------------------------------------------------------------------------
// Launch
// ---------------------------------------------------------------------------
extern "C" void kernel_launch(void* const* d_in, const int* in_sizes, int n_in,
                              void* d_out, int out_size)
{
    const float* hidden = (const float*)d_in[0];
    // d_in[1] = attention_mask: causal tril -> handled analytically
    const float* lora   = (const float*)d_in[2];   // [4, B, D, R]
    const float* ln_w   = (const float*)d_in[3];
    const float* Wq     = (const float*)d_in[4];
    const float* Wk     = (const float*)d_in[5];
    const float* Wv     = (const float*)d_in[6];
    const float* Wo     = (const float*)d_in[7];
    float* out = (float*)d_out;

    float *x, *hq, *hk, *hv, *attn;
    cudaGetSymbolAddress((void**)&x,    g_x);
    cudaGetSymbolAddress((void**)&hq,   g_hq);
    cudaGetSymbolAddress((void**)&hk,   g_hk);
    cudaGetSymbolAddress((void**)&hv,   g_hv);
    cudaGetSymbolAddress((void**)&attn, g_attn);

    cudaFuncSetAttribute(gemm_qkv_kernel, cudaFuncAttributeMaxDynamicSharedMemorySize, GEMM_SMEM);
    cudaFuncSetAttribute(gemm_o_kernel,   cudaFuncAttributeMaxDynamicSharedMemorySize, GEMM_SMEM);
    cudaFuncSetAttribute(flash_mma_kernel, cudaFuncAttributeMaxDynamicSharedMemorySize, FLASH_SMEM);
    cudaFuncSetAttribute(lora_fused_kernel, cudaFuncAttributeMaxDynamicSharedMemorySize, LORA_SMEM);

    // 1. RMSNorm
    rmsnorm_kernel<<<M_, 256>>>(hidden, ln_w, x);

    // 2. Fused QKV projections
    dim3 gq(24, M_ / 128);
    gemm_qkv_kernel<<<gq, 256, GEMM_SMEM>>>(x, Wq, Wk, Wv, hq, hk, hv);

    // 3. Fused LoRA deltas (q + k in one launch)
    dim3 gl(M_ / LROWS, 2);
    lora_fused_kernel<<<gl, 256, LORA_SMEM>>>(hq, hk, lora);

    // 4. Causal flash attention
    dim3 fg(S_ / 128, H_, B_);
    flash_mma_kernel<<<fg, 256, FLASH_SMEM>>>(hq, hk, hv, attn);

    // 5. Output projection + residual
    dim3 go(8, M_ / 128);
    gemm_o_kernel<<<go, 256, GEMM_SMEM>>>(attn, Wo, hidden, out);
}

// round 6
// speedup vs baseline: 3.4403x; 1.0075x over previous
#include <cuda_runtime.h>
#include <cstdint>
#include <math.h>

// Problem constants
#define B_  2
#define S_  2048
#define D_  1024
#define H_  16
#define DH_ 64
#define R_  8
#define M_  (B_*S_)          // 4096 rows

// Scratch (device globals; no allocation allowed)
__device__ float g_x[M_*D_];
__device__ float g_hq[M_*D_];
__device__ float g_hk[M_*D_];
__device__ float g_hv[M_*D_];
__device__ float g_attn[M_*D_];

#define FULLMASK 0xffffffffu

// ===========================================================================
// PTX helpers (arch-agnostic: mma.sync + ldmatrix + cp.async)
// ===========================================================================
__device__ __forceinline__ uint32_t smem_u32(const void* p) {
    uint32_t a;
    asm("{ .reg .u64 t; cvta.to.shared.u64 t, %1; cvt.u32.u64 %0, t; }"
        : "=r"(a) : "l"(p));
    return a;
}

#define LDSM4(R0,R1,R2,R3,ADDR) \
    asm volatile("ldmatrix.sync.aligned.m8n8.x4.shared.b16 {%0,%1,%2,%3}, [%4];" \
        : "=r"(R0), "=r"(R1), "=r"(R2), "=r"(R3) : "r"(ADDR))

#define MMA_TF32(C, A, B0, B1) \
    asm volatile("mma.sync.aligned.m16n8k8.row.col.f32.tf32.tf32.f32 " \
        "{%0,%1,%2,%3}, {%4,%5,%6,%7}, {%8,%9}, {%0,%1,%2,%3};" \
        : "+f"((C)[0]), "+f"((C)[1]), "+f"((C)[2]), "+f"((C)[3]) \
        : "r"((A)[0]), "r"((A)[1]), "r"((A)[2]), "r"((A)[3]), "r"(B0), "r"(B1))

#define CP16(DST, SRC) \
    asm volatile("cp.async.cg.shared.global [%0], [%1], 16;" :: "r"(DST), "l"(SRC))
#define CP_COMMIT() asm volatile("cp.async.commit_group;" ::: "memory")
#define CP_WAIT(N)  asm volatile("cp.async.wait_group %0;" :: "n"(N) : "memory")

// ---------------------------------------------------------------------------
// RMSNorm
// ---------------------------------------------------------------------------
__global__ __launch_bounds__(256) void rmsnorm_kernel(
    const float* __restrict__ hs, const float* __restrict__ w, float* __restrict__ out)
{
    int row = blockIdx.x;
    int t = threadIdx.x;
    const float* x = hs + (long)row * D_;

    float v[4];
    float ss = 0.f;
    #pragma unroll
    for (int i = 0; i < 4; i++) {
        v[i] = x[t + i * 256];
        ss += v[i] * v[i];
    }
    #pragma unroll
    for (int o = 16; o > 0; o >>= 1) ss += __shfl_xor_sync(FULLMASK, ss, o);
    __shared__ float red[8];
    if ((t & 31) == 0) red[t >> 5] = ss;
    __syncthreads();
    __shared__ float s_inv;
    if (t == 0) {
        float s = 0.f;
        #pragma unroll
        for (int i = 0; i < 8; i++) s += red[i];
        s_inv = rsqrtf(s / (float)D_ + 1e-5f);
    }
    __syncthreads();
    float inv = s_inv;
    #pragma unroll
    for (int i = 0; i < 4; i++) {
        int d = t + i * 256;
        out[(long)row * D_ + d] = v[i] * inv * w[d];
    }
}

// ---------------------------------------------------------------------------
// Shared GEMM core: C[128x128 tile] = A @ W^T (+resid). 256 threads, 8 warps,
// warp tile 32x64, cp.async double-buffered, BK=32, smem pitch 36 floats.
// ---------------------------------------------------------------------------
#define GP 36
#define GTILE_B (128*GP*4)       // 18432 bytes per tile buffer
#define GEMM_SMEM (4*GTILE_B)    // 73728

template <bool RESID>
__device__ __forceinline__ void gemm128_core(
    const float* __restrict__ A, const float* __restrict__ W,
    const float* __restrict__ resid, float* __restrict__ C,
    int by, int bx, char* gsm)
{
    const uint32_t sA = smem_u32(gsm);
    const uint32_t sB = sA + 2 * GTILE_B;
    int tid = threadIdx.x;
    int lane = tid & 31;
    int w = tid >> 5;             // 0..7
    int wm = (w >> 1) * 32;
    int wn = (w & 1) * 64;

    const float* aP[4]; const float* bP[4];
    uint32_t stA[4], stB[4];
    #pragma unroll
    for (int l = 0; l < 4; l++) {
        int idx = tid + l * 256;  // 0..1023
        int r = idx >> 3, c4 = idx & 7;
        aP[l] = A + (long)(by * 128 + r) * D_ + c4 * 4;
        bP[l] = W + (long)(bx * 128 + r) * D_ + c4 * 4;
        stA[l] = sA + r * (GP * 4) + c4 * 16;
        stB[l] = sB + r * (GP * 4) + c4 * 16;
    }

    float acc[2][8][4];
    #pragma unroll
    for (int mt = 0; mt < 2; mt++)
        #pragma unroll
        for (int nt = 0; nt < 8; nt++)
            #pragma unroll
            for (int j = 0; j < 4; j++) acc[mt][nt][j] = 0.f;

    const uint32_t aFragBase = sA +
        ((wm + (lane & 15)) * GP + ((lane >> 4) << 2)) * 4;
    const uint32_t bFragBase = sB +
        ((wn + (lane & 7) + ((lane >> 4) << 3)) * GP + (((lane >> 3) & 1) << 2)) * 4;

    #pragma unroll
    for (int l = 0; l < 4; l++) { CP16(stA[l], aP[l]); CP16(stB[l], bP[l]); }
    CP_COMMIT();

    for (int kc = 0; kc < 32; kc++) {
        int buf = kc & 1;
        if (kc + 1 < 32) {
            #pragma unroll
            for (int l = 0; l < 4; l++) {
                CP16(stA[l] + (buf ^ 1) * GTILE_B, aP[l] + (kc + 1) * 32);
                CP16(stB[l] + (buf ^ 1) * GTILE_B, bP[l] + (kc + 1) * 32);
            }
            CP_COMMIT();
            CP_WAIT(1);
        } else {
            CP_WAIT(0);
        }
        __syncthreads();

        uint32_t aBuf = aFragBase + buf * GTILE_B;
        uint32_t bBuf = bFragBase + buf * GTILE_B;

        #pragma unroll
        for (int ks = 0; ks < 4; ks++) {
            uint32_t af[2][4];
            uint32_t bf[8][2];
            #pragma unroll
            for (int mt = 0; mt < 2; mt++)
                LDSM4(af[mt][0], af[mt][1], af[mt][2], af[mt][3],
                      aBuf + (mt * 16 * GP + ks * 8) * 4);
            #pragma unroll
            for (int ntp = 0; ntp < 4; ntp++) {
                uint32_t r0, r1, r2, r3;
                LDSM4(r0, r1, r2, r3, bBuf + (ntp * 16 * GP + ks * 8) * 4);
                bf[2 * ntp][0] = r0; bf[2 * ntp][1] = r1;
                bf[2 * ntp + 1][0] = r2; bf[2 * ntp + 1][1] = r3;
            }
            #pragma unroll
            for (int mt = 0; mt < 2; mt++)
                #pragma unroll
                for (int nt = 0; nt < 8; nt++)
                    MMA_TF32(acc[mt][nt], af[mt], bf[nt][0], bf[nt][1]);
        }
        __syncthreads();
    }

    // Epilogue
    #pragma unroll
    for (int mt = 0; mt < 2; mt++) {
        int row = by * 128 + wm + mt * 16 + (lane >> 2);
        int col = bx * 128 + wn + 2 * (lane & 3);
        #pragma unroll
        for (int nt = 0; nt < 8; nt++) {
            long i0 = (long)row * D_ + col + nt * 8;
            long i1 = i0 + 8 * D_;
            float2 v0 = make_float2(acc[mt][nt][0], acc[mt][nt][1]);
            float2 v1 = make_float2(acc[mt][nt][2], acc[mt][nt][3]);
            if (RESID) {
                float2 r0 = *(const float2*)&resid[i0];
                float2 r1 = *(const float2*)&resid[i1];
                v0.x += r0.x; v0.y += r0.y;
                v1.x += r1.x; v1.y += r1.y;
            }
            *(float2*)&C[i0] = v0;
            *(float2*)&C[i1] = v1;
        }
    }
}

// Fused QKV: grid (24, 32)
__global__ __launch_bounds__(256, 2) void gemm_qkv_kernel(
    const float* __restrict__ A,
    const float* __restrict__ Wq, const float* __restrict__ Wk, const float* __restrict__ Wv,
    float* __restrict__ hq, float* __restrict__ hk, float* __restrict__ hv)
{
    extern __shared__ __align__(16) char gsm[];
    int wsel = blockIdx.x >> 3;
    int bx = blockIdx.x & 7;
    const float* W = (wsel == 0) ? Wq : (wsel == 1) ? Wk : Wv;
    float* C = (wsel == 0) ? hq : (wsel == 1) ? hk : hv;
    gemm128_core<false>(A, W, nullptr, C, blockIdx.y, bx, gsm);
}

// Output projection + residual: grid (8, 32)
__global__ __launch_bounds__(256, 2) void gemm_o_kernel(
    const float* __restrict__ A, const float* __restrict__ W,
    const float* __restrict__ resid, float* __restrict__ C)
{
    extern __shared__ __align__(16) char gsm[];
    gemm128_core<true>(A, W, resid, C, blockIdx.y, blockIdx.x, gsm);
}

// ---------------------------------------------------------------------------
// Fused LoRA (q and k in one launch): h += 2 * (h @ A) @ B^T
// ---------------------------------------------------------------------------
#define LROWS 32
#define LORA_SMEM (2 * R_ * D_ * 4)   // 65536

__global__ __launch_bounds__(256) void lora_fused_kernel(
    float* __restrict__ hq, float* __restrict__ hk, const float* __restrict__ lora)
{
    int which = blockIdx.y;                 // 0 = q, 1 = k
    float* h = which ? hk : hq;
    int rowBase = blockIdx.x * LROWS;
    int b = rowBase / S_;
    const float* Ag = lora + ((long)which * B_ + b) * D_ * R_;
    const float* Bg = lora + ((long)(2 + which) * B_ + b) * D_ * R_;

    extern __shared__ __align__(16) float lsm[];
    float* As = lsm;             // [r][d] transposed
    float* Bs = lsm + R_ * D_;   // [r][d] transposed
    __shared__ float z[LROWS][R_];

    int tid = threadIdx.x;
    int lane = tid & 31, w = tid >> 5;

    #pragma unroll
    for (int k = 0; k < 4; k++) {
        int d = tid + k * 256;
        float4 a0 = *(const float4*)&Ag[d * R_];
        float4 a1 = *(const float4*)&Ag[d * R_ + 4];
        float4 b0 = *(const float4*)&Bg[d * R_];
        float4 b1 = *(const float4*)&Bg[d * R_ + 4];
        As[0*D_+d] = a0.x; As[1*D_+d] = a0.y; As[2*D_+d] = a0.z; As[3*D_+d] = a0.w;
        As[4*D_+d] = a1.x; As[5*D_+d] = a1.y; As[6*D_+d] = a1.z; As[7*D_+d] = a1.w;
        Bs[0*D_+d] = b0.x; Bs[1*D_+d] = b0.y; Bs[2*D_+d] = b0.z; Bs[3*D_+d] = b0.w;
        Bs[4*D_+d] = b1.x; Bs[5*D_+d] = b1.y; Bs[6*D_+d] = b1.z; Bs[7*D_+d] = b1.w;
    }
    __syncthreads();

    #pragma unroll
    for (int rr = 0; rr < 4; rr++) {
        int row = rowBase + w * 4 + rr;
        const float* hrow = h + (long)row * D_;
        float part[R_];
        #pragma unroll
        for (int r = 0; r < R_; r++) part[r] = 0.f;
        #pragma unroll
        for (int k = 0; k < 32; k++) {
            int d = lane + k * 32;
            float hv = hrow[d];
            #pragma unroll
            for (int r = 0; r < R_; r++) part[r] += hv * As[r * D_ + d];
        }
        #pragma unroll
        for (int r = 0; r < R_; r++)
            #pragma unroll
            for (int o = 16; o > 0; o >>= 1)
                part[r] += __shfl_xor_sync(FULLMASK, part[r], o);
        if (lane == 0)
            #pragma unroll
            for (int r = 0; r < R_; r++) z[w * 4 + rr][r] = part[r];
    }
    __syncthreads();

    #pragma unroll
    for (int k = 0; k < 4; k++) {
        int d = tid + k * 256;
        float br[R_];
        #pragma unroll
        for (int r = 0; r < R_; r++) br[r] = Bs[r * D_ + d];
        for (int rr = 0; rr < LROWS; rr++) {
            long idx = (long)(rowBase + rr) * D_ + d;
            float delta = 0.f;
            #pragma unroll
            for (int r = 0; r < R_; r++) delta += z[rr][r] * br[r];
            h[idx] += 2.f * delta;
        }
    }
}

// ---------------------------------------------------------------------------
// Flash attention, tf32 mma, causal. Q tile = 128, K/V tile = 64.
// K via cp.async (double-buffered), V via LDG->STS transpose (double-buffered).
// ONE __syncthreads per kt iteration. S-loop LDSMs software-pipelined.
// ---------------------------------------------------------------------------
#define FP 68
#define KVT (64 * FP)                                 // floats per K or V buffer
#define FLASH_SMEM ((128 + 64*2 + 64*2 + 128) * FP * 4)   // 139264

__global__ __launch_bounds__(256, 1) void flash_mma_kernel(
    const float* __restrict__ Q, const float* __restrict__ K,
    const float* __restrict__ V, float* __restrict__ O)
{
    extern __shared__ __align__(16) float smf[];
    float* Qs = smf;                   // [128][FP]
    float* Ks = Qs + 128 * FP;         // 2 x [64][FP]  (k-major)
    float* Vs = Ks + 2 * KVT;          // 2 x [64][FP]  (d-major, transposed)
    float* Ps = Vs + 2 * KVT;          // [128][FP]
    const uint32_t qsB = smem_u32(Qs);
    const uint32_t ksB = smem_u32(Ks);
    const uint32_t vsB = smem_u32(Vs);
    const uint32_t psB = smem_u32(Ps);

    int qi = (gridDim.x - 1) - blockIdx.x;   // heavy tiles launch first
    int h  = blockIdx.y;
    int b  = blockIdx.z;
    int tid = threadIdx.x;
    int lane = tid & 31;
    int w = tid >> 5;

    const float* Qp = Q + (long)(b * S_ + qi * 128) * D_ + h * DH_;

    // --- Prologue: Q tile, K0 via cp.async, V0 via LDG+STS ---
    #pragma unroll
    for (int l = 0; l < 8; l++) {
        int idx = tid + l * 256;
        int q = idx >> 4, c4 = idx & 15;
        float4 v = *(const float4*)&Qp[(long)q * D_ + c4 * 4];
        *(float4*)&Qs[q * FP + c4 * 4] = v;
    }
    {
        const float* Kp = K + (long)(b * S_) * D_ + h * DH_;
        #pragma unroll
        for (int l = 0; l < 4; l++) {
            int idx = tid + l * 256;
            int kp = idx >> 4, c4 = idx & 15;
            CP16(ksB + (kp * FP + c4 * 4) * 4, Kp + (long)kp * D_ + c4 * 4);
        }
        CP_COMMIT();
        const float* Vp = V + (long)(b * S_) * D_ + h * DH_;
        int kp = tid & 63;
        int half = tid >> 6;
        #pragma unroll
        for (int i = 0; i < 4; i++) {
            int c4 = half * 4 + i;
            float4 v = *(const float4*)&Vp[(long)kp * D_ + c4 * 4];
            Vs[(c4 * 4 + 0) * FP + kp] = v.x;
            Vs[(c4 * 4 + 1) * FP + kp] = v.y;
            Vs[(c4 * 4 + 2) * FP + kp] = v.z;
            Vs[(c4 * 4 + 3) * FP + kp] = v.w;
        }
    }
    __syncthreads();

    // Q fragments (resident)
    uint32_t qf[8][4];
    {
        uint32_t base = qsB + ((w * 16 + (lane & 15)) * FP + ((lane >> 4) << 2)) * 4;
        #pragma unroll
        for (int ds = 0; ds < 8; ds++)
            LDSM4(qf[ds][0], qf[ds][1], qf[ds][2], qf[ds][3], base + ds * 8 * 4);
    }

    float o[8][4];
    #pragma unroll
    for (int nt = 0; nt < 8; nt++)
        #pragma unroll
        for (int j = 0; j < 4; j++) o[nt][j] = 0.f;
    float m0 = -1e30f, m1 = -1e30f, l0 = 0.f, l1 = 0.f;

    const uint32_t kFragOff = ksB +
        (((lane & 7) + ((lane >> 4) << 3)) * FP + (((lane >> 3) & 1) << 2)) * 4;
    const uint32_t vFragOff = vsB +
        (((lane & 7) + ((lane >> 4) << 3)) * FP + (((lane >> 3) & 1) << 2)) * 4;
    const uint32_t pFragBase = psB +
        ((w * 16 + (lane & 15)) * FP + ((lane >> 4) << 2)) * 4;
    float* pRow0 = Ps + (w * 16 + (lane >> 2)) * FP + 2 * (lane & 3);

    int ktmax = 2 * qi + 2;
    for (int kt = 0; kt < ktmax; kt++) {
        int buf = kt & 1;
        bool havenext = (kt + 1) < ktmax;

        // LDG next V early (latency covered by this tile's compute)
        float4 vreg[4];
        if (havenext) {
            const float* Vp = V + (long)(b * S_ + (kt + 1) * 64) * D_ + h * DH_;
            int kp = tid & 63;
            int half = tid >> 6;
            #pragma unroll
            for (int i = 0; i < 4; i++) {
                int c4 = half * 4 + i;
                vreg[i] = *(const float4*)&Vp[(long)kp * D_ + c4 * 4];
            }
        }

        CP_WAIT(0);
        __syncthreads();   // retires kt-1 compute, makes K(kt)/V(kt) visible

        if (havenext) {
            const float* Kp = K + (long)(b * S_ + (kt + 1) * 64) * D_ + h * DH_;
            uint32_t dst = ksB + (buf ^ 1) * (KVT * 4);
            #pragma unroll
            for (int l = 0; l < 4; l++) {
                int idx = tid + l * 256;
                int kp = idx >> 4, c4 = idx & 15;
                CP16(dst + (kp * FP + c4 * 4) * 4, Kp + (long)kp * D_ + c4 * 4);
            }
            CP_COMMIT();
        }

        bool active = (kt * 64) <= (qi * 128 + w * 16 + 15);
        if (active) {
            const uint32_t kFragBase = kFragOff + buf * (KVT * 4);
            const uint32_t vFragBase = vFragOff + buf * (KVT * 4);

            // ---- S = Q K^T with pipelined B-fragment LDSMs ----
            float s[8][4];
            #pragma unroll
            for (int nt = 0; nt < 8; nt++)
                #pragma unroll
                for (int j = 0; j < 4; j++) s[nt][j] = 0.f;

            uint32_t bfp[2][8][2];
            #pragma unroll
            for (int ntp = 0; ntp < 4; ntp++) {
                uint32_t r0, r1, r2, r3;
                LDSM4(r0, r1, r2, r3, kFragBase + (ntp * 16 * FP) * 4);
                bfp[0][2*ntp][0] = r0; bfp[0][2*ntp][1] = r1;
                bfp[0][2*ntp+1][0] = r2; bfp[0][2*ntp+1][1] = r3;
            }
            #pragma unroll
            for (int ds = 0; ds < 8; ds++) {
                int cur = ds & 1;
                if (ds < 7) {
                    #pragma unroll
                    for (int ntp = 0; ntp < 4; ntp++) {
                        uint32_t r0, r1, r2, r3;
                        LDSM4(r0, r1, r2, r3,
                              kFragBase + (ntp * 16 * FP + (ds + 1) * 8) * 4);
                        bfp[cur^1][2*ntp][0] = r0; bfp[cur^1][2*ntp][1] = r1;
                        bfp[cur^1][2*ntp+1][0] = r2; bfp[cur^1][2*ntp+1][1] = r3;
                    }
                }
                #pragma unroll
                for (int nt = 0; nt < 8; nt++)
                    MMA_TF32(s[nt], qf[ds], bfp[cur][nt][0], bfp[cur][nt][1]);
            }

            // ---- scale + causal mask + online softmax ----
            bool needmask = (kt * 64 + 63) > (qi * 128 + w * 16);
            int row0 = qi * 128 + w * 16 + (lane >> 2);
            float ml0 = -1e30f, ml1 = -1e30f;
            #pragma unroll
            for (int nt = 0; nt < 8; nt++) {
                #pragma unroll
                for (int j = 0; j < 4; j++) {
                    float v = s[nt][j] * 0.125f;
                    if (needmask) {
                        int col = kt * 64 + nt * 8 + 2 * (lane & 3) + (j & 1);
                        int row = row0 + ((j >> 1) << 3);
                        if (col > row) v = -1e30f;
                    }
                    s[nt][j] = v;
                }
                ml0 = fmaxf(ml0, fmaxf(s[nt][0], s[nt][1]));
                ml1 = fmaxf(ml1, fmaxf(s[nt][2], s[nt][3]));
            }
            ml0 = fmaxf(ml0, __shfl_xor_sync(FULLMASK, ml0, 1));
            ml0 = fmaxf(ml0, __shfl_xor_sync(FULLMASK, ml0, 2));
            ml1 = fmaxf(ml1, __shfl_xor_sync(FULLMASK, ml1, 1));
            ml1 = fmaxf(ml1, __shfl_xor_sync(FULLMASK, ml1, 2));
            float mn0 = fmaxf(m0, ml0), mn1 = fmaxf(m1, ml1);
            float a0 = __expf(m0 - mn0), a1 = __expf(m1 - mn1);
            float sum0 = 0.f, sum1 = 0.f;
            #pragma unroll
            for (int nt = 0; nt < 8; nt++) {
                s[nt][0] = __expf(s[nt][0] - mn0);
                s[nt][1] = __expf(s[nt][1] - mn0);
                s[nt][2] = __expf(s[nt][2] - mn1);
                s[nt][3] = __expf(s[nt][3] - mn1);
                sum0 += s[nt][0] + s[nt][1];
                sum1 += s[nt][2] + s[nt][3];
            }
            sum0 += __shfl_xor_sync(FULLMASK, sum0, 1);
            sum0 += __shfl_xor_sync(FULLMASK, sum0, 2);
            sum1 += __shfl_xor_sync(FULLMASK, sum1, 1);
            sum1 += __shfl_xor_sync(FULLMASK, sum1, 2);
            l0 = l0 * a0 + sum0;
            l1 = l1 * a1 + sum1;
            m0 = mn0; m1 = mn1;
            #pragma unroll
            for (int nt = 0; nt < 8; nt++) {
                o[nt][0] *= a0; o[nt][1] *= a0;
                o[nt][2] *= a1; o[nt][3] *= a1;
            }

            // store P (per-warp slice)
            #pragma unroll
            for (int nt = 0; nt < 8; nt++) {
                *(float2*)&pRow0[nt * 8] = make_float2(s[nt][0], s[nt][1]);
                *(float2*)&pRow0[8 * FP + nt * 8] = make_float2(s[nt][2], s[nt][3]);
            }
            __syncwarp();

            // ---- O += P V ----
            #pragma unroll
            for (int ks = 0; ks < 8; ks++) {
                uint32_t pf[4];
                LDSM4(pf[0], pf[1], pf[2], pf[3], pFragBase + ks * 8 * 4);
                uint32_t vf[8][2];
                #pragma unroll
                for (int ntp = 0; ntp < 4; ntp++) {
                    uint32_t r0, r1, r2, r3;
                    LDSM4(r0, r1, r2, r3, vFragBase + (ntp * 16 * FP + ks * 8) * 4);
                    vf[2 * ntp][0] = r0; vf[2 * ntp][1] = r1;
                    vf[2 * ntp + 1][0] = r2; vf[2 * ntp + 1][1] = r3;
                }
                #pragma unroll
                for (int nt = 0; nt < 8; nt++)
                    MMA_TF32(o[nt], pf, vf[nt][0], vf[nt][1]);
            }
        }

        // STS next V tile into the other buffer (safe: retired at this iter's barrier)
        if (havenext) {
            float* Vd = Vs + (buf ^ 1) * KVT;
            int kp = tid & 63;
            int half = tid >> 6;
            #pragma unroll
            for (int i = 0; i < 4; i++) {
                int c4 = half * 4 + i;
                Vd[(c4 * 4 + 0) * FP + kp] = vreg[i].x;
                Vd[(c4 * 4 + 1) * FP + kp] = vreg[i].y;
                Vd[(c4 * 4 + 2) * FP + kp] = vreg[i].z;
                Vd[(c4 * 4 + 3) * FP + kp] = vreg[i].w;
            }
        }
    }

    // normalize + write
    float inv0 = 1.f / l0, inv1 = 1.f / l1;
    int row0 = qi * 128 + w * 16 + (lane >> 2);
    long base0 = (long)(b * S_ + row0) * D_ + h * DH_ + 2 * (lane & 3);
    long base1 = base0 + 8 * D_;
    #pragma unroll
    for (int nt = 0; nt < 8; nt++) {
        *(float2*)&O[base0 + nt * 8] = make_float2(o[nt][0] * inv0, o[nt][1] * inv0);
        *(float2*)&O[base1 + nt * 8] = make_float2(o[nt][2] * inv1, o[nt][3] * inv1);
    }
}

// ---------------------------------------------------------------------------
// Launch
// ---------------------------------------------------------------------------
extern "C" void kernel_launch(void* const* d_in, const int* in_sizes, int n_in,
                              void* d_out, int out_size)
{
    const float* hidden = (const float*)d_in[0];
    // d_in[1] = attention_mask: causal tril -> handled analytically
    const float* lora   = (const float*)d_in[2];   // [4, B, D, R]
    const float* ln_w   = (const float*)d_in[3];
    const float* Wq     = (const float*)d_in[4];
    const float* Wk     = (const float*)d_in[5];
    const float* Wv     = (const float*)d_in[6];
    const float* Wo     = (const float*)d_in[7];
    float* out = (float*)d_out;

    float *x, *hq, *hk, *hv, *attn;
    cudaGetSymbolAddress((void**)&x,    g_x);
    cudaGetSymbolAddress((void**)&hq,   g_hq);
    cudaGetSymbolAddress((void**)&hk,   g_hk);
    cudaGetSymbolAddress((void**)&hv,   g_hv);
    cudaGetSymbolAddress((void**)&attn, g_attn);

    cudaFuncSetAttribute(gemm_qkv_kernel, cudaFuncAttributeMaxDynamicSharedMemorySize, GEMM_SMEM);
    cudaFuncSetAttribute(gemm_o_kernel,   cudaFuncAttributeMaxDynamicSharedMemorySize, GEMM_SMEM);
    cudaFuncSetAttribute(flash_mma_kernel, cudaFuncAttributeMaxDynamicSharedMemorySize, FLASH_SMEM);
    cudaFuncSetAttribute(lora_fused_kernel, cudaFuncAttributeMaxDynamicSharedMemorySize, LORA_SMEM);

    // 1. RMSNorm
    rmsnorm_kernel<<<M_, 256>>>(hidden, ln_w, x);

    // 2. Fused QKV projections
    dim3 gq(24, M_ / 128);
    gemm_qkv_kernel<<<gq, 256, GEMM_SMEM>>>(x, Wq, Wk, Wv, hq, hk, hv);

    // 3. Fused LoRA deltas (q + k in one launch)
    dim3 gl(M_ / LROWS, 2);
    lora_fused_kernel<<<gl, 256, LORA_SMEM>>>(hq, hk, lora);

    // 4. Causal flash attention
    dim3 fg(S_ / 128, H_, B_);
    flash_mma_kernel<<<fg, 256, FLASH_SMEM>>>(hq, hk, hv, attn);

    // 5. Output projection + residual
    dim3 go(8, M_ / 128);
    gemm_o_kernel<<<go, 256, GEMM_SMEM>>>(attn, Wo, hidden, out);
}

// round 7
// speedup vs baseline: 3.8902x; 1.1308x over previous
#include <cuda_runtime.h>
#include <cuda_bf16.h>
#include <cstdint>
#include <math.h>

// Problem constants
#define B_  2
#define S_  2048
#define D_  1024
#define H_  16
#define DH_ 64
#define R_  8
#define M_  (B_*S_)          // 4096 rows

// Scratch (device globals; no allocation allowed)
__device__ float g_x[M_*D_];
__device__ float g_hq[M_*D_];
__device__ float g_hk[M_*D_];
__device__ float g_hv[M_*D_];
__device__ float g_attn[M_*D_];

#define FULLMASK 0xffffffffu

// ===========================================================================
// PTX helpers
// ===========================================================================
__device__ __forceinline__ uint32_t smem_u32(const void* p) {
    uint32_t a;
    asm("{ .reg .u64 t; cvta.to.shared.u64 t, %1; cvt.u32.u64 %0, t; }"
        : "=r"(a) : "l"(p));
    return a;
}

#define LDSM4(R0,R1,R2,R3,ADDR) \
    asm volatile("ldmatrix.sync.aligned.m8n8.x4.shared.b16 {%0,%1,%2,%3}, [%4];" \
        : "=r"(R0), "=r"(R1), "=r"(R2), "=r"(R3) : "r"(ADDR))

#define MMA_TF32(C, A, B0, B1) \
    asm volatile("mma.sync.aligned.m16n8k8.row.col.f32.tf32.tf32.f32 " \
        "{%0,%1,%2,%3}, {%4,%5,%6,%7}, {%8,%9}, {%0,%1,%2,%3};" \
        : "+f"((C)[0]), "+f"((C)[1]), "+f"((C)[2]), "+f"((C)[3]) \
        : "r"((A)[0]), "r"((A)[1]), "r"((A)[2]), "r"((A)[3]), "r"(B0), "r"(B1))

#define MMA_BF16(C, A, B0, B1) \
    asm volatile("mma.sync.aligned.m16n8k16.row.col.f32.bf16.bf16.f32 " \
        "{%0,%1,%2,%3}, {%4,%5,%6,%7}, {%8,%9}, {%0,%1,%2,%3};" \
        : "+f"((C)[0]), "+f"((C)[1]), "+f"((C)[2]), "+f"((C)[3]) \
        : "r"((A)[0]), "r"((A)[1]), "r"((A)[2]), "r"((A)[3]), "r"(B0), "r"(B1))

#define CP16(DST, SRC) \
    asm volatile("cp.async.cg.shared.global [%0], [%1], 16;" :: "r"(DST), "l"(SRC))
#define CP_COMMIT() asm volatile("cp.async.commit_group;" ::: "memory")
#define CP_WAIT(N)  asm volatile("cp.async.wait_group %0;" :: "n"(N) : "memory")

__device__ __forceinline__ uint32_t pk_bf16x2(float a, float b) {
    __nv_bfloat162 t = __floats2bfloat162_rn(a, b);   // .x = a (low), .y = b (high)
    return *reinterpret_cast<uint32_t*>(&t);
}
__device__ __forceinline__ float rt_bf16(float a) {
    return __bfloat162float(__float2bfloat16(a));
}

// ---------------------------------------------------------------------------
// RMSNorm
// ---------------------------------------------------------------------------
__global__ __launch_bounds__(256) void rmsnorm_kernel(
    const float* __restrict__ hs, const float* __restrict__ w, float* __restrict__ out)
{
    int row = blockIdx.x;
    int t = threadIdx.x;
    const float* x = hs + (long)row * D_;

    float v[4];
    float ss = 0.f;
    #pragma unroll
    for (int i = 0; i < 4; i++) {
        v[i] = x[t + i * 256];
        ss += v[i] * v[i];
    }
    #pragma unroll
    for (int o = 16; o > 0; o >>= 1) ss += __shfl_xor_sync(FULLMASK, ss, o);
    __shared__ float red[8];
    if ((t & 31) == 0) red[t >> 5] = ss;
    __syncthreads();
    __shared__ float s_inv;
    if (t == 0) {
        float s = 0.f;
        #pragma unroll
        for (int i = 0; i < 8; i++) s += red[i];
        s_inv = rsqrtf(s / (float)D_ + 1e-5f);
    }
    __syncthreads();
    float inv = s_inv;
    #pragma unroll
    for (int i = 0; i < 4; i++) {
        int d = t + i * 256;
        out[(long)row * D_ + d] = v[i] * inv * w[d];
    }
}

// ---------------------------------------------------------------------------
// GEMM core (tf32, unchanged from round 6)
// ---------------------------------------------------------------------------
#define GP 36
#define GTILE_B (128*GP*4)
#define GEMM_SMEM (4*GTILE_B)

template <bool RESID>
__device__ __forceinline__ void gemm128_core(
    const float* __restrict__ A, const float* __restrict__ W,
    const float* __restrict__ resid, float* __restrict__ C,
    int by, int bx, char* gsm)
{
    const uint32_t sA = smem_u32(gsm);
    const uint32_t sB = sA + 2 * GTILE_B;
    int tid = threadIdx.x;
    int lane = tid & 31;
    int w = tid >> 5;
    int wm = (w >> 1) * 32;
    int wn = (w & 1) * 64;

    const float* aP[4]; const float* bP[4];
    uint32_t stA[4], stB[4];
    #pragma unroll
    for (int l = 0; l < 4; l++) {
        int idx = tid + l * 256;
        int r = idx >> 3, c4 = idx & 7;
        aP[l] = A + (long)(by * 128 + r) * D_ + c4 * 4;
        bP[l] = W + (long)(bx * 128 + r) * D_ + c4 * 4;
        stA[l] = sA + r * (GP * 4) + c4 * 16;
        stB[l] = sB + r * (GP * 4) + c4 * 16;
    }

    float acc[2][8][4];
    #pragma unroll
    for (int mt = 0; mt < 2; mt++)
        #pragma unroll
        for (int nt = 0; nt < 8; nt++)
            #pragma unroll
            for (int j = 0; j < 4; j++) acc[mt][nt][j] = 0.f;

    const uint32_t aFragBase = sA +
        ((wm + (lane & 15)) * GP + ((lane >> 4) << 2)) * 4;
    const uint32_t bFragBase = sB +
        ((wn + (lane & 7) + ((lane >> 4) << 3)) * GP + (((lane >> 3) & 1) << 2)) * 4;

    #pragma unroll
    for (int l = 0; l < 4; l++) { CP16(stA[l], aP[l]); CP16(stB[l], bP[l]); }
    CP_COMMIT();

    for (int kc = 0; kc < 32; kc++) {
        int buf = kc & 1;
        if (kc + 1 < 32) {
            #pragma unroll
            for (int l = 0; l < 4; l++) {
                CP16(stA[l] + (buf ^ 1) * GTILE_B, aP[l] + (kc + 1) * 32);
                CP16(stB[l] + (buf ^ 1) * GTILE_B, bP[l] + (kc + 1) * 32);
            }
            CP_COMMIT();
            CP_WAIT(1);
        } else {
            CP_WAIT(0);
        }
        __syncthreads();

        uint32_t aBuf = aFragBase + buf * GTILE_B;
        uint32_t bBuf = bFragBase + buf * GTILE_B;

        #pragma unroll
        for (int ks = 0; ks < 4; ks++) {
            uint32_t af[2][4];
            uint32_t bf[8][2];
            #pragma unroll
            for (int mt = 0; mt < 2; mt++)
                LDSM4(af[mt][0], af[mt][1], af[mt][2], af[mt][3],
                      aBuf + (mt * 16 * GP + ks * 8) * 4);
            #pragma unroll
            for (int ntp = 0; ntp < 4; ntp++) {
                uint32_t r0, r1, r2, r3;
                LDSM4(r0, r1, r2, r3, bBuf + (ntp * 16 * GP + ks * 8) * 4);
                bf[2 * ntp][0] = r0; bf[2 * ntp][1] = r1;
                bf[2 * ntp + 1][0] = r2; bf[2 * ntp + 1][1] = r3;
            }
            #pragma unroll
            for (int mt = 0; mt < 2; mt++)
                #pragma unroll
                for (int nt = 0; nt < 8; nt++)
                    MMA_TF32(acc[mt][nt], af[mt], bf[nt][0], bf[nt][1]);
        }
        __syncthreads();
    }

    #pragma unroll
    for (int mt = 0; mt < 2; mt++) {
        int row = by * 128 + wm + mt * 16 + (lane >> 2);
        int col = bx * 128 + wn + 2 * (lane & 3);
        #pragma unroll
        for (int nt = 0; nt < 8; nt++) {
            long i0 = (long)row * D_ + col + nt * 8;
            long i1 = i0 + 8 * D_;
            float2 v0 = make_float2(acc[mt][nt][0], acc[mt][nt][1]);
            float2 v1 = make_float2(acc[mt][nt][2], acc[mt][nt][3]);
            if (RESID) {
                float2 r0 = *(const float2*)&resid[i0];
                float2 r1 = *(const float2*)&resid[i1];
                v0.x += r0.x; v0.y += r0.y;
                v1.x += r1.x; v1.y += r1.y;
            }
            *(float2*)&C[i0] = v0;
            *(float2*)&C[i1] = v1;
        }
    }
}

__global__ __launch_bounds__(256, 2) void gemm_qkv_kernel(
    const float* __restrict__ A,
    const float* __restrict__ Wq, const float* __restrict__ Wk, const float* __restrict__ Wv,
    float* __restrict__ hq, float* __restrict__ hk, float* __restrict__ hv)
{
    extern __shared__ __align__(16) char gsm[];
    int wsel = blockIdx.x >> 3;
    int bx = blockIdx.x & 7;
    const float* W = (wsel == 0) ? Wq : (wsel == 1) ? Wk : Wv;
    float* C = (wsel == 0) ? hq : (wsel == 1) ? hk : hv;
    gemm128_core<false>(A, W, nullptr, C, blockIdx.y, bx, gsm);
}

__global__ __launch_bounds__(256, 2) void gemm_o_kernel(
    const float* __restrict__ A, const float* __restrict__ W,
    const float* __restrict__ resid, float* __restrict__ C)
{
    extern __shared__ __align__(16) char gsm[];
    gemm128_core<true>(A, W, resid, C, blockIdx.y, blockIdx.x, gsm);
}

// ---------------------------------------------------------------------------
// Fused LoRA (unchanged from round 6)
// ---------------------------------------------------------------------------
#define LROWS 32
#define LORA_SMEM (2 * R_ * D_ * 4)

__global__ __launch_bounds__(256) void lora_fused_kernel(
    float* __restrict__ hq, float* __restrict__ hk, const float* __restrict__ lora)
{
    int which = blockIdx.y;
    float* h = which ? hk : hq;
    int rowBase = blockIdx.x * LROWS;
    int b = rowBase / S_;
    const float* Ag = lora + ((long)which * B_ + b) * D_ * R_;
    const float* Bg = lora + ((long)(2 + which) * B_ + b) * D_ * R_;

    extern __shared__ __align__(16) float lsm[];
    float* As = lsm;
    float* Bs = lsm + R_ * D_;
    __shared__ float z[LROWS][R_];

    int tid = threadIdx.x;
    int lane = tid & 31, w = tid >> 5;

    #pragma unroll
    for (int k = 0; k < 4; k++) {
        int d = tid + k * 256;
        float4 a0 = *(const float4*)&Ag[d * R_];
        float4 a1 = *(const float4*)&Ag[d * R_ + 4];
        float4 b0 = *(const float4*)&Bg[d * R_];
        float4 b1 = *(const float4*)&Bg[d * R_ + 4];
        As[0*D_+d] = a0.x; As[1*D_+d] = a0.y; As[2*D_+d] = a0.z; As[3*D_+d] = a0.w;
        As[4*D_+d] = a1.x; As[5*D_+d] = a1.y; As[6*D_+d] = a1.z; As[7*D_+d] = a1.w;
        Bs[0*D_+d] = b0.x; Bs[1*D_+d] = b0.y; Bs[2*D_+d] = b0.z; Bs[3*D_+d] = b0.w;
        Bs[4*D_+d] = b1.x; Bs[5*D_+d] = b1.y; Bs[6*D_+d] = b1.z; Bs[7*D_+d] = b1.w;
    }
    __syncthreads();

    #pragma unroll
    for (int rr = 0; rr < 4; rr++) {
        int row = rowBase + w * 4 + rr;
        const float* hrow = h + (long)row * D_;
        float part[R_];
        #pragma unroll
        for (int r = 0; r < R_; r++) part[r] = 0.f;
        #pragma unroll
        for (int k = 0; k < 32; k++) {
            int d = lane + k * 32;
            float hv = hrow[d];
            #pragma unroll
            for (int r = 0; r < R_; r++) part[r] += hv * As[r * D_ + d];
        }
        #pragma unroll
        for (int r = 0; r < R_; r++)
            #pragma unroll
            for (int o = 16; o > 0; o >>= 1)
                part[r] += __shfl_xor_sync(FULLMASK, part[r], o);
        if (lane == 0)
            #pragma unroll
            for (int r = 0; r < R_; r++) z[w * 4 + rr][r] = part[r];
    }
    __syncthreads();

    #pragma unroll
    for (int k = 0; k < 4; k++) {
        int d = tid + k * 256;
        float br[R_];
        #pragma unroll
        for (int r = 0; r < R_; r++) br[r] = Bs[r * D_ + d];
        for (int rr = 0; rr < LROWS; rr++) {
            long idx = (long)(rowBase + rr) * D_ + d;
            float delta = 0.f;
            #pragma unroll
            for (int r = 0; r < R_; r++) delta += z[rr][r] * br[r];
            h[idx] += 2.f * delta;
        }
    }
}

// ---------------------------------------------------------------------------
// Flash attention, bf16 mma (m16n8k16), causal. Q tile 128, K/V tile 64.
// 3-slot K/V ring, one __syncthreads per iteration, LDG prefetch held in regs.
// smem (bytes): Q 18432 | K 3x9216 | V^T 3x9216 | P 18432  = 92160
// ---------------------------------------------------------------------------
#define RB 144                       // row pitch in bytes (72 bf16)
#define KSLOT_B (64 * RB)            // 9216 bytes per K or V slot
#define FQ_B  (128 * RB)             // 18432
#define FLASH_SMEM (FQ_B + 3*KSLOT_B + 3*KSLOT_B + FQ_B)   // 92160

__global__ __launch_bounds__(256, 1) void flash_mma_kernel(
    const float* __restrict__ Q, const float* __restrict__ K,
    const float* __restrict__ V, float* __restrict__ O)
{
    extern __shared__ __align__(16) char smc[];
    const uint32_t qsB = smem_u32(smc);
    const uint32_t ksB = qsB + FQ_B;
    const uint32_t vtB = ksB + 3 * KSLOT_B;
    const uint32_t psB = vtB + 3 * KSLOT_B;

    int qi = (gridDim.x - 1) - blockIdx.x;   // heavy tiles first
    int h  = blockIdx.y;
    int b  = blockIdx.z;
    int tid = threadIdx.x;
    int lane = tid & 31;
    int w = tid >> 5;

    const float* Qp = Q + (long)(b * S_ + qi * 128) * D_ + h * DH_;

    // --- Q load + convert to bf16: tasks (q, c8): 1024 ---
    #pragma unroll
    for (int l = 0; l < 4; l++) {
        int idx = tid + l * 256;
        int q = idx >> 3, c8 = idx & 7;
        float4 a = *(const float4*)&Qp[(long)q * D_ + c8 * 8];
        float4 c = *(const float4*)&Qp[(long)q * D_ + c8 * 8 + 4];
        uint4 u;
        u.x = pk_bf16x2(a.x, a.y); u.y = pk_bf16x2(a.z, a.w);
        u.z = pk_bf16x2(c.x, c.y); u.w = pk_bf16x2(c.z, c.w);
        asm volatile("st.shared.v4.b32 [%0], {%1,%2,%3,%4};" ::
            "r"(qsB + q * RB + c8 * 16), "r"(u.x), "r"(u.y), "r"(u.z), "r"(u.w) : "memory");
    }

    // V transpose indices: g = tid>>4 (d-group), p0 = tid&15 (kpos pair)
    int vg = tid >> 4, vp0 = tid & 15;

    // --- K0 / V0 staged directly ---
    {
        const float* Kp = K + (long)(b * S_) * D_ + h * DH_;
        #pragma unroll
        for (int l = 0; l < 2; l++) {
            int idx = tid + l * 256;
            int kp = idx >> 3, c8 = idx & 7;
            float4 a = *(const float4*)&Kp[(long)kp * D_ + c8 * 8];
            float4 c = *(const float4*)&Kp[(long)kp * D_ + c8 * 8 + 4];
            uint4 u;
            u.x = pk_bf16x2(a.x, a.y); u.y = pk_bf16x2(a.z, a.w);
            u.z = pk_bf16x2(c.x, c.y); u.w = pk_bf16x2(c.z, c.w);
            asm volatile("st.shared.v4.b32 [%0], {%1,%2,%3,%4};" ::
                "r"(ksB + kp * RB + c8 * 16), "r"(u.x), "r"(u.y), "r"(u.z), "r"(u.w) : "memory");
        }
        const float* Vp = V + (long)(b * S_) * D_ + h * DH_;
        #pragma unroll
        for (int tk = 0; tk < 2; tk++) {
            int p = vp0 + tk * 16;
            float4 v0 = *(const float4*)&Vp[(long)(2 * p) * D_ + vg * 4];
            float4 v1 = *(const float4*)&Vp[(long)(2 * p + 1) * D_ + vg * 4];
            const float* f0 = (const float*)&v0;
            const float* f1 = (const float*)&v1;
            #pragma unroll
            for (int j = 0; j < 4; j++) {
                uint32_t u = pk_bf16x2(f0[j], f1[j]);
                asm volatile("st.shared.b32 [%0], %1;" ::
                    "r"(vtB + (vg * 4 + j) * RB + p * 4), "r"(u) : "memory");
            }
        }
    }
    __syncthreads();

    // Q fragments resident: 4 k16-steps x 4 regs
    uint32_t qf[4][4];
    {
        uint32_t base = qsB + (w * 16 + (lane & 15)) * RB + (lane >> 4) * 16;
        #pragma unroll
        for (int ds = 0; ds < 4; ds++)
            LDSM4(qf[ds][0], qf[ds][1], qf[ds][2], qf[ds][3], base + ds * 32);
    }

    float o[8][4];
    #pragma unroll
    for (int nt = 0; nt < 8; nt++)
        #pragma unroll
        for (int j = 0; j < 4; j++) o[nt][j] = 0.f;
    float m0 = -1e30f, m1 = -1e30f, l0 = 0.f, l1 = 0.f;

    const uint32_t bFragOff = ((lane & 7) + ((lane >> 4) << 3)) * RB + ((lane >> 3) & 1) * 16;
    const uint32_t pFragBase = psB + (w * 16 + (lane & 15)) * RB + (lane >> 4) * 16;
    const uint32_t pStoreBase = psB + (w * 16 + (lane >> 2)) * RB + 2 * (lane & 3) * 2;

    int ktmax = 2 * qi + 2;
    for (int kt = 0; kt < ktmax; kt++) {
        int slot = kt % 3;
        bool havenext = (kt + 1) < ktmax;

        // Prefetch next K/V into registers (held through compute)
        float4 ka0, ka1, kb0, kb1, va0, va1, vb0, vb1;
        if (havenext) {
            const float* Kp = K + (long)(b * S_ + (kt + 1) * 64) * D_ + h * DH_;
            {
                int idx = tid;
                int kp = idx >> 3, c8 = idx & 7;
                ka0 = *(const float4*)&Kp[(long)kp * D_ + c8 * 8];
                ka1 = *(const float4*)&Kp[(long)kp * D_ + c8 * 8 + 4];
                idx = tid + 256;
                kp = idx >> 3; c8 = idx & 7;
                kb0 = *(const float4*)&Kp[(long)kp * D_ + c8 * 8];
                kb1 = *(const float4*)&Kp[(long)kp * D_ + c8 * 8 + 4];
            }
            const float* Vp = V + (long)(b * S_ + (kt + 1) * 64) * D_ + h * DH_;
            va0 = *(const float4*)&Vp[(long)(2 * vp0) * D_ + vg * 4];
            va1 = *(const float4*)&Vp[(long)(2 * vp0 + 1) * D_ + vg * 4];
            vb0 = *(const float4*)&Vp[(long)(2 * (vp0 + 16)) * D_ + vg * 4];
            vb1 = *(const float4*)&Vp[(long)(2 * (vp0 + 16) + 1) * D_ + vg * 4];
        }

        bool active = (kt * 64) <= (qi * 128 + w * 16 + 15);
        if (active) {
            const uint32_t kBase = ksB + slot * KSLOT_B + bFragOff;
            const uint32_t vBase = vtB + slot * KSLOT_B + bFragOff;

            // ---- S = Q K^T (bf16, 4 k16-steps over d) ----
            float s[8][4];
            #pragma unroll
            for (int nt = 0; nt < 8; nt++)
                #pragma unroll
                for (int j = 0; j < 4; j++) s[nt][j] = 0.f;

            #pragma unroll
            for (int ds = 0; ds < 4; ds++) {
                uint32_t bf[8][2];
                #pragma unroll
                for (int ntp = 0; ntp < 4; ntp++) {
                    uint32_t r0, r1, r2, r3;
                    LDSM4(r0, r1, r2, r3, kBase + ntp * 16 * RB + ds * 32);
                    bf[2 * ntp][0] = r0; bf[2 * ntp][1] = r1;
                    bf[2 * ntp + 1][0] = r2; bf[2 * ntp + 1][1] = r3;
                }
                #pragma unroll
                for (int nt = 0; nt < 8; nt++)
                    MMA_BF16(s[nt], qf[ds], bf[nt][0], bf[nt][1]);
            }

            // ---- scale + causal mask + online softmax ----
            bool needmask = (kt * 64 + 63) > (qi * 128 + w * 16);
            int row0 = qi * 128 + w * 16 + (lane >> 2);
            float ml0 = -1e30f, ml1 = -1e30f;
            #pragma unroll
            for (int nt = 0; nt < 8; nt++) {
                #pragma unroll
                for (int j = 0; j < 4; j++) {
                    float v = s[nt][j] * 0.125f;
                    if (needmask) {
                        int col = kt * 64 + nt * 8 + 2 * (lane & 3) + (j & 1);
                        int row = row0 + ((j >> 1) << 3);
                        if (col > row) v = -1e30f;
                    }
                    s[nt][j] = v;
                }
                ml0 = fmaxf(ml0, fmaxf(s[nt][0], s[nt][1]));
                ml1 = fmaxf(ml1, fmaxf(s[nt][2], s[nt][3]));
            }
            ml0 = fmaxf(ml0, __shfl_xor_sync(FULLMASK, ml0, 1));
            ml0 = fmaxf(ml0, __shfl_xor_sync(FULLMASK, ml0, 2));
            ml1 = fmaxf(ml1, __shfl_xor_sync(FULLMASK, ml1, 1));
            ml1 = fmaxf(ml1, __shfl_xor_sync(FULLMASK, ml1, 2));
            float mn0 = fmaxf(m0, ml0), mn1 = fmaxf(m1, ml1);
            float a0 = __expf(m0 - mn0), a1 = __expf(m1 - mn1);
            float sum0 = 0.f, sum1 = 0.f;
            #pragma unroll
            for (int nt = 0; nt < 8; nt++) {
                // round to bf16 so l-sum matches P used in PV exactly
                s[nt][0] = rt_bf16(__expf(s[nt][0] - mn0));
                s[nt][1] = rt_bf16(__expf(s[nt][1] - mn0));
                s[nt][2] = rt_bf16(__expf(s[nt][2] - mn1));
                s[nt][3] = rt_bf16(__expf(s[nt][3] - mn1));
                sum0 += s[nt][0] + s[nt][1];
                sum1 += s[nt][2] + s[nt][3];
            }
            sum0 += __shfl_xor_sync(FULLMASK, sum0, 1);
            sum0 += __shfl_xor_sync(FULLMASK, sum0, 2);
            sum1 += __shfl_xor_sync(FULLMASK, sum1, 1);
            sum1 += __shfl_xor_sync(FULLMASK, sum1, 2);
            l0 = l0 * a0 + sum0;
            l1 = l1 * a1 + sum1;
            m0 = mn0; m1 = mn1;
            #pragma unroll
            for (int nt = 0; nt < 8; nt++) {
                o[nt][0] *= a0; o[nt][1] *= a0;
                o[nt][2] *= a1; o[nt][3] *= a1;
            }

            // ---- store P (bf16, per-warp slice) ----
            #pragma unroll
            for (int nt = 0; nt < 8; nt++) {
                uint32_t u0 = pk_bf16x2(s[nt][0], s[nt][1]);
                uint32_t u1 = pk_bf16x2(s[nt][2], s[nt][3]);
                asm volatile("st.shared.b32 [%0], %1;" ::
                    "r"(pStoreBase + nt * 16), "r"(u0) : "memory");
                asm volatile("st.shared.b32 [%0], %1;" ::
                    "r"(pStoreBase + 8 * RB + nt * 16), "r"(u1) : "memory");
            }
            __syncwarp();

            // ---- O += P V (bf16, 4 k16-steps over kpos) ----
            #pragma unroll
            for (int ks = 0; ks < 4; ks++) {
                uint32_t pf[4];
                LDSM4(pf[0], pf[1], pf[2], pf[3], pFragBase + ks * 32);
                uint32_t vf[8][2];
                #pragma unroll
                for (int ntp = 0; ntp < 4; ntp++) {
                    uint32_t r0, r1, r2, r3;
                    LDSM4(r0, r1, r2, r3, vBase + ntp * 16 * RB + ks * 32);
                    vf[2 * ntp][0] = r0; vf[2 * ntp][1] = r1;
                    vf[2 * ntp + 1][0] = r2; vf[2 * ntp + 1][1] = r3;
                }
                #pragma unroll
                for (int nt = 0; nt < 8; nt++)
                    MMA_BF16(o[nt], pf, vf[nt][0], vf[nt][1]);
            }
        }

        // ---- stage next K/V into slot (kt+1)%3 (safe under 3-slot ring) ----
        if (havenext) {
            int ns = (kt + 1) % 3;
            uint32_t kd = ksB + ns * KSLOT_B;
            {
                int idx = tid;
                int kp = idx >> 3, c8 = idx & 7;
                uint4 u;
                u.x = pk_bf16x2(ka0.x, ka0.y); u.y = pk_bf16x2(ka0.z, ka0.w);
                u.z = pk_bf16x2(ka1.x, ka1.y); u.w = pk_bf16x2(ka1.z, ka1.w);
                asm volatile("st.shared.v4.b32 [%0], {%1,%2,%3,%4};" ::
                    "r"(kd + kp * RB + c8 * 16), "r"(u.x), "r"(u.y), "r"(u.z), "r"(u.w) : "memory");
                idx = tid + 256;
                kp = idx >> 3; c8 = idx & 7;
                u.x = pk_bf16x2(kb0.x, kb0.y); u.y = pk_bf16x2(kb0.z, kb0.w);
                u.z = pk_bf16x2(kb1.x, kb1.y); u.w = pk_bf16x2(kb1.z, kb1.w);
                asm volatile("st.shared.v4.b32 [%0], {%1,%2,%3,%4};" ::
                    "r"(kd + kp * RB + c8 * 16), "r"(u.x), "r"(u.y), "r"(u.z), "r"(u.w) : "memory");
            }
            uint32_t vd = vtB + ns * KSLOT_B;
            const float* f0 = (const float*)&va0;
            const float* f1 = (const float*)&va1;
            const float* f2 = (const float*)&vb0;
            const float* f3 = (const float*)&vb1;
            #pragma unroll
            for (int j = 0; j < 4; j++) {
                asm volatile("st.shared.b32 [%0], %1;" ::
                    "r"(vd + (vg * 4 + j) * RB + vp0 * 4), "r"(pk_bf16x2(f0[j], f1[j])) : "memory");
                asm volatile("st.shared.b32 [%0], %1;" ::
                    "r"(vd + (vg * 4 + j) * RB + (vp0 + 16) * 4), "r"(pk_bf16x2(f2[j], f3[j])) : "memory");
            }
        }
        __syncthreads();
    }

    // normalize + write
    float inv0 = 1.f / l0, inv1 = 1.f / l1;
    int row0 = qi * 128 + w * 16 + (lane >> 2);
    long base0 = (long)(b * S_ + row0) * D_ + h * DH_ + 2 * (lane & 3);
    long base1 = base0 + 8 * D_;
    #pragma unroll
    for (int nt = 0; nt < 8; nt++) {
        *(float2*)&O[base0 + nt * 8] = make_float2(o[nt][0] * inv0, o[nt][1] * inv0);
        *(float2*)&O[base1 + nt * 8] = make_float2(o[nt][2] * inv1, o[nt][3] * inv1);
    }
}

// ---------------------------------------------------------------------------
// Launch
// ---------------------------------------------------------------------------
extern "C" void kernel_launch(void* const* d_in, const int* in_sizes, int n_in,
                              void* d_out, int out_size)
{
    const float* hidden = (const float*)d_in[0];
    // d_in[1] = attention_mask: causal tril -> handled analytically
    const float* lora   = (const float*)d_in[2];   // [4, B, D, R]
    const float* ln_w   = (const float*)d_in[3];
    const float* Wq     = (const float*)d_in[4];
    const float* Wk     = (const float*)d_in[5];
    const float* Wv     = (const float*)d_in[6];
    const float* Wo     = (const float*)d_in[7];
    float* out = (float*)d_out;

    float *x, *hq, *hk, *hv, *attn;
    cudaGetSymbolAddress((void**)&x,    g_x);
    cudaGetSymbolAddress((void**)&hq,   g_hq);
    cudaGetSymbolAddress((void**)&hk,   g_hk);
    cudaGetSymbolAddress((void**)&hv,   g_hv);
    cudaGetSymbolAddress((void**)&attn, g_attn);

    cudaFuncSetAttribute(gemm_qkv_kernel, cudaFuncAttributeMaxDynamicSharedMemorySize, GEMM_SMEM);
    cudaFuncSetAttribute(gemm_o_kernel,   cudaFuncAttributeMaxDynamicSharedMemorySize, GEMM_SMEM);
    cudaFuncSetAttribute(flash_mma_kernel, cudaFuncAttributeMaxDynamicSharedMemorySize, FLASH_SMEM);
    cudaFuncSetAttribute(lora_fused_kernel, cudaFuncAttributeMaxDynamicSharedMemorySize, LORA_SMEM);

    // 1. RMSNorm
    rmsnorm_kernel<<<M_, 256>>>(hidden, ln_w, x);

    // 2. Fused QKV projections (tf32)
    dim3 gq(24, M_ / 128);
    gemm_qkv_kernel<<<gq, 256, GEMM_SMEM>>>(x, Wq, Wk, Wv, hq, hk, hv);

    // 3. Fused LoRA deltas
    dim3 gl(M_ / LROWS, 2);
    lora_fused_kernel<<<gl, 256, LORA_SMEM>>>(hq, hk, lora);

    // 4. Causal flash attention (bf16 mma)
    dim3 fg(S_ / 128, H_, B_);
    flash_mma_kernel<<<fg, 256, FLASH_SMEM>>>(hq, hk, hv, attn);

    // 5. Output projection + residual (tf32)
    dim3 go(8, M_ / 128);
    gemm_o_kernel<<<go, 256, GEMM_SMEM>>>(attn, Wo, hidden, out);
}

// round 8
// speedup vs baseline: 4.4658x; 1.1480x over previous
#include <cuda_runtime.h>
#include <cuda_bf16.h>
#include <cstdint>
#include <math.h>

// Problem constants
#define B_  2
#define S_  2048
#define D_  1024
#define H_  16
#define DH_ 64
#define R_  8
#define M_  (B_*S_)          // 4096 rows

// Scratch (device globals; no allocation allowed)
__device__ float g_x[M_*D_];
__device__ float g_hq[M_*D_];
__device__ float g_hk[M_*D_];
__device__ float g_attn[M_*D_];
__device__ __nv_bfloat16 g_q16[M_*D_];
__device__ __nv_bfloat16 g_k16[M_*D_];
__device__ __nv_bfloat16 g_v16[M_*D_];

#define FULLMASK 0xffffffffu

// ===========================================================================
// PTX helpers
// ===========================================================================
__device__ __forceinline__ uint32_t smem_u32(const void* p) {
    uint32_t a;
    asm("{ .reg .u64 t; cvta.to.shared.u64 t, %1; cvt.u32.u64 %0, t; }"
        : "=r"(a) : "l"(p));
    return a;
}

#define LDSM4(R0,R1,R2,R3,ADDR) \
    asm volatile("ldmatrix.sync.aligned.m8n8.x4.shared.b16 {%0,%1,%2,%3}, [%4];" \
        : "=r"(R0), "=r"(R1), "=r"(R2), "=r"(R3) : "r"(ADDR))

#define LDSM4T(R0,R1,R2,R3,ADDR) \
    asm volatile("ldmatrix.sync.aligned.m8n8.x4.trans.shared.b16 {%0,%1,%2,%3}, [%4];" \
        : "=r"(R0), "=r"(R1), "=r"(R2), "=r"(R3) : "r"(ADDR))

#define MMA_TF32(C, A, B0, B1) \
    asm volatile("mma.sync.aligned.m16n8k8.row.col.f32.tf32.tf32.f32 " \
        "{%0,%1,%2,%3}, {%4,%5,%6,%7}, {%8,%9}, {%0,%1,%2,%3};" \
        : "+f"((C)[0]), "+f"((C)[1]), "+f"((C)[2]), "+f"((C)[3]) \
        : "r"((A)[0]), "r"((A)[1]), "r"((A)[2]), "r"((A)[3]), "r"(B0), "r"(B1))

#define MMA_BF16(C, A, B0, B1) \
    asm volatile("mma.sync.aligned.m16n8k16.row.col.f32.bf16.bf16.f32 " \
        "{%0,%1,%2,%3}, {%4,%5,%6,%7}, {%8,%9}, {%0,%1,%2,%3};" \
        : "+f"((C)[0]), "+f"((C)[1]), "+f"((C)[2]), "+f"((C)[3]) \
        : "r"((A)[0]), "r"((A)[1]), "r"((A)[2]), "r"((A)[3]), "r"(B0), "r"(B1))

#define CP16(DST, SRC) \
    asm volatile("cp.async.cg.shared.global [%0], [%1], 16;" :: "r"(DST), "l"(SRC))
#define CP_COMMIT() asm volatile("cp.async.commit_group;" ::: "memory")
#define CP_WAIT(N)  asm volatile("cp.async.wait_group %0;" :: "n"(N) : "memory")

__device__ __forceinline__ uint32_t pk_bf16x2(float a, float b) {
    __nv_bfloat162 t = __floats2bfloat162_rn(a, b);
    return *reinterpret_cast<uint32_t*>(&t);
}
__device__ __forceinline__ float rt_bf16(float a) {
    return __bfloat162float(__float2bfloat16(a));
}

// ---------------------------------------------------------------------------
// RMSNorm
// ---------------------------------------------------------------------------
__global__ __launch_bounds__(256) void rmsnorm_kernel(
    const float* __restrict__ hs, const float* __restrict__ w, float* __restrict__ out)
{
    int row = blockIdx.x;
    int t = threadIdx.x;
    const float* x = hs + (long)row * D_;

    float v[4];
    float ss = 0.f;
    #pragma unroll
    for (int i = 0; i < 4; i++) {
        v[i] = x[t + i * 256];
        ss += v[i] * v[i];
    }
    #pragma unroll
    for (int o = 16; o > 0; o >>= 1) ss += __shfl_xor_sync(FULLMASK, ss, o);
    __shared__ float red[8];
    if ((t & 31) == 0) red[t >> 5] = ss;
    __syncthreads();
    __shared__ float s_inv;
    if (t == 0) {
        float s = 0.f;
        #pragma unroll
        for (int i = 0; i < 8; i++) s += red[i];
        s_inv = rsqrtf(s / (float)D_ + 1e-5f);
    }
    __syncthreads();
    float inv = s_inv;
    #pragma unroll
    for (int i = 0; i < 4; i++) {
        int d = t + i * 256;
        out[(long)row * D_ + d] = v[i] * inv * w[d];
    }
}

// ---------------------------------------------------------------------------
// GEMM core (tf32). MODE: 0 = fp32 out, 1 = fp32 + residual, 2 = bf16 out
// ---------------------------------------------------------------------------
#define GP 36
#define GTILE_B (128*GP*4)
#define GEMM_SMEM (4*GTILE_B)

template <int MODE>
__device__ __forceinline__ void gemm128_core(
    const float* __restrict__ A, const float* __restrict__ W,
    const float* __restrict__ resid, float* __restrict__ C32,
    __nv_bfloat16* __restrict__ C16,
    int by, int bx, char* gsm)
{
    const uint32_t sA = smem_u32(gsm);
    const uint32_t sB = sA + 2 * GTILE_B;
    int tid = threadIdx.x;
    int lane = tid & 31;
    int w = tid >> 5;
    int wm = (w >> 1) * 32;
    int wn = (w & 1) * 64;

    const float* aP[4]; const float* bP[4];
    uint32_t stA[4], stB[4];
    #pragma unroll
    for (int l = 0; l < 4; l++) {
        int idx = tid + l * 256;
        int r = idx >> 3, c4 = idx & 7;
        aP[l] = A + (long)(by * 128 + r) * D_ + c4 * 4;
        bP[l] = W + (long)(bx * 128 + r) * D_ + c4 * 4;
        stA[l] = sA + r * (GP * 4) + c4 * 16;
        stB[l] = sB + r * (GP * 4) + c4 * 16;
    }

    float acc[2][8][4];
    #pragma unroll
    for (int mt = 0; mt < 2; mt++)
        #pragma unroll
        for (int nt = 0; nt < 8; nt++)
            #pragma unroll
            for (int j = 0; j < 4; j++) acc[mt][nt][j] = 0.f;

    const uint32_t aFragBase = sA +
        ((wm + (lane & 15)) * GP + ((lane >> 4) << 2)) * 4;
    const uint32_t bFragBase = sB +
        ((wn + (lane & 7) + ((lane >> 4) << 3)) * GP + (((lane >> 3) & 1) << 2)) * 4;

    #pragma unroll
    for (int l = 0; l < 4; l++) { CP16(stA[l], aP[l]); CP16(stB[l], bP[l]); }
    CP_COMMIT();

    for (int kc = 0; kc < 32; kc++) {
        int buf = kc & 1;
        if (kc + 1 < 32) {
            #pragma unroll
            for (int l = 0; l < 4; l++) {
                CP16(stA[l] + (buf ^ 1) * GTILE_B, aP[l] + (kc + 1) * 32);
                CP16(stB[l] + (buf ^ 1) * GTILE_B, bP[l] + (kc + 1) * 32);
            }
            CP_COMMIT();
            CP_WAIT(1);
        } else {
            CP_WAIT(0);
        }
        __syncthreads();

        uint32_t aBuf = aFragBase + buf * GTILE_B;
        uint32_t bBuf = bFragBase + buf * GTILE_B;

        #pragma unroll
        for (int ks = 0; ks < 4; ks++) {
            uint32_t af[2][4];
            uint32_t bf[8][2];
            #pragma unroll
            for (int mt = 0; mt < 2; mt++)
                LDSM4(af[mt][0], af[mt][1], af[mt][2], af[mt][3],
                      aBuf + (mt * 16 * GP + ks * 8) * 4);
            #pragma unroll
            for (int ntp = 0; ntp < 4; ntp++) {
                uint32_t r0, r1, r2, r3;
                LDSM4(r0, r1, r2, r3, bBuf + (ntp * 16 * GP + ks * 8) * 4);
                bf[2 * ntp][0] = r0; bf[2 * ntp][1] = r1;
                bf[2 * ntp + 1][0] = r2; bf[2 * ntp + 1][1] = r3;
            }
            #pragma unroll
            for (int mt = 0; mt < 2; mt++)
                #pragma unroll
                for (int nt = 0; nt < 8; nt++)
                    MMA_TF32(acc[mt][nt], af[mt], bf[nt][0], bf[nt][1]);
        }
        __syncthreads();
    }

    #pragma unroll
    for (int mt = 0; mt < 2; mt++) {
        int row = by * 128 + wm + mt * 16 + (lane >> 2);
        int col = bx * 128 + wn + 2 * (lane & 3);
        #pragma unroll
        for (int nt = 0; nt < 8; nt++) {
            long i0 = (long)row * D_ + col + nt * 8;
            long i1 = i0 + 8 * D_;
            if (MODE == 2) {
                *(uint32_t*)&C16[i0] = pk_bf16x2(acc[mt][nt][0], acc[mt][nt][1]);
                *(uint32_t*)&C16[i1] = pk_bf16x2(acc[mt][nt][2], acc[mt][nt][3]);
            } else {
                float2 v0 = make_float2(acc[mt][nt][0], acc[mt][nt][1]);
                float2 v1 = make_float2(acc[mt][nt][2], acc[mt][nt][3]);
                if (MODE == 1) {
                    float2 r0 = *(const float2*)&resid[i0];
                    float2 r1 = *(const float2*)&resid[i1];
                    v0.x += r0.x; v0.y += r0.y;
                    v1.x += r1.x; v1.y += r1.y;
                }
                *(float2*)&C32[i0] = v0;
                *(float2*)&C32[i1] = v1;
            }
        }
    }
}

__global__ __launch_bounds__(256, 2) void gemm_qkv_kernel(
    const float* __restrict__ A,
    const float* __restrict__ Wq, const float* __restrict__ Wk, const float* __restrict__ Wv,
    float* __restrict__ hq, float* __restrict__ hk, __nv_bfloat16* __restrict__ v16)
{
    extern __shared__ __align__(16) char gsm[];
    int wsel = blockIdx.x >> 3;
    int bx = blockIdx.x & 7;
    if (wsel == 0)
        gemm128_core<0>(A, Wq, nullptr, hq, nullptr, blockIdx.y, bx, gsm);
    else if (wsel == 1)
        gemm128_core<0>(A, Wk, nullptr, hk, nullptr, blockIdx.y, bx, gsm);
    else
        gemm128_core<2>(A, Wv, nullptr, nullptr, v16, blockIdx.y, bx, gsm);
}

__global__ __launch_bounds__(256, 2) void gemm_o_kernel(
    const float* __restrict__ A, const float* __restrict__ W,
    const float* __restrict__ resid, float* __restrict__ C)
{
    extern __shared__ __align__(16) char gsm[];
    gemm128_core<1>(A, W, resid, C, nullptr, blockIdx.y, blockIdx.x, gsm);
}

// ---------------------------------------------------------------------------
// Fused LoRA: reads fp32 h (GEMM out), writes bf16 (h + 2*(h@A)@B^T)
// ---------------------------------------------------------------------------
#define LROWS 32
#define LORA_SMEM (2 * R_ * D_ * 4)

__global__ __launch_bounds__(256) void lora_fused_kernel(
    const float* __restrict__ hq, const float* __restrict__ hk,
    __nv_bfloat16* __restrict__ q16, __nv_bfloat16* __restrict__ k16,
    const float* __restrict__ lora)
{
    int which = blockIdx.y;
    const float* h = which ? hk : hq;
    __nv_bfloat16* g16 = which ? k16 : q16;
    int rowBase = blockIdx.x * LROWS;
    int b = rowBase / S_;
    const float* Ag = lora + ((long)which * B_ + b) * D_ * R_;
    const float* Bg = lora + ((long)(2 + which) * B_ + b) * D_ * R_;

    extern __shared__ __align__(16) float lsm[];
    float* As = lsm;
    float* Bs = lsm + R_ * D_;
    __shared__ float z[LROWS][R_];

    int tid = threadIdx.x;
    int lane = tid & 31, w = tid >> 5;

    #pragma unroll
    for (int k = 0; k < 4; k++) {
        int d = tid + k * 256;
        float4 a0 = *(const float4*)&Ag[d * R_];
        float4 a1 = *(const float4*)&Ag[d * R_ + 4];
        float4 b0 = *(const float4*)&Bg[d * R_];
        float4 b1 = *(const float4*)&Bg[d * R_ + 4];
        As[0*D_+d] = a0.x; As[1*D_+d] = a0.y; As[2*D_+d] = a0.z; As[3*D_+d] = a0.w;
        As[4*D_+d] = a1.x; As[5*D_+d] = a1.y; As[6*D_+d] = a1.z; As[7*D_+d] = a1.w;
        Bs[0*D_+d] = b0.x; Bs[1*D_+d] = b0.y; Bs[2*D_+d] = b0.z; Bs[3*D_+d] = b0.w;
        Bs[4*D_+d] = b1.x; Bs[5*D_+d] = b1.y; Bs[6*D_+d] = b1.z; Bs[7*D_+d] = b1.w;
    }
    __syncthreads();

    #pragma unroll
    for (int rr = 0; rr < 4; rr++) {
        int row = rowBase + w * 4 + rr;
        const float* hrow = h + (long)row * D_;
        float part[R_];
        #pragma unroll
        for (int r = 0; r < R_; r++) part[r] = 0.f;
        #pragma unroll
        for (int k = 0; k < 32; k++) {
            int d = lane + k * 32;
            float hv = hrow[d];
            #pragma unroll
            for (int r = 0; r < R_; r++) part[r] += hv * As[r * D_ + d];
        }
        #pragma unroll
        for (int r = 0; r < R_; r++)
            #pragma unroll
            for (int o = 16; o > 0; o >>= 1)
                part[r] += __shfl_xor_sync(FULLMASK, part[r], o);
        if (lane == 0)
            #pragma unroll
            for (int r = 0; r < R_; r++) z[w * 4 + rr][r] = part[r];
    }
    __syncthreads();

    #pragma unroll
    for (int k = 0; k < 2; k++) {
        int d0 = (tid + k * 256) * 2;     // each thread: 2 consecutive d
        float br0[R_], br1[R_];
        #pragma unroll
        for (int r = 0; r < R_; r++) { br0[r] = Bs[r * D_ + d0]; br1[r] = Bs[r * D_ + d0 + 1]; }
        for (int rr = 0; rr < LROWS; rr++) {
            long idx = (long)(rowBase + rr) * D_ + d0;
            float d0v = h[idx], d1v = h[idx + 1];
            float del0 = 0.f, del1 = 0.f;
            #pragma unroll
            for (int r = 0; r < R_; r++) {
                del0 += z[rr][r] * br0[r];
                del1 += z[rr][r] * br1[r];
            }
            *(uint32_t*)&g16[idx] = pk_bf16x2(d0v + 2.f * del0, d1v + 2.f * del1);
        }
    }
}

// ---------------------------------------------------------------------------
// Flash attention, bf16 mma, causal. Q tile 128, K/V tile 64.
// All inputs pre-converted bf16. K and V via cp.async (3-slot ring).
// V in natural [kpos][d] layout; B-fragments via ldmatrix.trans.
// ---------------------------------------------------------------------------
#define RB 144                       // row pitch bytes (72 bf16, data = 128B)
#define KSLOT_B (64 * RB)            // 9216
#define FQ_B  (128 * RB)             // 18432
#define FLASH_SMEM (FQ_B + 3*KSLOT_B + 3*KSLOT_B + FQ_B)   // 92160

__global__ __launch_bounds__(256, 1) void flash_mma_kernel(
    const __nv_bfloat16* __restrict__ Q, const __nv_bfloat16* __restrict__ K,
    const __nv_bfloat16* __restrict__ V, float* __restrict__ O)
{
    extern __shared__ __align__(16) char smc[];
    const uint32_t qsB = smem_u32(smc);
    const uint32_t ksB = qsB + FQ_B;
    const uint32_t vnB = ksB + 3 * KSLOT_B;
    const uint32_t psB = vnB + 3 * KSLOT_B;

    int qi = (gridDim.x - 1) - blockIdx.x;   // heavy tiles first
    int h  = blockIdx.y;
    int b  = blockIdx.z;
    int tid = threadIdx.x;
    int lane = tid & 31;
    int w = tid >> 5;

    // K/V cp.async task split: 512 chunks per tile, 2 per thread
    int cKp0 = tid >> 3, cC0 = tid & 7;            // l=0
    int cKp1 = (tid + 256) >> 3, cC1 = tid & 7;    // l=1

    // --- Prologue: Q (LDG bf16 -> STS), K0/V0 via cp.async ---
    const __nv_bfloat16* Qp = Q + (long)(b * S_ + qi * 128) * D_ + h * DH_;
    #pragma unroll
    for (int l = 0; l < 4; l++) {
        int idx = tid + l * 256;
        int q = idx >> 3, c8 = idx & 7;
        float4 v = *(const float4*)&Qp[(long)q * D_ + c8 * 8];
        asm volatile("st.shared.v4.b32 [%0], {%1,%2,%3,%4};" ::
            "r"(qsB + q * RB + c8 * 16),
            "r"(__float_as_uint(v.x)), "r"(__float_as_uint(v.y)),
            "r"(__float_as_uint(v.z)), "r"(__float_as_uint(v.w)) : "memory");
    }
    {
        const __nv_bfloat16* Kp = K + (long)(b * S_) * D_ + h * DH_;
        const __nv_bfloat16* Vp = V + (long)(b * S_) * D_ + h * DH_;
        CP16(ksB + cKp0 * RB + cC0 * 16, Kp + (long)cKp0 * D_ + cC0 * 8);
        CP16(ksB + cKp1 * RB + cC1 * 16, Kp + (long)cKp1 * D_ + cC1 * 8);
        CP16(vnB + cKp0 * RB + cC0 * 16, Vp + (long)cKp0 * D_ + cC0 * 8);
        CP16(vnB + cKp1 * RB + cC1 * 16, Vp + (long)cKp1 * D_ + cC1 * 8);
        CP_COMMIT();
    }

    float o[8][4];
    #pragma unroll
    for (int nt = 0; nt < 8; nt++)
        #pragma unroll
        for (int j = 0; j < 4; j++) o[nt][j] = 0.f;
    float m0 = -1e30f, m1 = -1e30f, l0 = 0.f, l1 = 0.f;

    // fragment offsets
    const uint32_t kFragOff = ((lane & 7) + ((lane >> 4) << 3)) * RB + ((lane >> 3) & 1) * 16;
    const uint32_t vFragOff = ((lane & 7) + ((lane >> 3) & 1) * 8) * RB + (lane >> 4) * 16;
    const uint32_t pFragBase = psB + (w * 16 + (lane & 15)) * RB + (lane >> 4) * 16;
    const uint32_t pStoreBase = psB + (w * 16 + (lane >> 2)) * RB + (lane & 3) * 4;

    bool qfLoaded = false;
    uint32_t qf[4][4];

    int ktmax = 2 * qi + 2;
    for (int kt = 0; kt < ktmax; kt++) {
        int slot = kt % 3;
        bool havenext = (kt + 1) < ktmax;

        // stage next K/V via cp.async into slot (kt+1)%3
        if (havenext) {
            int ns = (kt + 1) % 3;
            const __nv_bfloat16* Kp = K + (long)(b * S_ + (kt + 1) * 64) * D_ + h * DH_;
            const __nv_bfloat16* Vp = V + (long)(b * S_ + (kt + 1) * 64) * D_ + h * DH_;
            uint32_t kd = ksB + ns * KSLOT_B, vd = vnB + ns * KSLOT_B;
            CP16(kd + cKp0 * RB + cC0 * 16, Kp + (long)cKp0 * D_ + cC0 * 8);
            CP16(kd + cKp1 * RB + cC1 * 16, Kp + (long)cKp1 * D_ + cC1 * 8);
            CP16(vd + cKp0 * RB + cC0 * 16, Vp + (long)cKp0 * D_ + cC0 * 8);
            CP16(vd + cKp1 * RB + cC1 * 16, Vp + (long)cKp1 * D_ + cC1 * 8);
            CP_COMMIT();
            CP_WAIT(1);
        } else {
            CP_WAIT(0);
        }
        __syncthreads();

        if (!qfLoaded) {       // Q frags after first barrier (Q STS visible)
            uint32_t base = qsB + (w * 16 + (lane & 15)) * RB + (lane >> 4) * 16;
            #pragma unroll
            for (int ds = 0; ds < 4; ds++)
                LDSM4(qf[ds][0], qf[ds][1], qf[ds][2], qf[ds][3], base + ds * 32);
            qfLoaded = true;
        }

        bool active = (kt * 64) <= (qi * 128 + w * 16 + 15);
        if (active) {
            const uint32_t kBase = ksB + slot * KSLOT_B + kFragOff;
            const uint32_t vBase = vnB + slot * KSLOT_B + vFragOff;

            // ---- S = Q K^T ----
            float s[8][4];
            #pragma unroll
            for (int nt = 0; nt < 8; nt++)
                #pragma unroll
                for (int j = 0; j < 4; j++) s[nt][j] = 0.f;

            #pragma unroll
            for (int ds = 0; ds < 4; ds++) {
                uint32_t bf[8][2];
                #pragma unroll
                for (int ntp = 0; ntp < 4; ntp++) {
                    uint32_t r0, r1, r2, r3;
                    LDSM4(r0, r1, r2, r3, kBase + ntp * 16 * RB + ds * 32);
                    bf[2 * ntp][0] = r0; bf[2 * ntp][1] = r1;
                    bf[2 * ntp + 1][0] = r2; bf[2 * ntp + 1][1] = r3;
                }
                #pragma unroll
                for (int nt = 0; nt < 8; nt++)
                    MMA_BF16(s[nt], qf[ds], bf[nt][0], bf[nt][1]);
            }

            // ---- scale + causal mask + online softmax ----
            bool needmask = (kt * 64 + 63) > (qi * 128 + w * 16);
            int row0 = qi * 128 + w * 16 + (lane >> 2);
            float ml0 = -1e30f, ml1 = -1e30f;
            #pragma unroll
            for (int nt = 0; nt < 8; nt++) {
                #pragma unroll
                for (int j = 0; j < 4; j++) {
                    float v = s[nt][j] * 0.125f;
                    if (needmask) {
                        int col = kt * 64 + nt * 8 + 2 * (lane & 3) + (j & 1);
                        int row = row0 + ((j >> 1) << 3);
                        if (col > row) v = -1e30f;
                    }
                    s[nt][j] = v;
                }
                ml0 = fmaxf(ml0, fmaxf(s[nt][0], s[nt][1]));
                ml1 = fmaxf(ml1, fmaxf(s[nt][2], s[nt][3]));
            }
            ml0 = fmaxf(ml0, __shfl_xor_sync(FULLMASK, ml0, 1));
            ml0 = fmaxf(ml0, __shfl_xor_sync(FULLMASK, ml0, 2));
            ml1 = fmaxf(ml1, __shfl_xor_sync(FULLMASK, ml1, 1));
            ml1 = fmaxf(ml1, __shfl_xor_sync(FULLMASK, ml1, 2));
            float mn0 = fmaxf(m0, ml0), mn1 = fmaxf(m1, ml1);
            float a0 = __expf(m0 - mn0), a1 = __expf(m1 - mn1);
            float sum0 = 0.f, sum1 = 0.f;
            #pragma unroll
            for (int nt = 0; nt < 8; nt++) {
                s[nt][0] = rt_bf16(__expf(s[nt][0] - mn0));
                s[nt][1] = rt_bf16(__expf(s[nt][1] - mn0));
                s[nt][2] = rt_bf16(__expf(s[nt][2] - mn1));
                s[nt][3] = rt_bf16(__expf(s[nt][3] - mn1));
                sum0 += s[nt][0] + s[nt][1];
                sum1 += s[nt][2] + s[nt][3];
            }
            sum0 += __shfl_xor_sync(FULLMASK, sum0, 1);
            sum0 += __shfl_xor_sync(FULLMASK, sum0, 2);
            sum1 += __shfl_xor_sync(FULLMASK, sum1, 1);
            sum1 += __shfl_xor_sync(FULLMASK, sum1, 2);
            l0 = l0 * a0 + sum0;
            l1 = l1 * a1 + sum1;
            m0 = mn0; m1 = mn1;
            #pragma unroll
            for (int nt = 0; nt < 8; nt++) {
                o[nt][0] *= a0; o[nt][1] *= a0;
                o[nt][2] *= a1; o[nt][3] *= a1;
            }

            // ---- store P (bf16, per-warp slice) ----
            #pragma unroll
            for (int nt = 0; nt < 8; nt++) {
                asm volatile("st.shared.b32 [%0], %1;" ::
                    "r"(pStoreBase + nt * 16), "r"(pk_bf16x2(s[nt][0], s[nt][1])) : "memory");
                asm volatile("st.shared.b32 [%0], %1;" ::
                    "r"(pStoreBase + 8 * RB + nt * 16), "r"(pk_bf16x2(s[nt][2], s[nt][3])) : "memory");
            }
            __syncwarp();

            // ---- O += P V  (V natural layout, trans ldmatrix) ----
            #pragma unroll
            for (int ks = 0; ks < 4; ks++) {
                uint32_t pf[4];
                LDSM4(pf[0], pf[1], pf[2], pf[3], pFragBase + ks * 32);
                uint32_t vf[8][2];
                #pragma unroll
                for (int ntp = 0; ntp < 4; ntp++) {
                    uint32_t r0, r1, r2, r3;
                    LDSM4T(r0, r1, r2, r3, vBase + ks * 16 * RB + ntp * 32);
                    vf[2 * ntp][0] = r0; vf[2 * ntp][1] = r1;
                    vf[2 * ntp + 1][0] = r2; vf[2 * ntp + 1][1] = r3;
                }
                #pragma unroll
                for (int nt = 0; nt < 8; nt++)
                    MMA_BF16(o[nt], pf, vf[nt][0], vf[nt][1]);
            }
        }
    }

    // normalize + write
    float inv0 = 1.f / l0, inv1 = 1.f / l1;
    int row0 = qi * 128 + w * 16 + (lane >> 2);
    long base0 = (long)(b * S_ + row0) * D_ + h * DH_ + 2 * (lane & 3);
    long base1 = base0 + 8 * D_;
    #pragma unroll
    for (int nt = 0; nt < 8; nt++) {
        *(float2*)&O[base0 + nt * 8] = make_float2(o[nt][0] * inv0, o[nt][1] * inv0);
        *(float2*)&O[base1 + nt * 8] = make_float2(o[nt][2] * inv1, o[nt][3] * inv1);
    }
}

// ---------------------------------------------------------------------------
// Launch
// ---------------------------------------------------------------------------
extern "C" void kernel_launch(void* const* d_in, const int* in_sizes, int n_in,
                              void* d_out, int out_size)
{
    const float* hidden = (const float*)d_in[0];
    // d_in[1] = attention_mask: causal tril -> handled analytically
    const float* lora   = (const float*)d_in[2];   // [4, B, D, R]
    const float* ln_w   = (const float*)d_in[3];
    const float* Wq     = (const float*)d_in[4];
    const float* Wk     = (const float*)d_in[5];
    const float* Wv     = (const float*)d_in[6];
    const float* Wo     = (const float*)d_in[7];
    float* out = (float*)d_out;

    float *x, *hq, *hk, *attn;
    __nv_bfloat16 *q16, *k16, *v16;
    cudaGetSymbolAddress((void**)&x,    g_x);
    cudaGetSymbolAddress((void**)&hq,   g_hq);
    cudaGetSymbolAddress((void**)&hk,   g_hk);
    cudaGetSymbolAddress((void**)&attn, g_attn);
    cudaGetSymbolAddress((void**)&q16,  g_q16);
    cudaGetSymbolAddress((void**)&k16,  g_k16);
    cudaGetSymbolAddress((void**)&v16,  g_v16);

    cudaFuncSetAttribute(gemm_qkv_kernel, cudaFuncAttributeMaxDynamicSharedMemorySize, GEMM_SMEM);
    cudaFuncSetAttribute(gemm_o_kernel,   cudaFuncAttributeMaxDynamicSharedMemorySize, GEMM_SMEM);
    cudaFuncSetAttribute(flash_mma_kernel, cudaFuncAttributeMaxDynamicSharedMemorySize, FLASH_SMEM);
    cudaFuncSetAttribute(lora_fused_kernel, cudaFuncAttributeMaxDynamicSharedMemorySize, LORA_SMEM);

    // 1. RMSNorm
    rmsnorm_kernel<<<M_, 256>>>(hidden, ln_w, x);

    // 2. Fused QKV projections (tf32; V written bf16)
    dim3 gq(24, M_ / 128);
    gemm_qkv_kernel<<<gq, 256, GEMM_SMEM>>>(x, Wq, Wk, Wv, hq, hk, v16);

    // 3. Fused LoRA deltas -> bf16 q/k
    dim3 gl(M_ / LROWS, 2);
    lora_fused_kernel<<<gl, 256, LORA_SMEM>>>(hq, hk, q16, k16, lora);

    // 4. Causal flash attention (bf16 in, fp32 out)
    dim3 fg(S_ / 128, H_, B_);
    flash_mma_kernel<<<fg, 256, FLASH_SMEM>>>(q16, k16, v16, attn);

    // 5. Output projection + residual (tf32)
    dim3 go(8, M_ / 128);
    gemm_o_kernel<<<go, 256, GEMM_SMEM>>>(attn, Wo, hidden, out);
}

// round 10
// speedup vs baseline: 6.0204x; 1.3481x over previous
#include <cuda_runtime.h>
#include <cuda_bf16.h>
#include <cstdint>
#include <math.h>

// Problem constants
#define B_  2
#define S_  2048
#define D_  1024
#define H_  16
#define DH_ 64
#define R_  8
#define M_  (B_*S_)          // 4096 rows

// Scratch (device globals; no allocation allowed)
__device__ __nv_bfloat16 g_x16[M_*D_];
__device__ float g_hq[M_*D_];
__device__ float g_hk[M_*D_];
__device__ __nv_bfloat16 g_q16[M_*D_];
__device__ __nv_bfloat16 g_k16[M_*D_];
__device__ __nv_bfloat16 g_v16[M_*D_];
__device__ __nv_bfloat16 g_attn16[M_*D_];
__device__ __nv_bfloat16 g_wq16[D_*D_];
__device__ __nv_bfloat16 g_wk16[D_*D_];
__device__ __nv_bfloat16 g_wv16[D_*D_];
__device__ __nv_bfloat16 g_wo16[D_*D_];

#define FULLMASK 0xffffffffu

// ===========================================================================
// PTX helpers
// ===========================================================================
__device__ __forceinline__ uint32_t smem_u32(const void* p) {
    uint32_t a;
    asm("{ .reg .u64 t; cvta.to.shared.u64 t, %1; cvt.u32.u64 %0, t; }"
        : "=r"(a) : "l"(p));
    return a;
}

#define LDSM4(R0,R1,R2,R3,ADDR) \
    asm volatile("ldmatrix.sync.aligned.m8n8.x4.shared.b16 {%0,%1,%2,%3}, [%4];" \
        : "=r"(R0), "=r"(R1), "=r"(R2), "=r"(R3) : "r"(ADDR))

#define LDSM4T(R0,R1,R2,R3,ADDR) \
    asm volatile("ldmatrix.sync.aligned.m8n8.x4.trans.shared.b16 {%0,%1,%2,%3}, [%4];" \
        : "=r"(R0), "=r"(R1), "=r"(R2), "=r"(R3) : "r"(ADDR))

#define MMA_BF16(C, A, B0, B1) \
    asm volatile("mma.sync.aligned.m16n8k16.row.col.f32.bf16.bf16.f32 " \
        "{%0,%1,%2,%3}, {%4,%5,%6,%7}, {%8,%9}, {%0,%1,%2,%3};" \
        : "+f"((C)[0]), "+f"((C)[1]), "+f"((C)[2]), "+f"((C)[3]) \
        : "r"((A)[0]), "r"((A)[1]), "r"((A)[2]), "r"((A)[3]), "r"(B0), "r"(B1))

#define CP16(DST, SRC) \
    asm volatile("cp.async.cg.shared.global [%0], [%1], 16;" :: "r"(DST), "l"(SRC))
#define CP_COMMIT() asm volatile("cp.async.commit_group;" ::: "memory")
#define CP_WAIT(N)  asm volatile("cp.async.wait_group %0;" :: "n"(N) : "memory")

__device__ __forceinline__ uint32_t pk_bf16x2(float a, float b) {
    __nv_bfloat162 t = __floats2bfloat162_rn(a, b);
    return *reinterpret_cast<uint32_t*>(&t);
}
__device__ __forceinline__ float rt_bf16(float a) {
    return __bfloat162float(__float2bfloat16(a));
}

// ---------------------------------------------------------------------------
// RMSNorm -> bf16 output
// ---------------------------------------------------------------------------
__global__ __launch_bounds__(256) void rmsnorm_kernel(
    const float* __restrict__ hs, const float* __restrict__ w,
    __nv_bfloat16* __restrict__ out16)
{
    int row = blockIdx.x;
    int t = threadIdx.x;
    const float* x = hs + (long)row * D_;

    float4 v = *(const float4*)&x[t * 4];
    float ss = v.x*v.x + v.y*v.y + v.z*v.z + v.w*v.w;
    #pragma unroll
    for (int o = 16; o > 0; o >>= 1) ss += __shfl_xor_sync(FULLMASK, ss, o);
    __shared__ float red[8];
    if ((t & 31) == 0) red[t >> 5] = ss;
    __syncthreads();
    __shared__ float s_inv;
    if (t == 0) {
        float s = 0.f;
        #pragma unroll
        for (int i = 0; i < 8; i++) s += red[i];
        s_inv = rsqrtf(s / (float)D_ + 1e-5f);
    }
    __syncthreads();
    float inv = s_inv;
    float4 wv = *(const float4*)&w[t * 4];
    uint2 o2;
    o2.x = pk_bf16x2(v.x * inv * wv.x, v.y * inv * wv.y);
    o2.y = pk_bf16x2(v.z * inv * wv.z, v.w * inv * wv.w);
    *(uint2*)&out16[(long)row * D_ + t * 4] = o2;
}

// ---------------------------------------------------------------------------
// Weight conversion fp32 -> bf16 (4 matrices, one launch)
// ---------------------------------------------------------------------------
__global__ __launch_bounds__(256) void wconv_kernel(
    const float* __restrict__ Wq, const float* __restrict__ Wk,
    const float* __restrict__ Wv, const float* __restrict__ Wo,
    __nv_bfloat16* __restrict__ q16, __nv_bfloat16* __restrict__ k16,
    __nv_bfloat16* __restrict__ v16, __nv_bfloat16* __restrict__ o16)
{
    int sel = blockIdx.y;
    const float* src = (sel == 0) ? Wq : (sel == 1) ? Wk : (sel == 2) ? Wv : Wo;
    __nv_bfloat16* dst = (sel == 0) ? q16 : (sel == 1) ? k16 : (sel == 2) ? v16 : o16;
    long idx = ((long)blockIdx.x * 256 + threadIdx.x) * 8;
    float4 a = *(const float4*)&src[idx];
    float4 b = *(const float4*)&src[idx + 4];
    uint4 u;
    u.x = pk_bf16x2(a.x, a.y); u.y = pk_bf16x2(a.z, a.w);
    u.z = pk_bf16x2(b.x, b.y); u.w = pk_bf16x2(b.z, b.w);
    *(uint4*)&dst[idx] = u;
}

// ---------------------------------------------------------------------------
// bf16 GEMM core: C[128x128] = A[*,1024] @ W[*,1024]^T.
// BK=64 bf16, double-buffered cp.async, 8 warps x (32x64) warp tiles.
// MODE: 0 = fp32 out, 1 = fp32 + residual, 2 = bf16 out
// ---------------------------------------------------------------------------
#define RBW 144                     // 64 bf16 = 128B data + 16B pad
#define WTILE_B (128*RBW)           // 18432
#define GEMM_SMEM (4*WTILE_B)       // 73728

template <int MODE>
__device__ __forceinline__ void gemm128_bf16_core(
    const __nv_bfloat16* __restrict__ A, const __nv_bfloat16* __restrict__ W,
    const float* __restrict__ resid, float* __restrict__ C32,
    __nv_bfloat16* __restrict__ C16,
    int by, int bx, char* gsm)
{
    const uint32_t sA = smem_u32(gsm);
    const uint32_t sB = sA + 2 * WTILE_B;
    int tid = threadIdx.x;
    int lane = tid & 31;
    int w = tid >> 5;
    int wm = (w >> 1) * 32;
    int wn = (w & 1) * 64;

    // cp.async tasks: 128 rows x 8 chunks of 16B = 1024 per matrix, 4 per thread
    const __nv_bfloat16* aP[4]; const __nv_bfloat16* bP[4];
    uint32_t stA[4], stB[4];
    #pragma unroll
    for (int l = 0; l < 4; l++) {
        int idx = tid + l * 256;
        int r = idx >> 3, c8 = idx & 7;
        aP[l] = A + (long)(by * 128 + r) * D_ + c8 * 8;
        bP[l] = W + (long)(bx * 128 + r) * D_ + c8 * 8;
        stA[l] = sA + r * RBW + c8 * 16;
        stB[l] = sB + r * RBW + c8 * 16;
    }

    float acc[2][8][4];
    #pragma unroll
    for (int mt = 0; mt < 2; mt++)
        #pragma unroll
        for (int nt = 0; nt < 8; nt++)
            #pragma unroll
            for (int j = 0; j < 4; j++) acc[mt][nt][j] = 0.f;

    const uint32_t aFragBase = sA + (wm + (lane & 15)) * RBW + (lane >> 4) * 16;
    const uint32_t bFragBase = sB +
        (wn + (lane & 7) + ((lane >> 4) << 3)) * RBW + ((lane >> 3) & 1) * 16;

    #pragma unroll
    for (int l = 0; l < 4; l++) { CP16(stA[l], aP[l]); CP16(stB[l], bP[l]); }
    CP_COMMIT();

    for (int kc = 0; kc < 16; kc++) {          // D/64
        int buf = kc & 1;
        if (kc + 1 < 16) {
            #pragma unroll
            for (int l = 0; l < 4; l++) {
                CP16(stA[l] + (buf ^ 1) * WTILE_B, aP[l] + (kc + 1) * 64);
                CP16(stB[l] + (buf ^ 1) * WTILE_B, bP[l] + (kc + 1) * 64);
            }
            CP_COMMIT();
            CP_WAIT(1);
        } else {
            CP_WAIT(0);
        }
        __syncthreads();

        uint32_t aBuf = aFragBase + buf * WTILE_B;
        uint32_t bBuf = bFragBase + buf * WTILE_B;

        #pragma unroll
        for (int ks = 0; ks < 4; ks++) {       // 4 k16-steps per BK=64
            uint32_t af[2][4];
            uint32_t bf[8][2];
            #pragma unroll
            for (int mt = 0; mt < 2; mt++)
                LDSM4(af[mt][0], af[mt][1], af[mt][2], af[mt][3],
                      aBuf + mt * 16 * RBW + ks * 32);
            #pragma unroll
            for (int ntp = 0; ntp < 4; ntp++) {
                uint32_t r0, r1, r2, r3;
                LDSM4(r0, r1, r2, r3, bBuf + ntp * 16 * RBW + ks * 32);
                bf[2 * ntp][0] = r0; bf[2 * ntp][1] = r1;
                bf[2 * ntp + 1][0] = r2; bf[2 * ntp + 1][1] = r3;
            }
            #pragma unroll
            for (int mt = 0; mt < 2; mt++)
                #pragma unroll
                for (int nt = 0; nt < 8; nt++)
                    MMA_BF16(acc[mt][nt], af[mt], bf[nt][0], bf[nt][1]);
        }
        __syncthreads();
    }

    #pragma unroll
    for (int mt = 0; mt < 2; mt++) {
        int row = by * 128 + wm + mt * 16 + (lane >> 2);
        int col = bx * 128 + wn + 2 * (lane & 3);
        #pragma unroll
        for (int nt = 0; nt < 8; nt++) {
            long i0 = (long)row * D_ + col + nt * 8;
            long i1 = i0 + 8 * D_;
            if (MODE == 2) {
                *(uint32_t*)&C16[i0] = pk_bf16x2(acc[mt][nt][0], acc[mt][nt][1]);
                *(uint32_t*)&C16[i1] = pk_bf16x2(acc[mt][nt][2], acc[mt][nt][3]);
            } else {
                float2 v0 = make_float2(acc[mt][nt][0], acc[mt][nt][1]);
                float2 v1 = make_float2(acc[mt][nt][2], acc[mt][nt][3]);
                if (MODE == 1) {
                    float2 r0 = *(const float2*)&resid[i0];
                    float2 r1 = *(const float2*)&resid[i1];
                    v0.x += r0.x; v0.y += r0.y;
                    v1.x += r1.x; v1.y += r1.y;
                }
                *(float2*)&C32[i0] = v0;
                *(float2*)&C32[i1] = v1;
            }
        }
    }
}

__global__ __launch_bounds__(256, 2) void gemm_qkv_kernel(
    const __nv_bfloat16* __restrict__ A,
    const __nv_bfloat16* __restrict__ Wq, const __nv_bfloat16* __restrict__ Wk,
    const __nv_bfloat16* __restrict__ Wv,
    float* __restrict__ hq, float* __restrict__ hk, __nv_bfloat16* __restrict__ v16)
{
    extern __shared__ __align__(16) char gsm[];
    int wsel = blockIdx.x >> 3;
    int bx = blockIdx.x & 7;
    if (wsel == 0)
        gemm128_bf16_core<0>(A, Wq, nullptr, hq, nullptr, blockIdx.y, bx, gsm);
    else if (wsel == 1)
        gemm128_bf16_core<0>(A, Wk, nullptr, hk, nullptr, blockIdx.y, bx, gsm);
    else
        gemm128_bf16_core<2>(A, Wv, nullptr, nullptr, v16, blockIdx.y, bx, gsm);
}

__global__ __launch_bounds__(256, 2) void gemm_o_kernel(
    const __nv_bfloat16* __restrict__ A, const __nv_bfloat16* __restrict__ W,
    const float* __restrict__ resid, float* __restrict__ C)
{
    extern __shared__ __align__(16) char gsm[];
    gemm128_bf16_core<1>(A, W, resid, C, nullptr, blockIdx.y, blockIdx.x, gsm);
}

// ---------------------------------------------------------------------------
// Fused LoRA: reads fp32 h (GEMM out), writes bf16 (h + 2*(h@A)@B^T)
// ---------------------------------------------------------------------------
#define LROWS 32
#define LORA_SMEM (2 * R_ * D_ * 4)

__global__ __launch_bounds__(256) void lora_fused_kernel(
    const float* __restrict__ hq, const float* __restrict__ hk,
    __nv_bfloat16* __restrict__ q16, __nv_bfloat16* __restrict__ k16,
    const float* __restrict__ lora)
{
    int which = blockIdx.y;
    const float* h = which ? hk : hq;
    __nv_bfloat16* g16 = which ? k16 : q16;
    int rowBase = blockIdx.x * LROWS;
    int b = rowBase / S_;
    const float* Ag = lora + ((long)which * B_ + b) * D_ * R_;
    const float* Bg = lora + ((long)(2 + which) * B_ + b) * D_ * R_;

    extern __shared__ __align__(16) float lsm[];
    float* As = lsm;
    float* Bs = lsm + R_ * D_;
    __shared__ float z[LROWS][R_];

    int tid = threadIdx.x;
    int lane = tid & 31, w = tid >> 5;

    #pragma unroll
    for (int k = 0; k < 4; k++) {
        int d = tid + k * 256;
        float4 a0 = *(const float4*)&Ag[d * R_];
        float4 a1 = *(const float4*)&Ag[d * R_ + 4];
        float4 b0 = *(const float4*)&Bg[d * R_];
        float4 b1 = *(const float4*)&Bg[d * R_ + 4];
        As[0*D_+d] = a0.x; As[1*D_+d] = a0.y; As[2*D_+d] = a0.z; As[3*D_+d] = a0.w;
        As[4*D_+d] = a1.x; As[5*D_+d] = a1.y; As[6*D_+d] = a1.z; As[7*D_+d] = a1.w;
        Bs[0*D_+d] = b0.x; Bs[1*D_+d] = b0.y; Bs[2*D_+d] = b0.z; Bs[3*D_+d] = b0.w;
        Bs[4*D_+d] = b1.x; Bs[5*D_+d] = b1.y; Bs[6*D_+d] = b1.z; Bs[7*D_+d] = b1.w;
    }
    __syncthreads();

    #pragma unroll
    for (int rr = 0; rr < 4; rr++) {
        int row = rowBase + w * 4 + rr;
        const float* hrow = h + (long)row * D_;
        float part[R_];
        #pragma unroll
        for (int r = 0; r < R_; r++) part[r] = 0.f;
        #pragma unroll
        for (int k = 0; k < 32; k++) {
            int d = lane + k * 32;
            float hv = hrow[d];
            #pragma unroll
            for (int r = 0; r < R_; r++) part[r] += hv * As[r * D_ + d];
        }
        #pragma unroll
        for (int r = 0; r < R_; r++)
            #pragma unroll
            for (int o = 16; o > 0; o >>= 1)
                part[r] += __shfl_xor_sync(FULLMASK, part[r], o);
        if (lane == 0)
            #pragma unroll
            for (int r = 0; r < R_; r++) z[w * 4 + rr][r] = part[r];
    }
    __syncthreads();

    #pragma unroll
    for (int k = 0; k < 2; k++) {
        int d0 = (tid + k * 256) * 2;
        float br0[R_], br1[R_];
        #pragma unroll
        for (int r = 0; r < R_; r++) { br0[r] = Bs[r * D_ + d0]; br1[r] = Bs[r * D_ + d0 + 1]; }
        for (int rr = 0; rr < LROWS; rr++) {
            long idx = (long)(rowBase + rr) * D_ + d0;
            float d0v = h[idx], d1v = h[idx + 1];
            float del0 = 0.f, del1 = 0.f;
            #pragma unroll
            for (int r = 0; r < R_; r++) {
                del0 += z[rr][r] * br0[r];
                del1 += z[rr][r] * br1[r];
            }
            *(uint32_t*)&g16[idx] = pk_bf16x2(d0v + 2.f * del0, d1v + 2.f * del1);
        }
    }
}

// ---------------------------------------------------------------------------
// Flash attention, bf16 mma, causal. Q tile 128, K/V tile 64.
// bf16 in, bf16 out. exp2-domain softmax. K/V cp.async 3-slot ring.
// ---------------------------------------------------------------------------
#define RB 144
#define KSLOT_B (64 * RB)
#define FQ_B  (128 * RB)
#define FLASH_SMEM (FQ_B + 3*KSLOT_B + 3*KSLOT_B + FQ_B)   // 92160

__global__ __launch_bounds__(256, 1) void flash_mma_kernel(
    const __nv_bfloat16* __restrict__ Q, const __nv_bfloat16* __restrict__ K,
    const __nv_bfloat16* __restrict__ V, __nv_bfloat16* __restrict__ O16)
{
    extern __shared__ __align__(16) char smc[];
    const uint32_t qsB = smem_u32(smc);
    const uint32_t ksB = qsB + FQ_B;
    const uint32_t vnB = ksB + 3 * KSLOT_B;
    const uint32_t psB = vnB + 3 * KSLOT_B;

    int qi = (gridDim.x - 1) - blockIdx.x;
    int h  = blockIdx.y;
    int b  = blockIdx.z;
    int tid = threadIdx.x;
    int lane = tid & 31;
    int w = tid >> 5;

    int cKp0 = tid >> 3, cC0 = tid & 7;
    int cKp1 = (tid + 256) >> 3, cC1 = tid & 7;

    const __nv_bfloat16* Qp = Q + (long)(b * S_ + qi * 128) * D_ + h * DH_;
    #pragma unroll
    for (int l = 0; l < 4; l++) {
        int idx = tid + l * 256;
        int q = idx >> 3, c8 = idx & 7;
        float4 v = *(const float4*)&Qp[(long)q * D_ + c8 * 8];
        asm volatile("st.shared.v4.b32 [%0], {%1,%2,%3,%4};" ::
            "r"(qsB + q * RB + c8 * 16),
            "r"(__float_as_uint(v.x)), "r"(__float_as_uint(v.y)),
            "r"(__float_as_uint(v.z)), "r"(__float_as_uint(v.w)) : "memory");
    }
    {
        const __nv_bfloat16* Kp = K + (long)(b * S_) * D_ + h * DH_;
        const __nv_bfloat16* Vp = V + (long)(b * S_) * D_ + h * DH_;
        CP16(ksB + cKp0 * RB + cC0 * 16, Kp + (long)cKp0 * D_ + cC0 * 8);
        CP16(ksB + cKp1 * RB + cC1 * 16, Kp + (long)cKp1 * D_ + cC1 * 8);
        CP16(vnB + cKp0 * RB + cC0 * 16, Vp + (long)cKp0 * D_ + cC0 * 8);
        CP16(vnB + cKp1 * RB + cC1 * 16, Vp + (long)cKp1 * D_ + cC1 * 8);
        CP_COMMIT();
    }

    float o[8][4];
    #pragma unroll
    for (int nt = 0; nt < 8; nt++)
        #pragma unroll
        for (int j = 0; j < 4; j++) o[nt][j] = 0.f;
    float m0 = -1e30f, m1 = -1e30f, l0 = 0.f, l1 = 0.f;

    const uint32_t kFragOff = ((lane & 7) + ((lane >> 4) << 3)) * RB + ((lane >> 3) & 1) * 16;
    const uint32_t vFragOff = ((lane & 7) + ((lane >> 3) & 1) * 8) * RB + (lane >> 4) * 16;
    const uint32_t pFragBase = psB + (w * 16 + (lane & 15)) * RB + (lane >> 4) * 16;
    const uint32_t pStoreBase = psB + (w * 16 + (lane >> 2)) * RB + (lane & 3) * 4;

    bool qfLoaded = false;
    uint32_t qf[4][4];

    const float SC = 0.125f * 1.44269504f;   // scale * log2(e)

    int ktmax = 2 * qi + 2;
    for (int kt = 0; kt < ktmax; kt++) {
        int slot = kt % 3;
        bool havenext = (kt + 1) < ktmax;

        if (havenext) {
            int ns = (kt + 1) % 3;
            const __nv_bfloat16* Kp = K + (long)(b * S_ + (kt + 1) * 64) * D_ + h * DH_;
            const __nv_bfloat16* Vp = V + (long)(b * S_ + (kt + 1) * 64) * D_ + h * DH_;
            uint32_t kd = ksB + ns * KSLOT_B, vd = vnB + ns * KSLOT_B;
            CP16(kd + cKp0 * RB + cC0 * 16, Kp + (long)cKp0 * D_ + cC0 * 8);
            CP16(kd + cKp1 * RB + cC1 * 16, Kp + (long)cKp1 * D_ + cC1 * 8);
            CP16(vd + cKp0 * RB + cC0 * 16, Vp + (long)cKp0 * D_ + cC0 * 8);
            CP16(vd + cKp1 * RB + cC1 * 16, Vp + (long)cKp1 * D_ + cC1 * 8);
            CP_COMMIT();
            CP_WAIT(1);
        } else {
            CP_WAIT(0);
        }
        __syncthreads();

        if (!qfLoaded) {
            uint32_t base = qsB + (w * 16 + (lane & 15)) * RB + (lane >> 4) * 16;
            #pragma unroll
            for (int ds = 0; ds < 4; ds++)
                LDSM4(qf[ds][0], qf[ds][1], qf[ds][2], qf[ds][3], base + ds * 32);
            qfLoaded = true;
        }

        bool active = (kt * 64) <= (qi * 128 + w * 16 + 15);
        if (active) {
            const uint32_t kBase = ksB + slot * KSLOT_B + kFragOff;
            const uint32_t vBase = vnB + slot * KSLOT_B + vFragOff;

            float s[8][4];
            #pragma unroll
            for (int nt = 0; nt < 8; nt++)
                #pragma unroll
                for (int j = 0; j < 4; j++) s[nt][j] = 0.f;

            #pragma unroll
            for (int ds = 0; ds < 4; ds++) {
                uint32_t bf[8][2];
                #pragma unroll
                for (int ntp = 0; ntp < 4; ntp++) {
                    uint32_t r0, r1, r2, r3;
                    LDSM4(r0, r1, r2, r3, kBase + ntp * 16 * RB + ds * 32);
                    bf[2 * ntp][0] = r0; bf[2 * ntp][1] = r1;
                    bf[2 * ntp + 1][0] = r2; bf[2 * ntp + 1][1] = r3;
                }
                #pragma unroll
                for (int nt = 0; nt < 8; nt++)
                    MMA_BF16(s[nt], qf[ds], bf[nt][0], bf[nt][1]);
            }

            bool needmask = (kt * 64 + 63) > (qi * 128 + w * 16);
            int row0 = qi * 128 + w * 16 + (lane >> 2);
            float ml0 = -1e30f, ml1 = -1e30f;
            #pragma unroll
            for (int nt = 0; nt < 8; nt++) {
                #pragma unroll
                for (int j = 0; j < 4; j++) {
                    float v = s[nt][j] * SC;     // exp2 domain
                    if (needmask) {
                        int col = kt * 64 + nt * 8 + 2 * (lane & 3) + (j & 1);
                        int row = row0 + ((j >> 1) << 3);
                        if (col > row) v = -1e30f;
                    }
                    s[nt][j] = v;
                }
                ml0 = fmaxf(ml0, fmaxf(s[nt][0], s[nt][1]));
                ml1 = fmaxf(ml1, fmaxf(s[nt][2], s[nt][3]));
            }
            ml0 = fmaxf(ml0, __shfl_xor_sync(FULLMASK, ml0, 1));
            ml0 = fmaxf(ml0, __shfl_xor_sync(FULLMASK, ml0, 2));
            ml1 = fmaxf(ml1, __shfl_xor_sync(FULLMASK, ml1, 1));
            ml1 = fmaxf(ml1, __shfl_xor_sync(FULLMASK, ml1, 2));
            float mn0 = fmaxf(m0, ml0), mn1 = fmaxf(m1, ml1);
            float a0 = exp2f(m0 - mn0), a1 = exp2f(m1 - mn1);
            float sum0 = 0.f, sum1 = 0.f;
            #pragma unroll
            for (int nt = 0; nt < 8; nt++) {
                s[nt][0] = rt_bf16(exp2f(s[nt][0] - mn0));
                s[nt][1] = rt_bf16(exp2f(s[nt][1] - mn0));
                s[nt][2] = rt_bf16(exp2f(s[nt][2] - mn1));
                s[nt][3] = rt_bf16(exp2f(s[nt][3] - mn1));
                sum0 += s[nt][0] + s[nt][1];
                sum1 += s[nt][2] + s[nt][3];
            }
            sum0 += __shfl_xor_sync(FULLMASK, sum0, 1);
            sum0 += __shfl_xor_sync(FULLMASK, sum0, 2);
            sum1 += __shfl_xor_sync(FULLMASK, sum1, 1);
            sum1 += __shfl_xor_sync(FULLMASK, sum1, 2);
            l0 = l0 * a0 + sum0;
            l1 = l1 * a1 + sum1;
            m0 = mn0; m1 = mn1;
            #pragma unroll
            for (int nt = 0; nt < 8; nt++) {
                o[nt][0] *= a0; o[nt][1] *= a0;
                o[nt][2] *= a1; o[nt][3] *= a1;
            }

            #pragma unroll
            for (int nt = 0; nt < 8; nt++) {
                asm volatile("st.shared.b32 [%0], %1;" ::
                    "r"(pStoreBase + nt * 16), "r"(pk_bf16x2(s[nt][0], s[nt][1])) : "memory");
                asm volatile("st.shared.b32 [%0], %1;" ::
                    "r"(pStoreBase + 8 * RB + nt * 16), "r"(pk_bf16x2(s[nt][2], s[nt][3])) : "memory");
            }
            __syncwarp();

            #pragma unroll
            for (int ks = 0; ks < 4; ks++) {
                uint32_t pf[4];
                LDSM4(pf[0], pf[1], pf[2], pf[3], pFragBase + ks * 32);
                uint32_t vf[8][2];
                #pragma unroll
                for (int ntp = 0; ntp < 4; ntp++) {
                    uint32_t r0, r1, r2, r3;
                    LDSM4T(r0, r1, r2, r3, vBase + ks * 16 * RB + ntp * 32);
                    vf[2 * ntp][0] = r0; vf[2 * ntp][1] = r1;
                    vf[2 * ntp + 1][0] = r2; vf[2 * ntp + 1][1] = r3;
                }
                #pragma unroll
                for (int nt = 0; nt < 8; nt++)
                    MMA_BF16(o[nt], pf, vf[nt][0], vf[nt][1]);
            }
        }
    }

    // normalize + write bf16
    float inv0 = 1.f / l0, inv1 = 1.f / l1;
    int row0 = qi * 128 + w * 16 + (lane >> 2);
    long base0 = (long)(b * S_ + row0) * D_ + h * DH_ + 2 * (lane & 3);
    long base1 = base0 + 8 * D_;
    #pragma unroll
    for (int nt = 0; nt < 8; nt++) {
        *(uint32_t*)&O16[base0 + nt * 8] = pk_bf16x2(o[nt][0] * inv0, o[nt][1] * inv0);
        *(uint32_t*)&O16[base1 + nt * 8] = pk_bf16x2(o[nt][2] * inv1, o[nt][3] * inv1);
    }
}

// ---------------------------------------------------------------------------
// Launch
// ---------------------------------------------------------------------------
extern "C" void kernel_launch(void* const* d_in, const int* in_sizes, int n_in,
                              void* d_out, int out_size)
{
    const float* hidden = (const float*)d_in[0];
    // d_in[1] = attention_mask: causal tril -> handled analytically
    const float* lora   = (const float*)d_in[2];   // [4, B, D, R]
    const float* ln_w   = (const float*)d_in[3];
    const float* Wq     = (const float*)d_in[4];
    const float* Wk     = (const float*)d_in[5];
    const float* Wv     = (const float*)d_in[6];
    const float* Wo     = (const float*)d_in[7];
    float* out = (float*)d_out;

    float *hq, *hk;
    __nv_bfloat16 *x16, *q16, *k16, *v16, *attn16, *wq16, *wk16, *wv16, *wo16;
    cudaGetSymbolAddress((void**)&x16,    g_x16);
    cudaGetSymbolAddress((void**)&hq,     g_hq);
    cudaGetSymbolAddress((void**)&hk,     g_hk);
    cudaGetSymbolAddress((void**)&q16,    g_q16);
    cudaGetSymbolAddress((void**)&k16,    g_k16);
    cudaGetSymbolAddress((void**)&v16,    g_v16);
    cudaGetSymbolAddress((void**)&attn16, g_attn16);
    cudaGetSymbolAddress((void**)&wq16,   g_wq16);
    cudaGetSymbolAddress((void**)&wk16,   g_wk16);
    cudaGetSymbolAddress((void**)&wv16,   g_wv16);
    cudaGetSymbolAddress((void**)&wo16,   g_wo16);

    cudaFuncSetAttribute(gemm_qkv_kernel, cudaFuncAttributeMaxDynamicSharedMemorySize, GEMM_SMEM);
    cudaFuncSetAttribute(gemm_o_kernel,   cudaFuncAttributeMaxDynamicSharedMemorySize, GEMM_SMEM);
    cudaFuncSetAttribute(flash_mma_kernel, cudaFuncAttributeMaxDynamicSharedMemorySize, FLASH_SMEM);
    cudaFuncSetAttribute(lora_fused_kernel, cudaFuncAttributeMaxDynamicSharedMemorySize, LORA_SMEM);

    // 0. Weight conversion fp32 -> bf16 (grid: 512 x 4; 8 elems/thread)
    dim3 gw(D_ * D_ / (256 * 8), 4);
    wconv_kernel<<<gw, 256>>>(Wq, Wk, Wv, Wo, wq16, wk16, wv16, wo16);

    // 1. RMSNorm -> bf16
    rmsnorm_kernel<<<M_, 256>>>(hidden, ln_w, x16);

    // 2. Fused QKV projections (bf16; q/k out fp32 for LoRA, V out bf16)
    dim3 gq(24, M_ / 128);
    gemm_qkv_kernel<<<gq, 256, GEMM_SMEM>>>(x16, wq16, wk16, wv16, hq, hk, v16);

    // 3. Fused LoRA deltas -> bf16 q/k
    dim3 gl(M_ / LROWS, 2);
    lora_fused_kernel<<<gl, 256, LORA_SMEM>>>(hq, hk, q16, k16, lora);

    // 4. Causal flash attention (bf16 in/out)
    dim3 fg(S_ / 128, H_, B_);
    flash_mma_kernel<<<fg, 256, FLASH_SMEM>>>(q16, k16, v16, attn16);

    // 5. Output projection + residual (bf16 in, fp32 out)
    dim3 go(8, M_ / 128);
    gemm_o_kernel<<<go, 256, GEMM_SMEM>>>(attn16, wo16, hidden, out);
}

// round 11
// speedup vs baseline: 6.0677x; 1.0078x over previous
#include <cuda_runtime.h>
#include <cuda_bf16.h>
#include <cstdint>
#include <math.h>

// Problem constants
#define B_  2
#define S_  2048
#define D_  1024
#define H_  16
#define DH_ 64
#define R_  8
#define M_  (B_*S_)          // 4096 rows

// Scratch (device globals; no allocation allowed)
__device__ __nv_bfloat16 g_x16[M_*D_];
__device__ float g_hq[M_*D_];
__device__ float g_hk[M_*D_];
__device__ float g_z[2*M_*R_];
__device__ __nv_bfloat16 g_q16[M_*D_];
__device__ __nv_bfloat16 g_k16[M_*D_];
__device__ __nv_bfloat16 g_v16[M_*D_];
__device__ __nv_bfloat16 g_attn16[M_*D_];
__device__ __nv_bfloat16 g_wq16[D_*D_];
__device__ __nv_bfloat16 g_wk16[D_*D_];
__device__ __nv_bfloat16 g_wv16[D_*D_];
__device__ __nv_bfloat16 g_wo16[D_*D_];

#define FULLMASK 0xffffffffu

// ===========================================================================
// PTX helpers
// ===========================================================================
__device__ __forceinline__ uint32_t smem_u32(const void* p) {
    uint32_t a;
    asm("{ .reg .u64 t; cvta.to.shared.u64 t, %1; cvt.u32.u64 %0, t; }"
        : "=r"(a) : "l"(p));
    return a;
}

#define LDSM4(R0,R1,R2,R3,ADDR) \
    asm volatile("ldmatrix.sync.aligned.m8n8.x4.shared.b16 {%0,%1,%2,%3}, [%4];" \
        : "=r"(R0), "=r"(R1), "=r"(R2), "=r"(R3) : "r"(ADDR))

#define LDSM4T(R0,R1,R2,R3,ADDR) \
    asm volatile("ldmatrix.sync.aligned.m8n8.x4.trans.shared.b16 {%0,%1,%2,%3}, [%4];" \
        : "=r"(R0), "=r"(R1), "=r"(R2), "=r"(R3) : "r"(ADDR))

#define MMA_BF16(C, A, B0, B1) \
    asm volatile("mma.sync.aligned.m16n8k16.row.col.f32.bf16.bf16.f32 " \
        "{%0,%1,%2,%3}, {%4,%5,%6,%7}, {%8,%9}, {%0,%1,%2,%3};" \
        : "+f"((C)[0]), "+f"((C)[1]), "+f"((C)[2]), "+f"((C)[3]) \
        : "r"((A)[0]), "r"((A)[1]), "r"((A)[2]), "r"((A)[3]), "r"(B0), "r"(B1))

#define CP16(DST, SRC) \
    asm volatile("cp.async.cg.shared.global [%0], [%1], 16;" :: "r"(DST), "l"(SRC))
#define CP_COMMIT() asm volatile("cp.async.commit_group;" ::: "memory")
#define CP_WAIT(N)  asm volatile("cp.async.wait_group %0;" :: "n"(N) : "memory")

__device__ __forceinline__ uint32_t pk_bf16x2(float a, float b) {
    __nv_bfloat162 t = __floats2bfloat162_rn(a, b);
    return *reinterpret_cast<uint32_t*>(&t);
}
__device__ __forceinline__ float rt_bf16(float a) {
    return __bfloat162float(__float2bfloat16(a));
}

// ---------------------------------------------------------------------------
// Prep: RMSNorm (blocks 0..M_-1) + weight conversion (blocks M_..M_+2047)
// ---------------------------------------------------------------------------
__global__ __launch_bounds__(256) void prep_kernel(
    const float* __restrict__ hs, const float* __restrict__ w,
    const float* __restrict__ Wq, const float* __restrict__ Wk,
    const float* __restrict__ Wv, const float* __restrict__ Wo,
    __nv_bfloat16* __restrict__ x16,
    __nv_bfloat16* __restrict__ wq16, __nv_bfloat16* __restrict__ wk16,
    __nv_bfloat16* __restrict__ wv16, __nv_bfloat16* __restrict__ wo16)
{
    int t = threadIdx.x;
    if (blockIdx.x < M_) {
        int row = blockIdx.x;
        const float* x = hs + (long)row * D_;
        float4 v = *(const float4*)&x[t * 4];
        float ss = v.x*v.x + v.y*v.y + v.z*v.z + v.w*v.w;
        #pragma unroll
        for (int o = 16; o > 0; o >>= 1) ss += __shfl_xor_sync(FULLMASK, ss, o);
        __shared__ float red[8];
        if ((t & 31) == 0) red[t >> 5] = ss;
        __syncthreads();
        __shared__ float s_inv;
        if (t == 0) {
            float s = 0.f;
            #pragma unroll
            for (int i = 0; i < 8; i++) s += red[i];
            s_inv = rsqrtf(s / (float)D_ + 1e-5f);
        }
        __syncthreads();
        float inv = s_inv;
        float4 wv4 = *(const float4*)&w[t * 4];
        uint2 o2;
        o2.x = pk_bf16x2(v.x * inv * wv4.x, v.y * inv * wv4.y);
        o2.y = pk_bf16x2(v.z * inv * wv4.z, v.w * inv * wv4.w);
        *(uint2*)&x16[(long)row * D_ + t * 4] = o2;
    } else {
        int bid2 = blockIdx.x - M_;          // 0..2047
        int sel = bid2 >> 9;                 // 512 blocks per matrix
        int ib  = bid2 & 511;
        const float* src = (sel == 0) ? Wq : (sel == 1) ? Wk : (sel == 2) ? Wv : Wo;
        __nv_bfloat16* dst = (sel == 0) ? wq16 : (sel == 1) ? wk16 : (sel == 2) ? wv16 : wo16;
        long idx = ((long)ib * 256 + t) * 8;
        float4 a = *(const float4*)&src[idx];
        float4 b = *(const float4*)&src[idx + 4];
        uint4 u;
        u.x = pk_bf16x2(a.x, a.y); u.y = pk_bf16x2(a.z, a.w);
        u.z = pk_bf16x2(b.x, b.y); u.w = pk_bf16x2(b.z, b.w);
        *(uint4*)&dst[idx] = u;
    }
}

// ---------------------------------------------------------------------------
// bf16 GEMM core: C[128x128] = A[*,1024] @ W[*,1024]^T.
// BK=64 bf16, double-buffered cp.async, 8 warps x (32x64) warp tiles.
// MODE: 0 = fp32 out, 1 = fp32 + residual, 2 = bf16 out
// ---------------------------------------------------------------------------
#define RBW 144                     // 64 bf16 = 128B data + 16B pad
#define WTILE_B (128*RBW)           // 18432
#define GEMM_SMEM (4*WTILE_B)       // 73728

template <int MODE>
__device__ __forceinline__ void gemm128_bf16_core(
    const __nv_bfloat16* __restrict__ A, const __nv_bfloat16* __restrict__ W,
    const float* __restrict__ resid, float* __restrict__ C32,
    __nv_bfloat16* __restrict__ C16,
    int by, int bx, char* gsm)
{
    const uint32_t sA = smem_u32(gsm);
    const uint32_t sB = sA + 2 * WTILE_B;
    int tid = threadIdx.x;
    int lane = tid & 31;
    int w = tid >> 5;
    int wm = (w >> 1) * 32;
    int wn = (w & 1) * 64;

    // cp.async tasks: 128 rows x 8 chunks of 16B = 1024 per matrix, 4 per thread
    const __nv_bfloat16* aP[4]; const __nv_bfloat16* bP[4];
    uint32_t stA[4], stB[4];
    #pragma unroll
    for (int l = 0; l < 4; l++) {
        int idx = tid + l * 256;
        int r = idx >> 3, c8 = idx & 7;
        aP[l] = A + (long)(by * 128 + r) * D_ + c8 * 8;
        bP[l] = W + (long)(bx * 128 + r) * D_ + c8 * 8;
        stA[l] = sA + r * RBW + c8 * 16;
        stB[l] = sB + r * RBW + c8 * 16;
    }

    float acc[2][8][4];
    #pragma unroll
    for (int mt = 0; mt < 2; mt++)
        #pragma unroll
        for (int nt = 0; nt < 8; nt++)
            #pragma unroll
            for (int j = 0; j < 4; j++) acc[mt][nt][j] = 0.f;

    const uint32_t aFragBase = sA + (wm + (lane & 15)) * RBW + (lane >> 4) * 16;
    const uint32_t bFragBase = sB +
        (wn + (lane & 7) + ((lane >> 4) << 3)) * RBW + ((lane >> 3) & 1) * 16;

    #pragma unroll
    for (int l = 0; l < 4; l++) { CP16(stA[l], aP[l]); CP16(stB[l], bP[l]); }
    CP_COMMIT();

    for (int kc = 0; kc < 16; kc++) {          // D/64
        int buf = kc & 1;
        if (kc + 1 < 16) {
            #pragma unroll
            for (int l = 0; l < 4; l++) {
                CP16(stA[l] + (buf ^ 1) * WTILE_B, aP[l] + (kc + 1) * 64);
                CP16(stB[l] + (buf ^ 1) * WTILE_B, bP[l] + (kc + 1) * 64);
            }
            CP_COMMIT();
            CP_WAIT(1);
        } else {
            CP_WAIT(0);
        }
        __syncthreads();

        uint32_t aBuf = aFragBase + buf * WTILE_B;
        uint32_t bBuf = bFragBase + buf * WTILE_B;

        #pragma unroll
        for (int ks = 0; ks < 4; ks++) {       // 4 k16-steps per BK=64
            uint32_t af[2][4];
            uint32_t bf[8][2];
            #pragma unroll
            for (int mt = 0; mt < 2; mt++)
                LDSM4(af[mt][0], af[mt][1], af[mt][2], af[mt][3],
                      aBuf + mt * 16 * RBW + ks * 32);
            #pragma unroll
            for (int ntp = 0; ntp < 4; ntp++) {
                uint32_t r0, r1, r2, r3;
                LDSM4(r0, r1, r2, r3, bBuf + ntp * 16 * RBW + ks * 32);
                bf[2 * ntp][0] = r0; bf[2 * ntp][1] = r1;
                bf[2 * ntp + 1][0] = r2; bf[2 * ntp + 1][1] = r3;
            }
            #pragma unroll
            for (int mt = 0; mt < 2; mt++)
                #pragma unroll
                for (int nt = 0; nt < 8; nt++)
                    MMA_BF16(acc[mt][nt], af[mt], bf[nt][0], bf[nt][1]);
        }
        __syncthreads();
    }

    #pragma unroll
    for (int mt = 0; mt < 2; mt++) {
        int row = by * 128 + wm + mt * 16 + (lane >> 2);
        int col = bx * 128 + wn + 2 * (lane & 3);
        #pragma unroll
        for (int nt = 0; nt < 8; nt++) {
            long i0 = (long)row * D_ + col + nt * 8;
            long i1 = i0 + 8 * D_;
            if (MODE == 2) {
                *(uint32_t*)&C16[i0] = pk_bf16x2(acc[mt][nt][0], acc[mt][nt][1]);
                *(uint32_t*)&C16[i1] = pk_bf16x2(acc[mt][nt][2], acc[mt][nt][3]);
            } else {
                float2 v0 = make_float2(acc[mt][nt][0], acc[mt][nt][1]);
                float2 v1 = make_float2(acc[mt][nt][2], acc[mt][nt][3]);
                if (MODE == 1) {
                    float2 r0 = *(const float2*)&resid[i0];
                    float2 r1 = *(const float2*)&resid[i1];
                    v0.x += r0.x; v0.y += r0.y;
                    v1.x += r1.x; v1.y += r1.y;
                }
                *(float2*)&C32[i0] = v0;
                *(float2*)&C32[i1] = v1;
            }
        }
    }
}

__global__ __launch_bounds__(256, 2) void gemm_qkv_kernel(
    const __nv_bfloat16* __restrict__ A,
    const __nv_bfloat16* __restrict__ Wq, const __nv_bfloat16* __restrict__ Wk,
    const __nv_bfloat16* __restrict__ Wv,
    float* __restrict__ hq, float* __restrict__ hk, __nv_bfloat16* __restrict__ v16)
{
    extern __shared__ __align__(16) char gsm[];
    int wsel = blockIdx.x >> 3;
    int bx = blockIdx.x & 7;
    if (wsel == 0)
        gemm128_bf16_core<0>(A, Wq, nullptr, hq, nullptr, blockIdx.y, bx, gsm);
    else if (wsel == 1)
        gemm128_bf16_core<0>(A, Wk, nullptr, hk, nullptr, blockIdx.y, bx, gsm);
    else
        gemm128_bf16_core<2>(A, Wv, nullptr, nullptr, v16, blockIdx.y, bx, gsm);
}

__global__ __launch_bounds__(256, 2) void gemm_o_kernel(
    const __nv_bfloat16* __restrict__ A, const __nv_bfloat16* __restrict__ W,
    const float* __restrict__ resid, float* __restrict__ C)
{
    extern __shared__ __align__(16) char gsm[];
    gemm128_bf16_core<1>(A, W, resid, C, nullptr, blockIdx.y, blockIdx.x, gsm);
}

// ---------------------------------------------------------------------------
// LoRA phase 1: z[row][:] = h[row] @ A   (grid: (M_/32, 2), 256 threads)
// A staged transposed in 32KB smem; warp handles 4 rows.
// ---------------------------------------------------------------------------
__global__ __launch_bounds__(256) void lora_z_kernel(
    const float* __restrict__ hq, const float* __restrict__ hk,
    const float* __restrict__ lora, float* __restrict__ z)
{
    int which = blockIdx.y;
    const float* h = which ? hk : hq;
    int rowBase = blockIdx.x * 32;
    int b = rowBase / S_;
    const float* Ag = lora + ((long)which * B_ + b) * D_ * R_;

    __shared__ float As[R_ * D_];    // 32KB, [r][d]
    int tid = threadIdx.x;
    int lane = tid & 31, w = tid >> 5;

    #pragma unroll
    for (int k = 0; k < 4; k++) {
        int d = tid + k * 256;
        float4 a0 = *(const float4*)&Ag[d * R_];
        float4 a1 = *(const float4*)&Ag[d * R_ + 4];
        As[0*D_+d] = a0.x; As[1*D_+d] = a0.y; As[2*D_+d] = a0.z; As[3*D_+d] = a0.w;
        As[4*D_+d] = a1.x; As[5*D_+d] = a1.y; As[6*D_+d] = a1.z; As[7*D_+d] = a1.w;
    }
    __syncthreads();

    #pragma unroll
    for (int rr = 0; rr < 4; rr++) {
        int row = rowBase + w * 4 + rr;
        const float* hrow = h + (long)row * D_;
        float part[R_];
        #pragma unroll
        for (int r = 0; r < R_; r++) part[r] = 0.f;
        #pragma unroll
        for (int k = 0; k < 32; k++) {
            int d = lane + k * 32;
            float hv = hrow[d];
            #pragma unroll
            for (int r = 0; r < R_; r++) part[r] += hv * As[r * D_ + d];
        }
        #pragma unroll
        for (int r = 0; r < R_; r++)
            #pragma unroll
            for (int o = 16; o > 0; o >>= 1)
                part[r] += __shfl_xor_sync(FULLMASK, part[r], o);
        if (lane == 0) {
            #pragma unroll
            for (int r = 0; r < R_; r++)
                z[((long)which * M_ + row) * R_ + r] = part[r];
        }
    }
}

// ---------------------------------------------------------------------------
// LoRA phase 2: g16[row][d] = bf16(h[row][d] + 2 * sum_r z[row][r] * B[d][r])
// Grid (M_/32, 2), 256 threads. Thread owns 4 consecutive d's; streams 32 rows.
// ---------------------------------------------------------------------------
__global__ __launch_bounds__(256) void lora_apply_kernel(
    const float* __restrict__ hq, const float* __restrict__ hk,
    __nv_bfloat16* __restrict__ q16, __nv_bfloat16* __restrict__ k16,
    const float* __restrict__ lora, const float* __restrict__ z)
{
    int which = blockIdx.y;
    const float* h = which ? hk : hq;
    __nv_bfloat16* g16 = which ? k16 : q16;
    int rowBase = blockIdx.x * 32;
    int b = rowBase / S_;
    const float* Bg = lora + ((long)(2 + which) * B_ + b) * D_ * R_;

    __shared__ float zs[32][R_];
    int tid = threadIdx.x;
    zs[tid >> 3][tid & 7] = z[((long)which * M_ + rowBase + (tid >> 3)) * R_ + (tid & 7)];
    __syncthreads();

    int d0 = tid * 4;
    float br[4][R_];
    #pragma unroll
    for (int j = 0; j < 4; j++) {
        float4 b0 = *(const float4*)&Bg[(d0 + j) * R_];
        float4 b1 = *(const float4*)&Bg[(d0 + j) * R_ + 4];
        br[j][0] = b0.x; br[j][1] = b0.y; br[j][2] = b0.z; br[j][3] = b0.w;
        br[j][4] = b1.x; br[j][5] = b1.y; br[j][6] = b1.z; br[j][7] = b1.w;
    }

    #pragma unroll 4
    for (int rr = 0; rr < 32; rr++) {
        long idx = (long)(rowBase + rr) * D_ + d0;
        float4 hv = *(const float4*)&h[idx];
        float del[4];
        #pragma unroll
        for (int j = 0; j < 4; j++) {
            float s = 0.f;
            #pragma unroll
            for (int r = 0; r < R_; r++) s += zs[rr][r] * br[j][r];
            del[j] = s;
        }
        uint2 o2;
        o2.x = pk_bf16x2(hv.x + 2.f * del[0], hv.y + 2.f * del[1]);
        o2.y = pk_bf16x2(hv.z + 2.f * del[2], hv.w + 2.f * del[3]);
        *(uint2*)&g16[idx] = o2;
    }
}

// ---------------------------------------------------------------------------
// Flash attention, bf16 mma, causal. Q tile 128, K/V tile 64.
// bf16 in, bf16 out. exp2-domain softmax. K/V cp.async 3-slot ring.
// ---------------------------------------------------------------------------
#define RB 144
#define KSLOT_B (64 * RB)
#define FQ_B  (128 * RB)
#define FLASH_SMEM (FQ_B + 3*KSLOT_B + 3*KSLOT_B + FQ_B)   // 92160

__global__ __launch_bounds__(256, 1) void flash_mma_kernel(
    const __nv_bfloat16* __restrict__ Q, const __nv_bfloat16* __restrict__ K,
    const __nv_bfloat16* __restrict__ V, __nv_bfloat16* __restrict__ O16)
{
    extern __shared__ __align__(16) char smc[];
    const uint32_t qsB = smem_u32(smc);
    const uint32_t ksB = qsB + FQ_B;
    const uint32_t vnB = ksB + 3 * KSLOT_B;
    const uint32_t psB = vnB + 3 * KSLOT_B;

    int qi = (gridDim.x - 1) - blockIdx.x;
    int h  = blockIdx.y;
    int b  = blockIdx.z;
    int tid = threadIdx.x;
    int lane = tid & 31;
    int w = tid >> 5;

    int cKp0 = tid >> 3, cC0 = tid & 7;
    int cKp1 = (tid + 256) >> 3, cC1 = tid & 7;

    const __nv_bfloat16* Qp = Q + (long)(b * S_ + qi * 128) * D_ + h * DH_;
    #pragma unroll
    for (int l = 0; l < 4; l++) {
        int idx = tid + l * 256;
        int q = idx >> 3, c8 = idx & 7;
        float4 v = *(const float4*)&Qp[(long)q * D_ + c8 * 8];
        asm volatile("st.shared.v4.b32 [%0], {%1,%2,%3,%4};" ::
            "r"(qsB + q * RB + c8 * 16),
            "r"(__float_as_uint(v.x)), "r"(__float_as_uint(v.y)),
            "r"(__float_as_uint(v.z)), "r"(__float_as_uint(v.w)) : "memory");
    }
    {
        const __nv_bfloat16* Kp = K + (long)(b * S_) * D_ + h * DH_;
        const __nv_bfloat16* Vp = V + (long)(b * S_) * D_ + h * DH_;
        CP16(ksB + cKp0 * RB + cC0 * 16, Kp + (long)cKp0 * D_ + cC0 * 8);
        CP16(ksB + cKp1 * RB + cC1 * 16, Kp + (long)cKp1 * D_ + cC1 * 8);
        CP16(vnB + cKp0 * RB + cC0 * 16, Vp + (long)cKp0 * D_ + cC0 * 8);
        CP16(vnB + cKp1 * RB + cC1 * 16, Vp + (long)cKp1 * D_ + cC1 * 8);
        CP_COMMIT();
    }

    float o[8][4];
    #pragma unroll
    for (int nt = 0; nt < 8; nt++)
        #pragma unroll
        for (int j = 0; j < 4; j++) o[nt][j] = 0.f;
    float m0 = -1e30f, m1 = -1e30f, l0 = 0.f, l1 = 0.f;

    const uint32_t kFragOff = ((lane & 7) + ((lane >> 4) << 3)) * RB + ((lane >> 3) & 1) * 16;
    const uint32_t vFragOff = ((lane & 7) + ((lane >> 3) & 1) * 8) * RB + (lane >> 4) * 16;
    const uint32_t pFragBase = psB + (w * 16 + (lane & 15)) * RB + (lane >> 4) * 16;
    const uint32_t pStoreBase = psB + (w * 16 + (lane >> 2)) * RB + (lane & 3) * 4;

    bool qfLoaded = false;
    uint32_t qf[4][4];

    const float SC = 0.125f * 1.44269504f;   // scale * log2(e)

    int ktmax = 2 * qi + 2;
    for (int kt = 0; kt < ktmax; kt++) {
        int slot = kt % 3;
        bool havenext = (kt + 1) < ktmax;

        if (havenext) {
            int ns = (kt + 1) % 3;
            const __nv_bfloat16* Kp = K + (long)(b * S_ + (kt + 1) * 64) * D_ + h * DH_;
            const __nv_bfloat16* Vp = V + (long)(b * S_ + (kt + 1) * 64) * D_ + h * DH_;
            uint32_t kd = ksB + ns * KSLOT_B, vd = vnB + ns * KSLOT_B;
            CP16(kd + cKp0 * RB + cC0 * 16, Kp + (long)cKp0 * D_ + cC0 * 8);
            CP16(kd + cKp1 * RB + cC1 * 16, Kp + (long)cKp1 * D_ + cC1 * 8);
            CP16(vd + cKp0 * RB + cC0 * 16, Vp + (long)cKp0 * D_ + cC0 * 8);
            CP16(vd + cKp1 * RB + cC1 * 16, Vp + (long)cKp1 * D_ + cC1 * 8);
            CP_COMMIT();
            CP_WAIT(1);
        } else {
            CP_WAIT(0);
        }
        __syncthreads();

        if (!qfLoaded) {
            uint32_t base = qsB + (w * 16 + (lane & 15)) * RB + (lane >> 4) * 16;
            #pragma unroll
            for (int ds = 0; ds < 4; ds++)
                LDSM4(qf[ds][0], qf[ds][1], qf[ds][2], qf[ds][3], base + ds * 32);
            qfLoaded = true;
        }

        bool active = (kt * 64) <= (qi * 128 + w * 16 + 15);
        if (active) {
            const uint32_t kBase = ksB + slot * KSLOT_B + kFragOff;
            const uint32_t vBase = vnB + slot * KSLOT_B + vFragOff;

            float s[8][4];
            #pragma unroll
            for (int nt = 0; nt < 8; nt++)
                #pragma unroll
                for (int j = 0; j < 4; j++) s[nt][j] = 0.f;

            #pragma unroll
            for (int ds = 0; ds < 4; ds++) {
                uint32_t bf[8][2];
                #pragma unroll
                for (int ntp = 0; ntp < 4; ntp++) {
                    uint32_t r0, r1, r2, r3;
                    LDSM4(r0, r1, r2, r3, kBase + ntp * 16 * RB + ds * 32);
                    bf[2 * ntp][0] = r0; bf[2 * ntp][1] = r1;
                    bf[2 * ntp + 1][0] = r2; bf[2 * ntp + 1][1] = r3;
                }
                #pragma unroll
                for (int nt = 0; nt < 8; nt++)
                    MMA_BF16(s[nt], qf[ds], bf[nt][0], bf[nt][1]);
            }

            bool needmask = (kt * 64 + 63) > (qi * 128 + w * 16);
            int row0 = qi * 128 + w * 16 + (lane >> 2);
            float ml0 = -1e30f, ml1 = -1e30f;
            #pragma unroll
            for (int nt = 0; nt < 8; nt++) {
                #pragma unroll
                for (int j = 0; j < 4; j++) {
                    float v = s[nt][j] * SC;     // exp2 domain
                    if (needmask) {
                        int col = kt * 64 + nt * 8 + 2 * (lane & 3) + (j & 1);
                        int row = row0 + ((j >> 1) << 3);
                        if (col > row) v = -1e30f;
                    }
                    s[nt][j] = v;
                }
                ml0 = fmaxf(ml0, fmaxf(s[nt][0], s[nt][1]));
                ml1 = fmaxf(ml1, fmaxf(s[nt][2], s[nt][3]));
            }
            ml0 = fmaxf(ml0, __shfl_xor_sync(FULLMASK, ml0, 1));
            ml0 = fmaxf(ml0, __shfl_xor_sync(FULLMASK, ml0, 2));
            ml1 = fmaxf(ml1, __shfl_xor_sync(FULLMASK, ml1, 1));
            ml1 = fmaxf(ml1, __shfl_xor_sync(FULLMASK, ml1, 2));
            float mn0 = fmaxf(m0, ml0), mn1 = fmaxf(m1, ml1);
            float a0 = exp2f(m0 - mn0), a1 = exp2f(m1 - mn1);
            float sum0 = 0.f, sum1 = 0.f;
            #pragma unroll
            for (int nt = 0; nt < 8; nt++) {
                s[nt][0] = rt_bf16(exp2f(s[nt][0] - mn0));
                s[nt][1] = rt_bf16(exp2f(s[nt][1] - mn0));
                s[nt][2] = rt_bf16(exp2f(s[nt][2] - mn1));
                s[nt][3] = rt_bf16(exp2f(s[nt][3] - mn1));
                sum0 += s[nt][0] + s[nt][1];
                sum1 += s[nt][2] + s[nt][3];
            }
            sum0 += __shfl_xor_sync(FULLMASK, sum0, 1);
            sum0 += __shfl_xor_sync(FULLMASK, sum0, 2);
            sum1 += __shfl_xor_sync(FULLMASK, sum1, 1);
            sum1 += __shfl_xor_sync(FULLMASK, sum1, 2);
            l0 = l0 * a0 + sum0;
            l1 = l1 * a1 + sum1;
            m0 = mn0; m1 = mn1;
            #pragma unroll
            for (int nt = 0; nt < 8; nt++) {
                o[nt][0] *= a0; o[nt][1] *= a0;
                o[nt][2] *= a1; o[nt][3] *= a1;
            }

            #pragma unroll
            for (int nt = 0; nt < 8; nt++) {
                asm volatile("st.shared.b32 [%0], %1;" ::
                    "r"(pStoreBase + nt * 16), "r"(pk_bf16x2(s[nt][0], s[nt][1])) : "memory");
                asm volatile("st.shared.b32 [%0], %1;" ::
                    "r"(pStoreBase + 8 * RB + nt * 16), "r"(pk_bf16x2(s[nt][2], s[nt][3])) : "memory");
            }
            __syncwarp();

            #pragma unroll
            for (int ks = 0; ks < 4; ks++) {
                uint32_t pf[4];
                LDSM4(pf[0], pf[1], pf[2], pf[3], pFragBase + ks * 32);
                uint32_t vf[8][2];
                #pragma unroll
                for (int ntp = 0; ntp < 4; ntp++) {
                    uint32_t r0, r1, r2, r3;
                    LDSM4T(r0, r1, r2, r3, vBase + ks * 16 * RB + ntp * 32);
                    vf[2 * ntp][0] = r0; vf[2 * ntp][1] = r1;
                    vf[2 * ntp + 1][0] = r2; vf[2 * ntp + 1][1] = r3;
                }
                #pragma unroll
                for (int nt = 0; nt < 8; nt++)
                    MMA_BF16(o[nt], pf, vf[nt][0], vf[nt][1]);
            }
        }
    }

    // normalize + write bf16
    float inv0 = 1.f / l0, inv1 = 1.f / l1;
    int row0 = qi * 128 + w * 16 + (lane >> 2);
    long base0 = (long)(b * S_ + row0) * D_ + h * DH_ + 2 * (lane & 3);
    long base1 = base0 + 8 * D_;
    #pragma unroll
    for (int nt = 0; nt < 8; nt++) {
        *(uint32_t*)&O16[base0 + nt * 8] = pk_bf16x2(o[nt][0] * inv0, o[nt][1] * inv0);
        *(uint32_t*)&O16[base1 + nt * 8] = pk_bf16x2(o[nt][2] * inv1, o[nt][3] * inv1);
    }
}

// ---------------------------------------------------------------------------
// Launch
// ---------------------------------------------------------------------------
extern "C" void kernel_launch(void* const* d_in, const int* in_sizes, int n_in,
                              void* d_out, int out_size)
{
    const float* hidden = (const float*)d_in[0];
    // d_in[1] = attention_mask: causal tril -> handled analytically
    const float* lora   = (const float*)d_in[2];   // [4, B, D, R]
    const float* ln_w   = (const float*)d_in[3];
    const float* Wq     = (const float*)d_in[4];
    const float* Wk     = (const float*)d_in[5];
    const float* Wv     = (const float*)d_in[6];
    const float* Wo     = (const float*)d_in[7];
    float* out = (float*)d_out;

    float *hq, *hk, *z;
    __nv_bfloat16 *x16, *q16, *k16, *v16, *attn16, *wq16, *wk16, *wv16, *wo16;
    cudaGetSymbolAddress((void**)&x16,    g_x16);
    cudaGetSymbolAddress((void**)&hq,     g_hq);
    cudaGetSymbolAddress((void**)&hk,     g_hk);
    cudaGetSymbolAddress((void**)&z,      g_z);
    cudaGetSymbolAddress((void**)&q16,    g_q16);
    cudaGetSymbolAddress((void**)&k16,    g_k16);
    cudaGetSymbolAddress((void**)&v16,    g_v16);
    cudaGetSymbolAddress((void**)&attn16, g_attn16);
    cudaGetSymbolAddress((void**)&wq16,   g_wq16);
    cudaGetSymbolAddress((void**)&wk16,   g_wk16);
    cudaGetSymbolAddress((void**)&wv16,   g_wv16);
    cudaGetSymbolAddress((void**)&wo16,   g_wo16);

    cudaFuncSetAttribute(gemm_qkv_kernel, cudaFuncAttributeMaxDynamicSharedMemorySize, GEMM_SMEM);
    cudaFuncSetAttribute(gemm_o_kernel,   cudaFuncAttributeMaxDynamicSharedMemorySize, GEMM_SMEM);
    cudaFuncSetAttribute(flash_mma_kernel, cudaFuncAttributeMaxDynamicSharedMemorySize, FLASH_SMEM);

    // 0+1. RMSNorm (-> bf16) + weight conversion in one launch
    prep_kernel<<<M_ + 2048, 256>>>(hidden, ln_w, Wq, Wk, Wv, Wo,
                                    x16, wq16, wk16, wv16, wo16);

    // 2. Fused QKV projections (bf16; q/k out fp32 for LoRA, V out bf16)
    dim3 gq(24, M_ / 128);
    gemm_qkv_kernel<<<gq, 256, GEMM_SMEM>>>(x16, wq16, wk16, wv16, hq, hk, v16);

    // 3. LoRA: z = h@A, then h += 2 z@B^T -> bf16
    dim3 gl(M_ / 32, 2);
    lora_z_kernel<<<gl, 256>>>(hq, hk, lora, z);
    lora_apply_kernel<<<gl, 256>>>(hq, hk, q16, k16, lora, z);

    // 4. Causal flash attention (bf16 in/out)
    dim3 fg(S_ / 128, H_, B_);
    flash_mma_kernel<<<fg, 256, FLASH_SMEM>>>(q16, k16, v16, attn16);

    // 5. Output projection + residual (bf16 in, fp32 out)
    dim3 go(8, M_ / 128);
    gemm_o_kernel<<<go, 256, GEMM_SMEM>>>(attn16, wo16, hidden, out);
}

// round 12
// speedup vs baseline: 6.7615x; 1.1144x over previous
#include <cuda_runtime.h>
#include <cuda_bf16.h>
#include <cstdint>
#include <math.h>

// Problem constants
#define B_  2
#define S_  2048
#define D_  1024
#define H_  16
#define DH_ 64
#define R_  8
#define M_  (B_*S_)          // 4096 rows

// Scratch (device globals; no allocation allowed)
__device__ __nv_bfloat16 g_x16[M_*D_];
__device__ float g_hq[M_*D_];
__device__ float g_hk[M_*D_];
__device__ float g_z[2*M_*R_];
__device__ __nv_bfloat16 g_q16[M_*D_];
__device__ __nv_bfloat16 g_k16[M_*D_];
__device__ __nv_bfloat16 g_v16[M_*D_];
__device__ __nv_bfloat16 g_attn16[M_*D_];
__device__ __nv_bfloat16 g_wq16[D_*D_];
__device__ __nv_bfloat16 g_wk16[D_*D_];
__device__ __nv_bfloat16 g_wv16[D_*D_];
__device__ __nv_bfloat16 g_wo16[D_*D_];

#define FULLMASK 0xffffffffu

// ===========================================================================
// PTX helpers
// ===========================================================================
__device__ __forceinline__ uint32_t smem_u32(const void* p) {
    uint32_t a;
    asm("{ .reg .u64 t; cvta.to.shared.u64 t, %1; cvt.u32.u64 %0, t; }"
        : "=r"(a) : "l"(p));
    return a;
}

#define LDSM4(R0,R1,R2,R3,ADDR) \
    asm volatile("ldmatrix.sync.aligned.m8n8.x4.shared.b16 {%0,%1,%2,%3}, [%4];" \
        : "=r"(R0), "=r"(R1), "=r"(R2), "=r"(R3) : "r"(ADDR))

#define LDSM4T(R0,R1,R2,R3,ADDR) \
    asm volatile("ldmatrix.sync.aligned.m8n8.x4.trans.shared.b16 {%0,%1,%2,%3}, [%4];" \
        : "=r"(R0), "=r"(R1), "=r"(R2), "=r"(R3) : "r"(ADDR))

#define MMA_BF16(C, A, B0, B1) \
    asm volatile("mma.sync.aligned.m16n8k16.row.col.f32.bf16.bf16.f32 " \
        "{%0,%1,%2,%3}, {%4,%5,%6,%7}, {%8,%9}, {%0,%1,%2,%3};" \
        : "+f"((C)[0]), "+f"((C)[1]), "+f"((C)[2]), "+f"((C)[3]) \
        : "r"((A)[0]), "r"((A)[1]), "r"((A)[2]), "r"((A)[3]), "r"(B0), "r"(B1))

#define CP16(DST, SRC) \
    asm volatile("cp.async.cg.shared.global [%0], [%1], 16;" :: "r"(DST), "l"(SRC))
#define CP_COMMIT() asm volatile("cp.async.commit_group;" ::: "memory")
#define CP_WAIT(N)  asm volatile("cp.async.wait_group %0;" :: "n"(N) : "memory")

__device__ __forceinline__ uint32_t pk_bf16x2(float a, float b) {
    __nv_bfloat162 t = __floats2bfloat162_rn(a, b);
    return *reinterpret_cast<uint32_t*>(&t);
}
__device__ __forceinline__ float rt_bf16(float a) {
    return __bfloat162float(__float2bfloat16(a));
}

// ---------------------------------------------------------------------------
// Prep: RMSNorm (blocks 0..M_-1) + weight conversion (blocks M_..M_+2047)
// ---------------------------------------------------------------------------
__global__ __launch_bounds__(256) void prep_kernel(
    const float* __restrict__ hs, const float* __restrict__ w,
    const float* __restrict__ Wq, const float* __restrict__ Wk,
    const float* __restrict__ Wv, const float* __restrict__ Wo,
    __nv_bfloat16* __restrict__ x16,
    __nv_bfloat16* __restrict__ wq16, __nv_bfloat16* __restrict__ wk16,
    __nv_bfloat16* __restrict__ wv16, __nv_bfloat16* __restrict__ wo16)
{
    int t = threadIdx.x;
    if (blockIdx.x < M_) {
        int row = blockIdx.x;
        const float* x = hs + (long)row * D_;
        float4 v = *(const float4*)&x[t * 4];
        float ss = v.x*v.x + v.y*v.y + v.z*v.z + v.w*v.w;
        #pragma unroll
        for (int o = 16; o > 0; o >>= 1) ss += __shfl_xor_sync(FULLMASK, ss, o);
        __shared__ float red[8];
        if ((t & 31) == 0) red[t >> 5] = ss;
        __syncthreads();
        __shared__ float s_inv;
        if (t == 0) {
            float s = 0.f;
            #pragma unroll
            for (int i = 0; i < 8; i++) s += red[i];
            s_inv = rsqrtf(s / (float)D_ + 1e-5f);
        }
        __syncthreads();
        float inv = s_inv;
        float4 wv4 = *(const float4*)&w[t * 4];
        uint2 o2;
        o2.x = pk_bf16x2(v.x * inv * wv4.x, v.y * inv * wv4.y);
        o2.y = pk_bf16x2(v.z * inv * wv4.z, v.w * inv * wv4.w);
        *(uint2*)&x16[(long)row * D_ + t * 4] = o2;
    } else {
        int bid2 = blockIdx.x - M_;          // 0..2047
        int sel = bid2 >> 9;                 // 512 blocks per matrix
        int ib  = bid2 & 511;
        const float* src = (sel == 0) ? Wq : (sel == 1) ? Wk : (sel == 2) ? Wv : Wo;
        __nv_bfloat16* dst = (sel == 0) ? wq16 : (sel == 1) ? wk16 : (sel == 2) ? wv16 : wo16;
        long idx = ((long)ib * 256 + t) * 8;
        float4 a = *(const float4*)&src[idx];
        float4 b = *(const float4*)&src[idx + 4];
        uint4 u;
        u.x = pk_bf16x2(a.x, a.y); u.y = pk_bf16x2(a.z, a.w);
        u.z = pk_bf16x2(b.x, b.y); u.w = pk_bf16x2(b.z, b.w);
        *(uint4*)&dst[idx] = u;
    }
}

// ---------------------------------------------------------------------------
// bf16 GEMM core: C[128x128] = A[*,1024] @ W[*,1024]^T.
// BK=64 bf16, double-buffered cp.async, 8 warps x (32x64) warp tiles.
// MODE: 0 = fp32 out, 1 = fp32 + residual, 2 = bf16 out
// ---------------------------------------------------------------------------
#define RBW 144                     // 64 bf16 = 128B data + 16B pad
#define WTILE_B (128*RBW)           // 18432
#define GEMM_SMEM (4*WTILE_B)       // 73728

template <int MODE>
__device__ __forceinline__ void gemm128_bf16_core(
    const __nv_bfloat16* __restrict__ A, const __nv_bfloat16* __restrict__ W,
    const float* __restrict__ resid, float* __restrict__ C32,
    __nv_bfloat16* __restrict__ C16,
    int by, int bx, char* gsm)
{
    const uint32_t sA = smem_u32(gsm);
    const uint32_t sB = sA + 2 * WTILE_B;
    int tid = threadIdx.x;
    int lane = tid & 31;
    int w = tid >> 5;
    int wm = (w >> 1) * 32;
    int wn = (w & 1) * 64;

    // cp.async tasks: 128 rows x 8 chunks of 16B = 1024 per matrix, 4 per thread
    const __nv_bfloat16* aP[4]; const __nv_bfloat16* bP[4];
    uint32_t stA[4], stB[4];
    #pragma unroll
    for (int l = 0; l < 4; l++) {
        int idx = tid + l * 256;
        int r = idx >> 3, c8 = idx & 7;
        aP[l] = A + (long)(by * 128 + r) * D_ + c8 * 8;
        bP[l] = W + (long)(bx * 128 + r) * D_ + c8 * 8;
        stA[l] = sA + r * RBW + c8 * 16;
        stB[l] = sB + r * RBW + c8 * 16;
    }

    float acc[2][8][4];
    #pragma unroll
    for (int mt = 0; mt < 2; mt++)
        #pragma unroll
        for (int nt = 0; nt < 8; nt++)
            #pragma unroll
            for (int j = 0; j < 4; j++) acc[mt][nt][j] = 0.f;

    const uint32_t aFragBase = sA + (wm + (lane & 15)) * RBW + (lane >> 4) * 16;
    const uint32_t bFragBase = sB +
        (wn + (lane & 7) + ((lane >> 4) << 3)) * RBW + ((lane >> 3) & 1) * 16;

    #pragma unroll
    for (int l = 0; l < 4; l++) { CP16(stA[l], aP[l]); CP16(stB[l], bP[l]); }
    CP_COMMIT();

    for (int kc = 0; kc < 16; kc++) {          // D/64
        int buf = kc & 1;
        if (kc + 1 < 16) {
            #pragma unroll
            for (int l = 0; l < 4; l++) {
                CP16(stA[l] + (buf ^ 1) * WTILE_B, aP[l] + (kc + 1) * 64);
                CP16(stB[l] + (buf ^ 1) * WTILE_B, bP[l] + (kc + 1) * 64);
            }
            CP_COMMIT();
            CP_WAIT(1);
        } else {
            CP_WAIT(0);
        }
        __syncthreads();

        uint32_t aBuf = aFragBase + buf * WTILE_B;
        uint32_t bBuf = bFragBase + buf * WTILE_B;

        #pragma unroll
        for (int ks = 0; ks < 4; ks++) {       // 4 k16-steps per BK=64
            uint32_t af[2][4];
            uint32_t bf[8][2];
            #pragma unroll
            for (int mt = 0; mt < 2; mt++)
                LDSM4(af[mt][0], af[mt][1], af[mt][2], af[mt][3],
                      aBuf + mt * 16 * RBW + ks * 32);
            #pragma unroll
            for (int ntp = 0; ntp < 4; ntp++) {
                uint32_t r0, r1, r2, r3;
                LDSM4(r0, r1, r2, r3, bBuf + ntp * 16 * RBW + ks * 32);
                bf[2 * ntp][0] = r0; bf[2 * ntp][1] = r1;
                bf[2 * ntp + 1][0] = r2; bf[2 * ntp + 1][1] = r3;
            }
            #pragma unroll
            for (int mt = 0; mt < 2; mt++)
                #pragma unroll
                for (int nt = 0; nt < 8; nt++)
                    MMA_BF16(acc[mt][nt], af[mt], bf[nt][0], bf[nt][1]);
        }
        __syncthreads();
    }

    #pragma unroll
    for (int mt = 0; mt < 2; mt++) {
        int row = by * 128 + wm + mt * 16 + (lane >> 2);
        int col = bx * 128 + wn + 2 * (lane & 3);
        #pragma unroll
        for (int nt = 0; nt < 8; nt++) {
            long i0 = (long)row * D_ + col + nt * 8;
            long i1 = i0 + 8 * D_;
            if (MODE == 2) {
                *(uint32_t*)&C16[i0] = pk_bf16x2(acc[mt][nt][0], acc[mt][nt][1]);
                *(uint32_t*)&C16[i1] = pk_bf16x2(acc[mt][nt][2], acc[mt][nt][3]);
            } else {
                float2 v0 = make_float2(acc[mt][nt][0], acc[mt][nt][1]);
                float2 v1 = make_float2(acc[mt][nt][2], acc[mt][nt][3]);
                if (MODE == 1) {
                    float2 r0 = *(const float2*)&resid[i0];
                    float2 r1 = *(const float2*)&resid[i1];
                    v0.x += r0.x; v0.y += r0.y;
                    v1.x += r1.x; v1.y += r1.y;
                }
                *(float2*)&C32[i0] = v0;
                *(float2*)&C32[i1] = v1;
            }
        }
    }
}

__global__ __launch_bounds__(256, 2) void gemm_qkv_kernel(
    const __nv_bfloat16* __restrict__ A,
    const __nv_bfloat16* __restrict__ Wq, const __nv_bfloat16* __restrict__ Wk,
    const __nv_bfloat16* __restrict__ Wv,
    float* __restrict__ hq, float* __restrict__ hk, __nv_bfloat16* __restrict__ v16)
{
    extern __shared__ __align__(16) char gsm[];
    int wsel = blockIdx.x >> 3;
    int bx = blockIdx.x & 7;
    if (wsel == 0)
        gemm128_bf16_core<0>(A, Wq, nullptr, hq, nullptr, blockIdx.y, bx, gsm);
    else if (wsel == 1)
        gemm128_bf16_core<0>(A, Wk, nullptr, hk, nullptr, blockIdx.y, bx, gsm);
    else
        gemm128_bf16_core<2>(A, Wv, nullptr, nullptr, v16, blockIdx.y, bx, gsm);
}

__global__ __launch_bounds__(256, 2) void gemm_o_kernel(
    const __nv_bfloat16* __restrict__ A, const __nv_bfloat16* __restrict__ W,
    const float* __restrict__ resid, float* __restrict__ C)
{
    extern __shared__ __align__(16) char gsm[];
    gemm128_bf16_core<1>(A, W, resid, C, nullptr, blockIdx.y, blockIdx.x, gsm);
}

// ---------------------------------------------------------------------------
// LoRA phase 1: z[row][:] = h[row] @ A   (grid: (M_/32, 2), 256 threads)
// ---------------------------------------------------------------------------
__global__ __launch_bounds__(256) void lora_z_kernel(
    const float* __restrict__ hq, const float* __restrict__ hk,
    const float* __restrict__ lora, float* __restrict__ z)
{
    int which = blockIdx.y;
    const float* h = which ? hk : hq;
    int rowBase = blockIdx.x * 32;
    int b = rowBase / S_;
    const float* Ag = lora + ((long)which * B_ + b) * D_ * R_;

    __shared__ float As[R_ * D_];    // 32KB, [r][d]
    int tid = threadIdx.x;
    int lane = tid & 31, w = tid >> 5;

    #pragma unroll
    for (int k = 0; k < 4; k++) {
        int d = tid + k * 256;
        float4 a0 = *(const float4*)&Ag[d * R_];
        float4 a1 = *(const float4*)&Ag[d * R_ + 4];
        As[0*D_+d] = a0.x; As[1*D_+d] = a0.y; As[2*D_+d] = a0.z; As[3*D_+d] = a0.w;
        As[4*D_+d] = a1.x; As[5*D_+d] = a1.y; As[6*D_+d] = a1.z; As[7*D_+d] = a1.w;
    }
    __syncthreads();

    #pragma unroll
    for (int rr = 0; rr < 4; rr++) {
        int row = rowBase + w * 4 + rr;
        const float* hrow = h + (long)row * D_;
        float part[R_];
        #pragma unroll
        for (int r = 0; r < R_; r++) part[r] = 0.f;
        #pragma unroll
        for (int k = 0; k < 32; k++) {
            int d = lane + k * 32;
            float hv = hrow[d];
            #pragma unroll
            for (int r = 0; r < R_; r++) part[r] += hv * As[r * D_ + d];
        }
        #pragma unroll
        for (int r = 0; r < R_; r++)
            #pragma unroll
            for (int o = 16; o > 0; o >>= 1)
                part[r] += __shfl_xor_sync(FULLMASK, part[r], o);
        if (lane == 0) {
            #pragma unroll
            for (int r = 0; r < R_; r++)
                z[((long)which * M_ + row) * R_ + r] = part[r];
        }
    }
}

// ---------------------------------------------------------------------------
// LoRA phase 2: g16[row][d] = bf16(h[row][d] + 2 * sum_r z[row][r] * B[d][r])
// Grid (M_/16, 2), 256 threads. Thread owns 4 consecutive d's; streams 16 rows.
// ---------------------------------------------------------------------------
#define LAR 16
__global__ __launch_bounds__(256) void lora_apply_kernel(
    const float* __restrict__ hq, const float* __restrict__ hk,
    __nv_bfloat16* __restrict__ q16, __nv_bfloat16* __restrict__ k16,
    const float* __restrict__ lora, const float* __restrict__ z)
{
    int which = blockIdx.y;
    const float* h = which ? hk : hq;
    __nv_bfloat16* g16 = which ? k16 : q16;
    int rowBase = blockIdx.x * LAR;
    int b = rowBase / S_;
    const float* Bg = lora + ((long)(2 + which) * B_ + b) * D_ * R_;

    __shared__ float zs[LAR][R_];
    int tid = threadIdx.x;
    if (tid < LAR * R_)
        zs[tid >> 3][tid & 7] = z[((long)which * M_ + rowBase + (tid >> 3)) * R_ + (tid & 7)];
    __syncthreads();

    int d0 = tid * 4;
    float br[4][R_];
    #pragma unroll
    for (int j = 0; j < 4; j++) {
        float4 b0 = *(const float4*)&Bg[(d0 + j) * R_];
        float4 b1 = *(const float4*)&Bg[(d0 + j) * R_ + 4];
        br[j][0] = b0.x; br[j][1] = b0.y; br[j][2] = b0.z; br[j][3] = b0.w;
        br[j][4] = b1.x; br[j][5] = b1.y; br[j][6] = b1.z; br[j][7] = b1.w;
    }

    #pragma unroll 4
    for (int rr = 0; rr < LAR; rr++) {
        long idx = (long)(rowBase + rr) * D_ + d0;
        float4 hv = *(const float4*)&h[idx];
        float del[4];
        #pragma unroll
        for (int j = 0; j < 4; j++) {
            float s = 0.f;
            #pragma unroll
            for (int r = 0; r < R_; r++) s += zs[rr][r] * br[j][r];
            del[j] = s;
        }
        uint2 o2;
        o2.x = pk_bf16x2(hv.x + 2.f * del[0], hv.y + 2.f * del[1]);
        o2.y = pk_bf16x2(hv.z + 2.f * del[2], hv.w + 2.f * del[3]);
        *(uint2*)&g16[idx] = o2;
    }
}

// ---------------------------------------------------------------------------
// Flash attention, bf16 mma, causal. Q tile 64, K/V tile 64, 128 threads
// (4 warps x 16 q-rows). 3 CTAs/SM. bf16 in/out. exp2-domain softmax.
// K/V cp.async 3-slot ring. smem = 9216(Q) + 3x9216(K) + 3x9216(V) + 9216(P)
// ---------------------------------------------------------------------------
#define RB 144
#define KSLOT_B (64 * RB)
#define FQ_B  (64 * RB)              // 9216
#define FLASH_SMEM (FQ_B + 3*KSLOT_B + 3*KSLOT_B + FQ_B)   // 73728

__global__ __launch_bounds__(128, 3) void flash_mma_kernel(
    const __nv_bfloat16* __restrict__ Q, const __nv_bfloat16* __restrict__ K,
    const __nv_bfloat16* __restrict__ V, __nv_bfloat16* __restrict__ O16)
{
    extern __shared__ __align__(16) char smc[];
    const uint32_t qsB = smem_u32(smc);
    const uint32_t ksB = qsB + FQ_B;
    const uint32_t vnB = ksB + 3 * KSLOT_B;
    const uint32_t psB = vnB + 3 * KSLOT_B;

    int qi = (gridDim.x - 1) - blockIdx.x;   // heavy tiles first
    int h  = blockIdx.y;
    int b  = blockIdx.z;
    int tid = threadIdx.x;
    int lane = tid & 31;
    int w = tid >> 5;                         // 0..3

    // cp.async task split: 64 rows x 8 chunks = 512 tasks, 4 per thread
    int cKp[4], cC[4];
    #pragma unroll
    for (int l = 0; l < 4; l++) {
        int idx = tid + l * 128;
        cKp[l] = idx >> 3; cC[l] = idx & 7;
    }

    // --- Prologue: Q (LDG bf16 -> STS), K0/V0 via cp.async ---
    const __nv_bfloat16* Qp = Q + (long)(b * S_ + qi * 64) * D_ + h * DH_;
    #pragma unroll
    for (int l = 0; l < 4; l++) {
        int idx = tid + l * 128;
        int q = idx >> 3, c8 = idx & 7;
        float4 v = *(const float4*)&Qp[(long)q * D_ + c8 * 8];
        asm volatile("st.shared.v4.b32 [%0], {%1,%2,%3,%4};" ::
            "r"(qsB + q * RB + c8 * 16),
            "r"(__float_as_uint(v.x)), "r"(__float_as_uint(v.y)),
            "r"(__float_as_uint(v.z)), "r"(__float_as_uint(v.w)) : "memory");
    }
    {
        const __nv_bfloat16* Kp = K + (long)(b * S_) * D_ + h * DH_;
        const __nv_bfloat16* Vp = V + (long)(b * S_) * D_ + h * DH_;
        #pragma unroll
        for (int l = 0; l < 4; l++) {
            CP16(ksB + cKp[l] * RB + cC[l] * 16, Kp + (long)cKp[l] * D_ + cC[l] * 8);
            CP16(vnB + cKp[l] * RB + cC[l] * 16, Vp + (long)cKp[l] * D_ + cC[l] * 8);
        }
        CP_COMMIT();
    }

    float o[8][4];
    #pragma unroll
    for (int nt = 0; nt < 8; nt++)
        #pragma unroll
        for (int j = 0; j < 4; j++) o[nt][j] = 0.f;
    float m0 = -1e30f, m1 = -1e30f, l0 = 0.f, l1 = 0.f;

    const uint32_t kFragOff = ((lane & 7) + ((lane >> 4) << 3)) * RB + ((lane >> 3) & 1) * 16;
    const uint32_t vFragOff = ((lane & 7) + ((lane >> 3) & 1) * 8) * RB + (lane >> 4) * 16;
    const uint32_t pFragBase = psB + (w * 16 + (lane & 15)) * RB + (lane >> 4) * 16;
    const uint32_t pStoreBase = psB + (w * 16 + (lane >> 2)) * RB + (lane & 3) * 4;

    bool qfLoaded = false;
    uint32_t qf[4][4];

    const float SC = 0.125f * 1.44269504f;   // scale * log2(e)

    int ktmax = qi + 1;
    for (int kt = 0; kt < ktmax; kt++) {
        int slot = kt % 3;
        bool havenext = (kt + 1) < ktmax;

        if (havenext) {
            int ns = (kt + 1) % 3;
            const __nv_bfloat16* Kp = K + (long)(b * S_ + (kt + 1) * 64) * D_ + h * DH_;
            const __nv_bfloat16* Vp = V + (long)(b * S_ + (kt + 1) * 64) * D_ + h * DH_;
            uint32_t kd = ksB + ns * KSLOT_B, vd = vnB + ns * KSLOT_B;
            #pragma unroll
            for (int l = 0; l < 4; l++) {
                CP16(kd + cKp[l] * RB + cC[l] * 16, Kp + (long)cKp[l] * D_ + cC[l] * 8);
                CP16(vd + cKp[l] * RB + cC[l] * 16, Vp + (long)cKp[l] * D_ + cC[l] * 8);
            }
            CP_COMMIT();
            CP_WAIT(1);
        } else {
            CP_WAIT(0);
        }
        __syncthreads();

        if (!qfLoaded) {
            uint32_t base = qsB + (w * 16 + (lane & 15)) * RB + (lane >> 4) * 16;
            #pragma unroll
            for (int ds = 0; ds < 4; ds++)
                LDSM4(qf[ds][0], qf[ds][1], qf[ds][2], qf[ds][3], base + ds * 32);
            qfLoaded = true;
        }

        {
            const uint32_t kBase = ksB + slot * KSLOT_B + kFragOff;
            const uint32_t vBase = vnB + slot * KSLOT_B + vFragOff;

            // ---- S = Q K^T ----
            float s[8][4];
            #pragma unroll
            for (int nt = 0; nt < 8; nt++)
                #pragma unroll
                for (int j = 0; j < 4; j++) s[nt][j] = 0.f;

            #pragma unroll
            for (int ds = 0; ds < 4; ds++) {
                uint32_t bf[8][2];
                #pragma unroll
                for (int ntp = 0; ntp < 4; ntp++) {
                    uint32_t r0, r1, r2, r3;
                    LDSM4(r0, r1, r2, r3, kBase + ntp * 16 * RB + ds * 32);
                    bf[2 * ntp][0] = r0; bf[2 * ntp][1] = r1;
                    bf[2 * ntp + 1][0] = r2; bf[2 * ntp + 1][1] = r3;
                }
                #pragma unroll
                for (int nt = 0; nt < 8; nt++)
                    MMA_BF16(s[nt], qf[ds], bf[nt][0], bf[nt][1]);
            }

            // ---- scale + causal mask + online softmax ----
            bool needmask = (kt * 64 + 63) > (qi * 64 + w * 16);
            int row0 = qi * 64 + w * 16 + (lane >> 2);
            float ml0 = -1e30f, ml1 = -1e30f;
            #pragma unroll
            for (int nt = 0; nt < 8; nt++) {
                #pragma unroll
                for (int j = 0; j < 4; j++) {
                    float v = s[nt][j] * SC;     // exp2 domain
                    if (needmask) {
                        int col = kt * 64 + nt * 8 + 2 * (lane & 3) + (j & 1);
                        int row = row0 + ((j >> 1) << 3);
                        if (col > row) v = -1e30f;
                    }
                    s[nt][j] = v;
                }
                ml0 = fmaxf(ml0, fmaxf(s[nt][0], s[nt][1]));
                ml1 = fmaxf(ml1, fmaxf(s[nt][2], s[nt][3]));
            }
            ml0 = fmaxf(ml0, __shfl_xor_sync(FULLMASK, ml0, 1));
            ml0 = fmaxf(ml0, __shfl_xor_sync(FULLMASK, ml0, 2));
            ml1 = fmaxf(ml1, __shfl_xor_sync(FULLMASK, ml1, 1));
            ml1 = fmaxf(ml1, __shfl_xor_sync(FULLMASK, ml1, 2));
            float mn0 = fmaxf(m0, ml0), mn1 = fmaxf(m1, ml1);
            float a0 = exp2f(m0 - mn0), a1 = exp2f(m1 - mn1);
            float sum0 = 0.f, sum1 = 0.f;
            #pragma unroll
            for (int nt = 0; nt < 8; nt++) {
                s[nt][0] = rt_bf16(exp2f(s[nt][0] - mn0));
                s[nt][1] = rt_bf16(exp2f(s[nt][1] - mn0));
                s[nt][2] = rt_bf16(exp2f(s[nt][2] - mn1));
                s[nt][3] = rt_bf16(exp2f(s[nt][3] - mn1));
                sum0 += s[nt][0] + s[nt][1];
                sum1 += s[nt][2] + s[nt][3];
            }
            sum0 += __shfl_xor_sync(FULLMASK, sum0, 1);
            sum0 += __shfl_xor_sync(FULLMASK, sum0, 2);
            sum1 += __shfl_xor_sync(FULLMASK, sum1, 1);
            sum1 += __shfl_xor_sync(FULLMASK, sum1, 2);
            l0 = l0 * a0 + sum0;
            l1 = l1 * a1 + sum1;
            m0 = mn0; m1 = mn1;
            #pragma unroll
            for (int nt = 0; nt < 8; nt++) {
                o[nt][0] *= a0; o[nt][1] *= a0;
                o[nt][2] *= a1; o[nt][3] *= a1;
            }

            // ---- store P (bf16, per-warp slice) ----
            #pragma unroll
            for (int nt = 0; nt < 8; nt++) {
                asm volatile("st.shared.b32 [%0], %1;" ::
                    "r"(pStoreBase + nt * 16), "r"(pk_bf16x2(s[nt][0], s[nt][1])) : "memory");
                asm volatile("st.shared.b32 [%0], %1;" ::
                    "r"(pStoreBase + 8 * RB + nt * 16), "r"(pk_bf16x2(s[nt][2], s[nt][3])) : "memory");
            }
            __syncwarp();

            // ---- O += P V ----
            #pragma unroll
            for (int ks = 0; ks < 4; ks++) {
                uint32_t pf[4];
                LDSM4(pf[0], pf[1], pf[2], pf[3], pFragBase + ks * 32);
                uint32_t vf[8][2];
                #pragma unroll
                for (int ntp = 0; ntp < 4; ntp++) {
                    uint32_t r0, r1, r2, r3;
                    LDSM4T(r0, r1, r2, r3, vBase + ks * 16 * RB + ntp * 32);
                    vf[2 * ntp][0] = r0; vf[2 * ntp][1] = r1;
                    vf[2 * ntp + 1][0] = r2; vf[2 * ntp + 1][1] = r3;
                }
                #pragma unroll
                for (int nt = 0; nt < 8; nt++)
                    MMA_BF16(o[nt], pf, vf[nt][0], vf[nt][1]);
            }
        }
    }

    // normalize + write bf16
    float inv0 = 1.f / l0, inv1 = 1.f / l1;
    int row0 = qi * 64 + w * 16 + (lane >> 2);
    long base0 = (long)(b * S_ + row0) * D_ + h * DH_ + 2 * (lane & 3);
    long base1 = base0 + 8 * D_;
    #pragma unroll
    for (int nt = 0; nt < 8; nt++) {
        *(uint32_t*)&O16[base0 + nt * 8] = pk_bf16x2(o[nt][0] * inv0, o[nt][1] * inv0);
        *(uint32_t*)&O16[base1 + nt * 8] = pk_bf16x2(o[nt][2] * inv1, o[nt][3] * inv1);
    }
}

// ---------------------------------------------------------------------------
// Launch
// ---------------------------------------------------------------------------
extern "C" void kernel_launch(void* const* d_in, const int* in_sizes, int n_in,
                              void* d_out, int out_size)
{
    const float* hidden = (const float*)d_in[0];
    // d_in[1] = attention_mask: causal tril -> handled analytically
    const float* lora   = (const float*)d_in[2];   // [4, B, D, R]
    const float* ln_w   = (const float*)d_in[3];
    const float* Wq     = (const float*)d_in[4];
    const float* Wk     = (const float*)d_in[5];
    const float* Wv     = (const float*)d_in[6];
    const float* Wo     = (const float*)d_in[7];
    float* out = (float*)d_out;

    float *hq, *hk, *z;
    __nv_bfloat16 *x16, *q16, *k16, *v16, *attn16, *wq16, *wk16, *wv16, *wo16;
    cudaGetSymbolAddress((void**)&x16,    g_x16);
    cudaGetSymbolAddress((void**)&hq,     g_hq);
    cudaGetSymbolAddress((void**)&hk,     g_hk);
    cudaGetSymbolAddress((void**)&z,      g_z);
    cudaGetSymbolAddress((void**)&q16,    g_q16);
    cudaGetSymbolAddress((void**)&k16,    g_k16);
    cudaGetSymbolAddress((void**)&v16,    g_v16);
    cudaGetSymbolAddress((void**)&attn16, g_attn16);
    cudaGetSymbolAddress((void**)&wq16,   g_wq16);
    cudaGetSymbolAddress((void**)&wk16,   g_wk16);
    cudaGetSymbolAddress((void**)&wv16,   g_wv16);
    cudaGetSymbolAddress((void**)&wo16,   g_wo16);

    cudaFuncSetAttribute(gemm_qkv_kernel, cudaFuncAttributeMaxDynamicSharedMemorySize, GEMM_SMEM);
    cudaFuncSetAttribute(gemm_o_kernel,   cudaFuncAttributeMaxDynamicSharedMemorySize, GEMM_SMEM);
    cudaFuncSetAttribute(flash_mma_kernel, cudaFuncAttributeMaxDynamicSharedMemorySize, FLASH_SMEM);

    // 0+1. RMSNorm (-> bf16) + weight conversion in one launch
    prep_kernel<<<M_ + 2048, 256>>>(hidden, ln_w, Wq, Wk, Wv, Wo,
                                    x16, wq16, wk16, wv16, wo16);

    // 2. Fused QKV projections (bf16; q/k out fp32 for LoRA, V out bf16)
    dim3 gq(24, M_ / 128);
    gemm_qkv_kernel<<<gq, 256, GEMM_SMEM>>>(x16, wq16, wk16, wv16, hq, hk, v16);

    // 3. LoRA: z = h@A, then h += 2 z@B^T -> bf16
    dim3 gl(M_ / 32, 2);
    lora_z_kernel<<<gl, 256>>>(hq, hk, lora, z);
    dim3 gla(M_ / LAR, 2);
    lora_apply_kernel<<<gla, 256>>>(hq, hk, q16, k16, lora, z);

    // 4. Causal flash attention (bf16 in/out, Q-tile 64, 128 threads)
    dim3 fg(S_ / 64, H_, B_);
    flash_mma_kernel<<<fg, 128, FLASH_SMEM>>>(q16, k16, v16, attn16);

    // 5. Output projection + residual (bf16 in, fp32 out)
    dim3 go(8, M_ / 128);
    gemm_o_kernel<<<go, 256, GEMM_SMEM>>>(attn16, wo16, hidden, out);
}